// round 8
// baseline (speedup 1.0000x reference)
#include <cuda_runtime.h>
#include <math.h>
#include <stdint.h>

#define B_SZ   256
#define T_SZ   64
#define IN_SZ  500
#define HID    512
#define G4     2048
#define RAWN   16532
#define NA     500
#define NF     32
#define GRIDN  128

__device__ float g_xg[(size_t)T_SZ * B_SZ * G4];
__device__ float g_hseq[(size_t)T_SZ * B_SZ * HID];
__device__ float g_hA[B_SZ * HID];
__device__ float g_hB[B_SZ * HID];
__device__ float g_raw[(size_t)B_SZ * RAWN];
__device__ unsigned long long g_flags[GRIDN];

__device__ __forceinline__ float sigmf(float x) { return 1.f / (1.f + expf(-x)); }

__device__ __forceinline__ uint32_t f2tf32(float f) {
    uint32_t r;
    asm("cvt.rna.tf32.f32 %0, %1;" : "=r"(r) : "f"(f));
    return r;
}

__device__ __forceinline__ void mma_tf32(float* c, const uint32_t* a, const uint32_t* b) {
    asm volatile(
        "mma.sync.aligned.m16n8k8.row.col.f32.tf32.tf32.f32 "
        "{%0,%1,%2,%3}, {%4,%5,%6,%7}, {%8,%9}, {%0,%1,%2,%3};\n"
        : "+f"(c[0]), "+f"(c[1]), "+f"(c[2]), "+f"(c[3])
        : "r"(a[0]), "r"(a[1]), "r"(a[2]), "r"(a[3]), "r"(b[0]), "r"(b[1]));
}

__device__ __forceinline__ void ldsm_x4(uint32_t* r, uint32_t addr) {
    asm volatile("ldmatrix.sync.aligned.m8n8.x4.shared.b16 {%0,%1,%2,%3}, [%4];"
        : "=r"(r[0]), "=r"(r[1]), "=r"(r[2]), "=r"(r[3]) : "r"(addr));
}

__device__ __forceinline__ uint32_t smem_u32(const void* p) {
    uint32_t a;
    asm("{ .reg .u64 t; cvta.to.shared.u64 t, %1; cvt.u32.u64 %0, t; }" : "=r"(a) : "l"(p));
    return a;
}

// ================= persistent LSTM layer (fine-grained producer flags) =================
// 128 blocks (32 hid-chunks x 4 batch-chunks), 256 threads (8 warps = 4 pairs).
// Tile: 64 batch x 64 gate-cols (16 hid x 4 interleaved gates) x K=512.
// Chunk ck of h (k-cols 64ck..+63) depends only on producer blocks bc*32+4ck..+3:
// each staging lane polls exactly its own producer's flag (no global barrier).
//
// smem bytes:
//   W   [64][516]u32                      @ 0        132096
//   A   4 pairs x (3 bufs x 4352 + Cs 4608) @132096   70656
//   xg  8 warps x 2048B                   @ 202752    16384   total 219136
#define W_STR    516
#define A_STR    68
#define OFF_AP   132096
#define PAIR_ST  17664
#define BUF_ST   4352
#define OFF_CS   13056          // within pair region
#define OFF_XG   202752
#define SM_BYTES 219136

__global__ __launch_bounds__(256, 1) void lstm_persist(
    const float* __restrict__ w_hh, int layer)
{
    extern __shared__ __align__(16) uint32_t smraw[];
    uint32_t* Wsm = smraw;
    float*    smf = (float*)smraw;
    const uint32_t smem = smem_u32(smraw);

    const int tid  = threadIdx.x;
    const int lane = tid & 31;
    const int warp = tid >> 5;
    const int pair = warp >> 1;
    const int wh   = warp & 1;
    const int wm   = pair * 16;
    const int wn   = wh * 32;
    const int h0   = (blockIdx.x & 31) * 16;
    const int m0   = (blockIdx.x >> 5) * 64;
    const int grp  = (blockIdx.x >> 5) * 32;   // flag group base

    // ---- load W slice once: row n (0..63) = w_hh row (n&3)*HID + h0 + (n>>2) ----
#pragma unroll
    for (int i = 0; i < 32; i++) {
        int s   = tid + (i << 8);
        int row = s >> 7;
        int kq  = s & 127;
        int wr  = ((row & 3) << 9) + h0 + (row >> 2);
        float4 v = *(const float4*)&w_hh[(size_t)wr * HID + (kq << 2)];
        *(uint4*)&Wsm[row * W_STR + (kq << 2)] =
            make_uint4(f2tf32(v.x), f2tf32(v.y), f2tf32(v.z), f2tf32(v.w));
    }

    // ldmatrix bases
    const uint32_t pairBase = smem + OFF_AP + (uint32_t)pair * PAIR_ST;
    const uint32_t aFrag = pairBase
        + (uint32_t)(((lane & 15) * A_STR + (lane >> 4) * 4) << 2);
    const uint32_t rB = wn + (lane & 7) + ((lane & 16) ? 8 : 0);
    const uint32_t bBase0 = smem + (uint32_t)((rB * W_STR + ((lane >> 3) & 1) * 4) << 2);
    const uint32_t bBase1 = bBase0 + 16 * W_STR * 4;

    const int sRowBase = wh * 8;
    const uint32_t xgBase = smem + OFF_XG + (uint32_t)warp * 2048;
    const int xgW = (int)(OFF_XG / 4) + warp * 512;
    // Cs: warp-private, dedicated region (no aliasing with staging bufs)
    const int csW = (int)(OFF_AP / 4) + pair * (PAIR_ST / 4) + (OFF_CS / 4) + wh * 576;

    const unsigned long long barBase =
        *(volatile unsigned long long*)&g_flags[blockIdx.x];

    float creg[4] = {0.f, 0.f, 0.f, 0.f};
    // staging lane's producer sub-index for any chunk c: 4c + prodOff
    const int prodOff = (lane & 15) >> 2;

    __syncthreads();   // W visible to all

    // ---- prefetch xg for t=0 ----
    {
#pragma unroll
        for (int i = 0; i < 4; i++) {
            int idx = lane + 32 * i;
            int q = idx >> 5, r = (idx >> 1) & 15, gg = idx & 1;
            const float* src = g_xg + ((size_t)0 * B_SZ + m0 + wm + r) * G4
                             + q * HID + h0 + wh * 8 + gg * 4;
            asm volatile("cp.async.cg.shared.global [%0], [%1], 16;"
                :: "r"(xgBase + (uint32_t)(q * 512 + r * 32 + gg * 16)), "l"(src));
        }
        asm volatile("cp.async.commit_group;" ::: "memory");
    }

#define WCHUNK(c)                                                               \
    {                                                                           \
        const unsigned long long* fp = &g_flags[grp + 4 * (c) + prodOff];       \
        unsigned long long v;                                                   \
        do {                                                                    \
            asm volatile("ld.acquire.gpu.global.u64 %0, [%1];"                  \
                         : "=l"(v) : "l"(fp) : "memory");                       \
        } while (v < hTgt);                                                     \
    }

#define STAGE_H(c)                                                              \
    {                                                                           \
        uint32_t dbuf = pairBase + (uint32_t)(((c) % 3) * BUF_ST);              \
        _Pragma("unroll")                                                       \
        for (int i = 0; i < 4; i++) {                                           \
            int idx = lane + 32 * i;                                            \
            int rl = sRowBase + (idx >> 4);                                     \
            int gr = idx & 15;                                                  \
            const float* src = h_in + (size_t)(m0 + wm + rl) * HID              \
                             + (c) * 64 + gr * 4;                               \
            asm volatile("cp.async.cg.shared.global [%0], [%1], 16;"            \
                :: "r"(dbuf + (uint32_t)(rl * 272 + gr * 16)), "l"(src));       \
        }                                                                       \
        asm volatile("cp.async.commit_group;" ::: "memory");                    \
    }

#define MMA_CHUNK(ck)                                                           \
    {                                                                           \
        const uint32_t ab  = aFrag  + (uint32_t)(((ck) % 3) * BUF_ST);          \
        const uint32_t wb0 = bBase0 + (uint32_t)((ck) * 256);                   \
        const uint32_t wb1 = bBase1 + (uint32_t)((ck) * 256);                   \
        uint32_t fa[2][4], f0[2][4], f1[2][4];                                  \
        ldsm_x4(fa[0], ab);                                                     \
        ldsm_x4(f0[0], wb0);                                                    \
        ldsm_x4(f1[0], wb1);                                                    \
        _Pragma("unroll")                                                       \
        for (int k8 = 0; k8 < 8; k8++) {                                        \
            const int cur = k8 & 1, nxt = cur ^ 1;                              \
            if (k8 < 7) {                                                       \
                ldsm_x4(fa[nxt], ab  + (uint32_t)((k8 + 1) * 32));              \
                ldsm_x4(f0[nxt], wb0 + (uint32_t)((k8 + 1) * 32));              \
                ldsm_x4(f1[nxt], wb1 + (uint32_t)((k8 + 1) * 32));              \
            }                                                                   \
            mma_tf32(c[0], fa[cur], f0[cur]);                                   \
            mma_tf32(c[1], fa[cur], f0[cur] + 2);                               \
            mma_tf32(c[2], fa[cur], f1[cur]);                                   \
            mma_tf32(c[3], fa[cur], f1[cur] + 2);                               \
        }                                                                       \
    }

    for (int t = 0; t < T_SZ; t++) {
        const float* h_in = (t & 1) ? g_hB : g_hA;
        float* h_out      = (t & 1) ? g_hA : g_hB;
        const unsigned long long hTgt = barBase + (unsigned long long)t;

        float c[4][4];
#pragma unroll
        for (int nt = 0; nt < 4; nt++)
#pragma unroll
            for (int q = 0; q < 4; q++) c[nt][q] = 0.f;

        if (t > 0) {
            WCHUNK(0) STAGE_H(0)
            WCHUNK(1) STAGE_H(1)
            // iter ck: poll(ck+2) -> wait_group -> pair bar -> stage(ck+2) -> MMA(ck)
            const int barId = 1 + pair;
#define ITER(ck, WN)                                                            \
            if ((ck) < 6) WCHUNK((ck) + 2)                                      \
            asm volatile("cp.async.wait_group " #WN ";" ::: "memory");          \
            asm volatile("bar.sync %0, 64;" :: "r"(barId) : "memory");          \
            if ((ck) < 6) STAGE_H((ck) + 2)                                     \
            MMA_CHUNK(ck)
            ITER(0, 1) ITER(1, 1) ITER(2, 1) ITER(3, 1)
            ITER(4, 1) ITER(5, 1) ITER(6, 1) ITER(7, 0)
#undef ITER
            // ---- transpose gates via warp-private smem (dedicated region) ----
            {
                const int gid = lane >> 2, tig = lane & 3;
#pragma unroll
                for (int nt = 0; nt < 4; nt++) {
                    int cb = nt * 8 + 2 * tig;
                    smf[csW + gid * 36 + cb]           = c[nt][0];
                    smf[csW + gid * 36 + cb + 1]       = c[nt][1];
                    smf[csW + (gid + 8) * 36 + cb]     = c[nt][2];
                    smf[csW + (gid + 8) * 36 + cb + 1] = c[nt][3];
                }
            }
            __syncwarp();
        } else {
            asm volatile("cp.async.wait_group 0;" ::: "memory");  // xg(t=0)
        }

        // ---- epilogue: lane owns 4 cells: row wm+(lane>>1), hid (wh*8)+(lane&1)*4.. ----
        {
            const int rl = lane >> 1;
            const int hq = lane & 1;
            float4 gv[4];
            if (t > 0) {
#pragma unroll
                for (int k = 0; k < 4; k++)
                    gv[k] = *(float4*)&smf[csW + rl * 36 + hq * 16 + 4 * k];
            } else {
#pragma unroll
                for (int k = 0; k < 4; k++) gv[k] = make_float4(0, 0, 0, 0);
            }
            float4 xq[4];
#pragma unroll
            for (int q = 0; q < 4; q++)
                xq[q] = *(float4*)&smf[xgW + q * 128 + rl * 8 + hq * 4];

            float xiv[4] = {xq[0].x, xq[0].y, xq[0].z, xq[0].w};
            float xfv[4] = {xq[1].x, xq[1].y, xq[1].z, xq[1].w};
            float xgv[4] = {xq[2].x, xq[2].y, xq[2].z, xq[2].w};
            float xov[4] = {xq[3].x, xq[3].y, xq[3].z, xq[3].w};

            uint32_t hb[4];
#pragma unroll
            for (int k = 0; k < 4; k++) {
                float gi = gv[k].x + xiv[k];
                float gf = gv[k].y + xfv[k];
                float gg = gv[k].z + xgv[k];
                float go = gv[k].w + xov[k];
                float cn = sigmf(gf) * creg[k] + sigmf(gi) * tanhf(gg);
                float hn = sigmf(go) * tanhf(cn);
                creg[k] = cn;
                hb[k] = f2tf32(hn);
            }
            const int b = m0 + wm + rl;
            const int hh = h0 + wh * 8 + hq * 4;
            *(uint4*)&h_out[(size_t)b * HID + hh] = make_uint4(hb[0], hb[1], hb[2], hb[3]);
            if (layer == 0)
                *(uint4*)&g_hseq[((size_t)t * B_SZ + b) * HID + hh] =
                    make_uint4(hb[0], hb[1], hb[2], hb[3]);
        }

        // ---- prefetch xg for t+1 ----
        if (t + 1 < T_SZ) {
#pragma unroll
            for (int i = 0; i < 4; i++) {
                int idx = lane + 32 * i;
                int q = idx >> 5, r = (idx >> 1) & 15, gg = idx & 1;
                const float* src = g_xg + ((size_t)(t + 1) * B_SZ + m0 + wm + r) * G4
                                 + q * HID + h0 + wh * 8 + gg * 4;
                asm volatile("cp.async.cg.shared.global [%0], [%1], 16;"
                    :: "r"(xgBase + (uint32_t)(q * 512 + r * 32 + gg * 16)), "l"(src));
            }
            asm volatile("cp.async.commit_group;" ::: "memory");
        }

        // ---- publish own h (all warps' stores done -> flag) ----
        __syncthreads();
        if (tid == 0) {
            __threadfence();
            asm volatile("st.release.gpu.global.u64 [%0], %1;"
                         :: "l"(&g_flags[blockIdx.x]),
                            "l"(barBase + (unsigned long long)(t + 1)) : "memory");
        }
    }
#undef WCHUNK
#undef STAGE_H
#undef MMA_CHUNK
}

// ---------------- tensor-core GEMM (mma.sync): C = A @ W^T + bias ----------------
union SmemT {
    struct { uint32_t A[2][64][36]; uint32_t B[2][64][36]; } ld;
    float Cs[64][72];
};

__global__ __launch_bounds__(128) void gemm_tc(
    const float* __restrict__ Aext, int asel,
    const float* __restrict__ W,
    const float* __restrict__ bias1, const float* __restrict__ bias2,
    int csel, int N, int K, int remap)
{
    __shared__ SmemT sm;
    const float* A = (asel == 0) ? Aext : (asel == 1 ? g_hseq : g_hA);
    float* C = csel ? g_raw : g_xg;

    const int tid  = threadIdx.x;
    const int lane = tid & 31;
    const int warp = tid >> 5;
    const int wm   = (warp >> 1) * 32;
    const int wn   = (warp & 1) * 32;
    const int gid  = lane >> 2;
    const int tig  = lane & 3;
    const int m0   = blockIdx.y * 64;
    const int n0   = blockIdx.x * 64;

    float c[2][4][4];
#pragma unroll
    for (int mt = 0; mt < 2; mt++)
#pragma unroll
        for (int nt = 0; nt < 4; nt++)
#pragma unroll
            for (int q = 0; q < 4; q++) c[mt][nt][q] = 0.f;

    const int ktiles = (K + 31) >> 5;

#pragma unroll
    for (int i = 0; i < 4; i++) {
        int s = tid + i * 128;
        int row = s >> 3, kq = s & 7;
        int kk = kq * 4;
        float4 va = make_float4(0, 0, 0, 0), vb = make_float4(0, 0, 0, 0);
        if (kk < K) {
            va = *(const float4*)&A[(size_t)(m0 + row) * K + kk];
            int wr = n0 + row;
            if (wr < N) vb = *(const float4*)&W[(size_t)wr * K + kk];
        }
        *(uint4*)&sm.ld.A[0][row][kq * 4] =
            make_uint4(f2tf32(va.x), f2tf32(va.y), f2tf32(va.z), f2tf32(va.w));
        *(uint4*)&sm.ld.B[0][row][kq * 4] =
            make_uint4(f2tf32(vb.x), f2tf32(vb.y), f2tf32(vb.z), f2tf32(vb.w));
    }
    __syncthreads();

    float4 pa[4], pb[4];
    for (int kt = 0; kt < ktiles; kt++) {
        const int buf = kt & 1;
        const bool pf = (kt + 1 < ktiles);
        const int k0n = (kt + 1) << 5;
        if (pf) {
#pragma unroll
            for (int i = 0; i < 4; i++) {
                int s = tid + i * 128;
                int row = s >> 3, kq = s & 7;
                int kk = k0n + kq * 4;
                pa[i] = make_float4(0, 0, 0, 0);
                pb[i] = make_float4(0, 0, 0, 0);
                if (kk < K) {
                    pa[i] = *(const float4*)&A[(size_t)(m0 + row) * K + kk];
                    int wr = n0 + row;
                    if (wr < N) pb[i] = *(const float4*)&W[(size_t)wr * K + kk];
                }
            }
        }
#pragma unroll
        for (int kk8 = 0; kk8 < 4; kk8++) {
            uint32_t af[2][4];
#pragma unroll
            for (int mt = 0; mt < 2; mt++) {
                int r = wm + mt * 16 + gid;
                af[mt][0] = sm.ld.A[buf][r][kk8 * 8 + tig];
                af[mt][1] = sm.ld.A[buf][r + 8][kk8 * 8 + tig];
                af[mt][2] = sm.ld.A[buf][r][kk8 * 8 + tig + 4];
                af[mt][3] = sm.ld.A[buf][r + 8][kk8 * 8 + tig + 4];
            }
#pragma unroll
            for (int nt = 0; nt < 4; nt++) {
                uint32_t bf[2];
                int cn = wn + nt * 8 + gid;
                bf[0] = sm.ld.B[buf][cn][kk8 * 8 + tig];
                bf[1] = sm.ld.B[buf][cn][kk8 * 8 + tig + 4];
                mma_tf32(c[0][nt], af[0], bf);
                mma_tf32(c[1][nt], af[1], bf);
            }
        }
        if (pf) {
#pragma unroll
            for (int i = 0; i < 4; i++) {
                int s = tid + i * 128;
                int row = s >> 3, kq = s & 7;
                *(uint4*)&sm.ld.A[buf ^ 1][row][kq * 4] =
                    make_uint4(f2tf32(pa[i].x), f2tf32(pa[i].y), f2tf32(pa[i].z), f2tf32(pa[i].w));
                *(uint4*)&sm.ld.B[buf ^ 1][row][kq * 4] =
                    make_uint4(f2tf32(pb[i].x), f2tf32(pb[i].y), f2tf32(pb[i].z), f2tf32(pb[i].w));
            }
        }
        __syncthreads();
    }

#pragma unroll
    for (int mt = 0; mt < 2; mt++)
#pragma unroll
        for (int nt = 0; nt < 4; nt++) {
            int r  = wm + mt * 16 + gid;
            int cb = wn + nt * 8 + 2 * tig;
            sm.Cs[r][cb]         = c[mt][nt][0];
            sm.Cs[r][cb + 1]     = c[mt][nt][1];
            sm.Cs[r + 8][cb]     = c[mt][nt][2];
            sm.Cs[r + 8][cb + 1] = c[mt][nt][3];
        }
    __syncthreads();

#pragma unroll
    for (int i = 0; i < 8; i++) {
        int s = tid + i * 128;
        int row = s >> 4, cq = s & 15;
        int colb = n0 + cq * 4;
        if (colb < N) {
            float4 v = *(float4*)&sm.Cs[row][cq * 4];
            float4 b1 = *(const float4*)&bias1[colb];
            v.x += b1.x; v.y += b1.y; v.z += b1.z; v.w += b1.w;
            if (bias2) {
                float4 b2 = *(const float4*)&bias2[colb];
                v.x += b2.x; v.y += b2.y; v.z += b2.z; v.w += b2.w;
            }
            int m = m0 + row;
            int orow = remap ? ((m & 63) * 256 + (m >> 6)) : m;
            *(float4*)&C[(size_t)orow * N + colb] = v;
        }
    }
}

// ---------------- Sigma = (L*fv) @ L^T + diag(idio) ----------------
__global__ __launch_bounds__(256) void sigma_kernel(float* __restrict__ out)
{
    __shared__ float fvs[32];
    __shared__ float Ln[32][64];
    __shared__ float Lm[32][64];

    const int b  = blockIdx.z;
    const int n0 = blockIdx.y * 64;
    const int m0 = blockIdx.x * 64;
    const int tid = threadIdx.x;
    const int tx = tid & 15;
    const int ty = tid >> 4;
    const float* rb = g_raw + (size_t)b * RAWN;

    if (tid < 32) fvs[tid] = expf(rb[NA * NF + tid]);
    __syncthreads();

#pragma unroll
    for (int i = 0; i < 8; i++) {
        int idx = tid + i * 256;
        int nl = idx >> 5, f = idx & 31;
        int n = n0 + nl;
        float v = (n < NA) ? rb[n * NF + f] : 0.f;
        Ln[f][nl] = v * fvs[f];
        int m = m0 + nl;
        float w = (m < NA) ? rb[m * NF + f] : 0.f;
        Lm[f][nl] = w;
    }
    __syncthreads();

    float acc[4][4];
#pragma unroll
    for (int r = 0; r < 4; r++)
#pragma unroll
        for (int cc = 0; cc < 4; cc++) acc[r][cc] = 0.f;

#pragma unroll
    for (int f = 0; f < 32; f++) {
        float4 a  = *reinterpret_cast<const float4*>(&Ln[f][ty * 4]);
        float4 bb = *reinterpret_cast<const float4*>(&Lm[f][tx * 4]);
        float av[4] = {a.x, a.y, a.z, a.w};
        float bv[4] = {bb.x, bb.y, bb.z, bb.w};
#pragma unroll
        for (int r = 0; r < 4; r++)
#pragma unroll
            for (int cc = 0; cc < 4; cc++)
                acc[r][cc] = fmaf(av[r], bv[cc], acc[r][cc]);
    }

    const int mBase = m0 + tx * 4;
    if (mBase < NA) {
#pragma unroll
        for (int r = 0; r < 4; r++) {
            int n = n0 + ty * 4 + r;
            if (n >= NA) continue;
            float o[4] = {acc[r][0], acc[r][1], acc[r][2], acc[r][3]};
            int d = n - mBase;
            if (d >= 0 && d < 4) o[d] += expf(rb[NA * NF + NF + n]);
            float4 ov = {o[0], o[1], o[2], o[3]};
            *reinterpret_cast<float4*>(&out[(size_t)b * NA * NA + (size_t)n * NA + mBase]) = ov;
        }
    }
}

// ---------------- launch ----------------
extern "C" void kernel_launch(void* const* d_in, const int* in_sizes, int n_in,
                              void* d_out, int out_size)
{
    const float* x     = (const float*)d_in[0];
    const float* w_ih0 = (const float*)d_in[1];
    const float* w_hh0 = (const float*)d_in[2];
    const float* b_ih0 = (const float*)d_in[3];
    const float* b_hh0 = (const float*)d_in[4];
    const float* w_ih1 = (const float*)d_in[5];
    const float* w_hh1 = (const float*)d_in[6];
    const float* b_ih1 = (const float*)d_in[7];
    const float* b_hh1 = (const float*)d_in[8];
    const float* fc_w  = (const float*)d_in[9];
    const float* fc_b  = (const float*)d_in[10];
    float* out = (float*)d_out;

    static bool attr_done = false;
    if (!attr_done) {
        cudaFuncSetAttribute(lstm_persist,
            cudaFuncAttributeMaxDynamicSharedMemorySize, SM_BYTES);
        attr_done = true;
    }

    // layer 0
    gemm_tc<<<dim3(G4 / 64, (B_SZ * T_SZ) / 64), 128>>>(
        x, 0, w_ih0, b_ih0, b_hh0, 0, G4, IN_SZ, 1);
    lstm_persist<<<GRIDN, 256, SM_BYTES>>>(w_hh0, 0);

    // layer 1
    gemm_tc<<<dim3(G4 / 64, (B_SZ * T_SZ) / 64), 128>>>(
        nullptr, 1, w_ih1, b_ih1, b_hh1, 0, G4, HID, 0);
    lstm_persist<<<GRIDN, 256, SM_BYTES>>>(w_hh1, 1);
    // final h (t=63, odd) in g_hA

    // FC
    gemm_tc<<<dim3((RAWN + 63) / 64, B_SZ / 64), 128>>>(
        nullptr, 2, fc_w, fc_b, nullptr, 1, RAWN, HID, 0);

    // Sigma
    sigma_kernel<<<dim3(8, 8, B_SZ), 256>>>(out);
}

// round 9
// speedup vs baseline: 1.0439x; 1.0439x over previous
#include <cuda_runtime.h>
#include <math.h>
#include <stdint.h>

#define B_SZ   256
#define T_SZ   64
#define IN_SZ  500
#define HID    512
#define G4     2048
#define RAWN   16532
#define NA     500
#define NF     32
#define GRIDN  128

__device__ float g_xg[(size_t)T_SZ * B_SZ * G4];
__device__ float g_hseq[(size_t)T_SZ * B_SZ * HID];
__device__ float g_hA[B_SZ * HID];
__device__ float g_hB[B_SZ * HID];
__device__ float g_raw[(size_t)B_SZ * RAWN];
__device__ unsigned long long g_flags[GRIDN];

__device__ __forceinline__ float sigmf(float x) { return 1.f / (1.f + expf(-x)); }

__device__ __forceinline__ uint32_t f2tf32(float f) {
    uint32_t r;
    asm("cvt.rna.tf32.f32 %0, %1;" : "=r"(r) : "f"(f));
    return r;
}

__device__ __forceinline__ void mma_tf32(float* c, const uint32_t* a, const uint32_t* b) {
    asm volatile(
        "mma.sync.aligned.m16n8k8.row.col.f32.tf32.tf32.f32 "
        "{%0,%1,%2,%3}, {%4,%5,%6,%7}, {%8,%9}, {%0,%1,%2,%3};\n"
        : "+f"(c[0]), "+f"(c[1]), "+f"(c[2]), "+f"(c[3])
        : "r"(a[0]), "r"(a[1]), "r"(a[2]), "r"(a[3]), "r"(b[0]), "r"(b[1]));
}

__device__ __forceinline__ void ldsm_x4(uint32_t* r, uint32_t addr) {
    asm volatile("ldmatrix.sync.aligned.m8n8.x4.shared.b16 {%0,%1,%2,%3}, [%4];"
        : "=r"(r[0]), "=r"(r[1]), "=r"(r[2]), "=r"(r[3]) : "r"(addr));
}

__device__ __forceinline__ uint32_t smem_u32(const void* p) {
    uint32_t a;
    asm("{ .reg .u64 t; cvta.to.shared.u64 t, %1; cvt.u32.u64 %0, t; }" : "=r"(a) : "l"(p));
    return a;
}

// ================= persistent LSTM layer (R7 best-measured variant) =================
#define W_STR   516
#define A_STR   68
#define OFF_AP  132096
#define PAIR_ST 17408
#define BUF_ST  4352
#define OFF_XG  201728
#define SM_BYTES 218112

__global__ __launch_bounds__(256, 1) void lstm_persist(
    const float* __restrict__ w_hh, int layer)
{
    extern __shared__ __align__(16) uint32_t smraw[];
    uint32_t* Wsm = smraw;
    float*    smf = (float*)smraw;
    const uint32_t smem = smem_u32(smraw);

    const int tid  = threadIdx.x;
    const int lane = tid & 31;
    const int warp = tid >> 5;
    const int pair = warp >> 1;
    const int wh   = warp & 1;
    const int wm   = pair * 16;
    const int wn   = wh * 32;
    const int h0   = (blockIdx.x & 31) * 16;
    const int m0   = (blockIdx.x >> 5) * 64;

#pragma unroll
    for (int i = 0; i < 32; i++) {
        int s   = tid + (i << 8);
        int row = s >> 7;
        int kq  = s & 127;
        int wr  = ((row & 3) << 9) + h0 + (row >> 2);
        float4 v = *(const float4*)&w_hh[(size_t)wr * HID + (kq << 2)];
        *(uint4*)&Wsm[row * W_STR + (kq << 2)] =
            make_uint4(f2tf32(v.x), f2tf32(v.y), f2tf32(v.z), f2tf32(v.w));
    }

    const uint32_t pairBase = smem + OFF_AP + (uint32_t)pair * PAIR_ST;
    const uint32_t aFrag = pairBase
        + (uint32_t)(((lane & 15) * A_STR + (lane >> 4) * 4) << 2);
    const uint32_t rB = wn + (lane & 7) + ((lane & 16) ? 8 : 0);
    const uint32_t bBase0 = smem + (uint32_t)((rB * W_STR + ((lane >> 3) & 1) * 4) << 2);
    const uint32_t bBase1 = bBase0 + 16 * W_STR * 4;

    const int sRowBase = wh * 8;
    const uint32_t xgBase = smem + OFF_XG + (uint32_t)warp * 2048;
    const int xgW = (int)(OFF_XG / 4) + warp * 512;
    const int csW = (int)(OFF_AP / 4) + pair * (PAIR_ST / 4) + wh * 576;

    const unsigned long long barBase =
        *(volatile unsigned long long*)&g_flags[blockIdx.x];

    float creg[4] = {0.f, 0.f, 0.f, 0.f};
    const int barId = 1 + pair;

    __syncthreads();

    {
#pragma unroll
        for (int i = 0; i < 4; i++) {
            int idx = lane + 32 * i;
            int q = idx >> 5, r = (idx >> 1) & 15, gg = idx & 1;
            const float* src = g_xg + ((size_t)0 * B_SZ + m0 + wm + r) * G4
                             + q * HID + h0 + wh * 8 + gg * 4;
            asm volatile("cp.async.cg.shared.global [%0], [%1], 16;"
                :: "r"(xgBase + (uint32_t)(q * 512 + r * 32 + gg * 16)), "l"(src));
        }
        asm volatile("cp.async.commit_group;" ::: "memory");
    }

#define STAGE_H(c)                                                              \
    {                                                                           \
        uint32_t dbuf = pairBase + (uint32_t)(((c) & 3) * BUF_ST);              \
        _Pragma("unroll")                                                       \
        for (int i = 0; i < 4; i++) {                                           \
            int idx = lane + 32 * i;                                            \
            int rl = sRowBase + (idx >> 4);                                     \
            int gr = idx & 15;                                                  \
            const float* src = h_in + (size_t)(m0 + wm + rl) * HID              \
                             + (c) * 64 + gr * 4;                               \
            asm volatile("cp.async.cg.shared.global [%0], [%1], 16;"            \
                :: "r"(dbuf + (uint32_t)(rl * 272 + gr * 16)), "l"(src));       \
        }                                                                       \
        asm volatile("cp.async.commit_group;" ::: "memory");                    \
    }

#define MMA_CHUNK(ck)                                                           \
    {                                                                           \
        const uint32_t ab  = aFrag  + (uint32_t)(((ck) & 3) * BUF_ST);          \
        const uint32_t wb0 = bBase0 + (uint32_t)((ck) * 256);                   \
        const uint32_t wb1 = bBase1 + (uint32_t)((ck) * 256);                   \
        _Pragma("unroll")                                                       \
        for (int k8 = 0; k8 < 8; k8++) {                                        \
            uint32_t a[4], b0[4], b1[4];                                        \
            ldsm_x4(a,  ab  + (uint32_t)(k8 * 32));                             \
            ldsm_x4(b0, wb0 + (uint32_t)(k8 * 32));                             \
            ldsm_x4(b1, wb1 + (uint32_t)(k8 * 32));                             \
            mma_tf32(c[0], a, b0);                                              \
            mma_tf32(c[1], a, b0 + 2);                                          \
            mma_tf32(c[2], a, b1);                                              \
            mma_tf32(c[3], a, b1 + 2);                                          \
        }                                                                       \
    }

    for (int t = 0; t < T_SZ; t++) {
        const float* h_in = (t & 1) ? g_hB : g_hA;
        float* h_out      = (t & 1) ? g_hA : g_hB;

        float c[4][4];
#pragma unroll
        for (int nt = 0; nt < 4; nt++)
#pragma unroll
            for (int q = 0; q < 4; q++) c[nt][q] = 0.f;

        if (t > 0) {
            STAGE_H(0) STAGE_H(1) STAGE_H(2)
#define ITER(ck, WN)                                                            \
            asm volatile("cp.async.wait_group " #WN ";" ::: "memory");          \
            asm volatile("bar.sync %0, 64;" :: "r"(barId) : "memory");          \
            if ((ck) <= 4) STAGE_H((ck) + 3)                                    \
            MMA_CHUNK(ck)
            ITER(0, 2) ITER(1, 2) ITER(2, 2) ITER(3, 2)
            ITER(4, 2) ITER(5, 2) ITER(6, 1) ITER(7, 0)
#undef ITER
            {
                const int gid = lane >> 2, tig = lane & 3;
#pragma unroll
                for (int nt = 0; nt < 4; nt++) {
                    int cb = nt * 8 + 2 * tig;
                    smf[csW + gid * 36 + cb]           = c[nt][0];
                    smf[csW + gid * 36 + cb + 1]       = c[nt][1];
                    smf[csW + (gid + 8) * 36 + cb]     = c[nt][2];
                    smf[csW + (gid + 8) * 36 + cb + 1] = c[nt][3];
                }
            }
        } else {
            asm volatile("cp.async.wait_group 0;" ::: "memory");
        }
        __syncwarp();

        {
            const int rl = lane >> 1;
            const int hq = lane & 1;
            float4 gv[4];
            if (t > 0) {
#pragma unroll
                for (int k = 0; k < 4; k++)
                    gv[k] = *(float4*)&smf[csW + rl * 36 + hq * 16 + 4 * k];
            } else {
#pragma unroll
                for (int k = 0; k < 4; k++) gv[k] = make_float4(0, 0, 0, 0);
            }
            float4 xq[4];
#pragma unroll
            for (int q = 0; q < 4; q++)
                xq[q] = *(float4*)&smf[xgW + q * 128 + rl * 8 + hq * 4];

            float xiv[4] = {xq[0].x, xq[0].y, xq[0].z, xq[0].w};
            float xfv[4] = {xq[1].x, xq[1].y, xq[1].z, xq[1].w};
            float xgv[4] = {xq[2].x, xq[2].y, xq[2].z, xq[2].w};
            float xov[4] = {xq[3].x, xq[3].y, xq[3].z, xq[3].w};

            uint32_t hb[4];
#pragma unroll
            for (int k = 0; k < 4; k++) {
                float gi = gv[k].x + xiv[k];
                float gf = gv[k].y + xfv[k];
                float gg = gv[k].z + xgv[k];
                float go = gv[k].w + xov[k];
                float cn = sigmf(gf) * creg[k] + sigmf(gi) * tanhf(gg);
                float hn = sigmf(go) * tanhf(cn);
                creg[k] = cn;
                hb[k] = f2tf32(hn);
            }
            const int b = m0 + wm + rl;
            const int hh = h0 + wh * 8 + hq * 4;
            *(uint4*)&h_out[(size_t)b * HID + hh] = make_uint4(hb[0], hb[1], hb[2], hb[3]);
            if (layer == 0)
                *(uint4*)&g_hseq[((size_t)t * B_SZ + b) * HID + hh] =
                    make_uint4(hb[0], hb[1], hb[2], hb[3]);
        }

        if (t + 1 < T_SZ) {
#pragma unroll
            for (int i = 0; i < 4; i++) {
                int idx = lane + 32 * i;
                int q = idx >> 5, r = (idx >> 1) & 15, gg = idx & 1;
                const float* src = g_xg + ((size_t)(t + 1) * B_SZ + m0 + wm + r) * G4
                                 + q * HID + h0 + wh * 8 + gg * 4;
                asm volatile("cp.async.cg.shared.global [%0], [%1], 16;"
                    :: "r"(xgBase + (uint32_t)(q * 512 + r * 32 + gg * 16)), "l"(src));
            }
            asm volatile("cp.async.commit_group;" ::: "memory");

            __syncthreads();
            const unsigned long long tgt = barBase + (unsigned long long)(t + 1);
            if (tid == 0)
                asm volatile("st.release.gpu.global.u64 [%0], %1;"
                             :: "l"(&g_flags[blockIdx.x]), "l"(tgt) : "memory");
            if (tid < GRIDN) {
                unsigned long long v;
                do {
                    asm volatile("ld.acquire.gpu.global.u64 %0, [%1];"
                                 : "=l"(v) : "l"(&g_flags[tid]) : "memory");
                } while (v < tgt);
            }
            __syncthreads();
        }
    }
#undef STAGE_H
#undef MMA_CHUNK
}

// ============ tensor-core GEMM v2: 128x64 tile, 256 thr, ldmatrix ============
// C = A @ W^T + bias1 (+bias2).  A: MxK fp32 (M mult of 128), W: NxK, C: MxN.
// smem (dynamic): As [2][128][36]u32 @0 (36864B), Bs [2][64][36]u32 @36864 (18432B).
// Cs fp32 [128][68] aliases base (34816B < 55296B).
#define G_AST   36
#define G_ABUF  18432
#define G_BOFF  36864
#define G_BBUF  9216
#define G_CST   68
#define SM_BYTES_G 55296

__global__ __launch_bounds__(256) void gemm_tc(
    const float* __restrict__ Aext, int asel,
    const float* __restrict__ W,
    const float* __restrict__ bias1, const float* __restrict__ bias2,
    int csel, int N, int K, int remap)
{
    extern __shared__ __align__(16) uint32_t gsm[];
    uint32_t* As = gsm;                    // [2][128][36]
    uint32_t* Bs = gsm + G_BOFF / 4;       // [2][64][36]
    float*    Cs = (float*)gsm;            // [128][68]
    const uint32_t smem = smem_u32(gsm);

    const float* A = (asel == 0) ? Aext : (asel == 1 ? g_hseq : g_hA);
    float* C = csel ? g_raw : g_xg;

    const int tid  = threadIdx.x;
    const int lane = tid & 31;
    const int warp = tid >> 5;
    const int wm   = (warp >> 1) * 32;    // 4 warps along M (128)
    const int wn   = (warp & 1) * 32;     // 2 warps along N (64)
    const int m0   = blockIdx.y * 128;
    const int n0   = blockIdx.x * 64;

    float c[2][4][4];
#pragma unroll
    for (int mt = 0; mt < 2; mt++)
#pragma unroll
        for (int nt = 0; nt < 4; nt++)
#pragma unroll
            for (int q = 0; q < 4; q++) c[mt][nt][q] = 0.f;

    const int ktiles = (K + 31) >> 5;

    // ldmatrix fragment offsets (within a buffer)
    const uint32_t aOff = (uint32_t)(((wm + (lane & 15)) * G_AST + (lane >> 4) * 4) << 2);
    const uint32_t bRow = wn + (lane & 7) + ((lane & 16) ? 8 : 0);
    const uint32_t bOff = (uint32_t)((bRow * G_AST + ((lane >> 3) & 1) * 4) << 2);

    // ---- load tile 0 ----
#pragma unroll
    for (int i = 0; i < 4; i++) {         // A: 1024 granules
        int idx = tid + (i << 8);
        int row = idx >> 3, kq = idx & 7;
        int kk = kq << 2;
        float4 v = make_float4(0, 0, 0, 0);
        if (kk < K) v = *(const float4*)&A[(size_t)(m0 + row) * K + kk];
        *(uint4*)&As[row * G_AST + kk] =
            make_uint4(f2tf32(v.x), f2tf32(v.y), f2tf32(v.z), f2tf32(v.w));
    }
#pragma unroll
    for (int i = 0; i < 2; i++) {         // B: 512 granules
        int idx = tid + (i << 8);
        int row = idx >> 3, kq = idx & 7;
        int kk = kq << 2;
        int wr = n0 + row;
        float4 v = make_float4(0, 0, 0, 0);
        if (kk < K && wr < N) v = *(const float4*)&W[(size_t)wr * K + kk];
        *(uint4*)&Bs[row * G_AST + kk] =
            make_uint4(f2tf32(v.x), f2tf32(v.y), f2tf32(v.z), f2tf32(v.w));
    }
    __syncthreads();

    float4 pa[4], pb[2];
    for (int kt = 0; kt < ktiles; kt++) {
        const int buf = kt & 1;
        const bool pf = (kt + 1 < ktiles);
        const int k0n = (kt + 1) << 5;
        if (pf) {
#pragma unroll
            for (int i = 0; i < 4; i++) {
                int idx = tid + (i << 8);
                int row = idx >> 3, kq = idx & 7;
                int kk = k0n + (kq << 2);
                pa[i] = make_float4(0, 0, 0, 0);
                if (kk < K) pa[i] = *(const float4*)&A[(size_t)(m0 + row) * K + kk];
            }
#pragma unroll
            for (int i = 0; i < 2; i++) {
                int idx = tid + (i << 8);
                int row = idx >> 3, kq = idx & 7;
                int kk = k0n + (kq << 2);
                int wr = n0 + row;
                pb[i] = make_float4(0, 0, 0, 0);
                if (kk < K && wr < N) pb[i] = *(const float4*)&W[(size_t)wr * K + kk];
            }
        }

        const uint32_t abuf = smem + (uint32_t)(buf * G_ABUF);
        const uint32_t bbuf = smem + (uint32_t)(G_BOFF + buf * G_BBUF);
#pragma unroll
        for (int k8 = 0; k8 < 4; k8++) {
            uint32_t fa0[4], fa1[4], fb0[4], fb1[4];
            ldsm_x4(fa0, abuf + aOff + (uint32_t)(k8 * 32));
            ldsm_x4(fa1, abuf + aOff + (uint32_t)(16 * G_AST * 4 + k8 * 32));
            ldsm_x4(fb0, bbuf + bOff + (uint32_t)(k8 * 32));
            ldsm_x4(fb1, bbuf + bOff + (uint32_t)(16 * G_AST * 4 + k8 * 32));
            mma_tf32(c[0][0], fa0, fb0);
            mma_tf32(c[0][1], fa0, fb0 + 2);
            mma_tf32(c[0][2], fa0, fb1);
            mma_tf32(c[0][3], fa0, fb1 + 2);
            mma_tf32(c[1][0], fa1, fb0);
            mma_tf32(c[1][1], fa1, fb0 + 2);
            mma_tf32(c[1][2], fa1, fb1);
            mma_tf32(c[1][3], fa1, fb1 + 2);
        }

        if (pf) {
            __syncthreads();   // done reading buf^1 from 2 iters ago? (write target)
#pragma unroll
            for (int i = 0; i < 4; i++) {
                int idx = tid + (i << 8);
                int row = idx >> 3, kq = idx & 7;
                *(uint4*)&As[(buf ^ 1) * (G_ABUF / 4) + row * G_AST + (kq << 2)] =
                    make_uint4(f2tf32(pa[i].x), f2tf32(pa[i].y), f2tf32(pa[i].z), f2tf32(pa[i].w));
            }
#pragma unroll
            for (int i = 0; i < 2; i++) {
                int idx = tid + (i << 8);
                int row = idx >> 3, kq = idx & 7;
                *(uint4*)&Bs[(buf ^ 1) * (G_BBUF / 4) + row * G_AST + (kq << 2)] =
                    make_uint4(f2tf32(pb[i].x), f2tf32(pb[i].y), f2tf32(pb[i].z), f2tf32(pb[i].w));
            }
        }
        __syncthreads();
    }

    // ---- stage C to smem (aliases tile buffers; mainloop done) ----
    {
        const int gid = lane >> 2, tig = lane & 3;
#pragma unroll
        for (int mt = 0; mt < 2; mt++)
#pragma unroll
            for (int nt = 0; nt < 4; nt++) {
                int r  = wm + mt * 16 + gid;
                int cb = wn + nt * 8 + 2 * tig;
                Cs[r * G_CST + cb]               = c[mt][nt][0];
                Cs[r * G_CST + cb + 1]           = c[mt][nt][1];
                Cs[(r + 8) * G_CST + cb]         = c[mt][nt][2];
                Cs[(r + 8) * G_CST + cb + 1]     = c[mt][nt][3];
            }
    }
    __syncthreads();

    // ---- coalesced output with bias ----
#pragma unroll
    for (int i = 0; i < 8; i++) {
        int idx = tid + (i << 8);
        int row = idx >> 4, cq = idx & 15;
        int colb = n0 + cq * 4;
        if (colb < N) {   // N % 4 == 0 in all uses
            float4 v = *(float4*)&Cs[row * G_CST + cq * 4];
            float4 b1 = *(const float4*)&bias1[colb];
            v.x += b1.x; v.y += b1.y; v.z += b1.z; v.w += b1.w;
            if (bias2) {
                float4 b2 = *(const float4*)&bias2[colb];
                v.x += b2.x; v.y += b2.y; v.z += b2.z; v.w += b2.w;
            }
            int m = m0 + row;
            int orow = remap ? ((m & 63) * 256 + (m >> 6)) : m;
            *(float4*)&C[(size_t)orow * N + colb] = v;
        }
    }
}

// ---------------- Sigma = (L*fv) @ L^T + diag(idio) ----------------
__global__ __launch_bounds__(256) void sigma_kernel(float* __restrict__ out)
{
    __shared__ float fvs[32];
    __shared__ float Ln[32][64];
    __shared__ float Lm[32][64];

    const int b  = blockIdx.z;
    const int n0 = blockIdx.y * 64;
    const int m0 = blockIdx.x * 64;
    const int tid = threadIdx.x;
    const int tx = tid & 15;
    const int ty = tid >> 4;
    const float* rb = g_raw + (size_t)b * RAWN;

    if (tid < 32) fvs[tid] = expf(rb[NA * NF + tid]);
    __syncthreads();

#pragma unroll
    for (int i = 0; i < 8; i++) {
        int idx = tid + i * 256;
        int nl = idx >> 5, f = idx & 31;
        int n = n0 + nl;
        float v = (n < NA) ? rb[n * NF + f] : 0.f;
        Ln[f][nl] = v * fvs[f];
        int m = m0 + nl;
        float w = (m < NA) ? rb[m * NF + f] : 0.f;
        Lm[f][nl] = w;
    }
    __syncthreads();

    float acc[4][4];
#pragma unroll
    for (int r = 0; r < 4; r++)
#pragma unroll
        for (int cc = 0; cc < 4; cc++) acc[r][cc] = 0.f;

#pragma unroll
    for (int f = 0; f < 32; f++) {
        float4 a  = *reinterpret_cast<const float4*>(&Ln[f][ty * 4]);
        float4 bb = *reinterpret_cast<const float4*>(&Lm[f][tx * 4]);
        float av[4] = {a.x, a.y, a.z, a.w};
        float bv[4] = {bb.x, bb.y, bb.z, bb.w};
#pragma unroll
        for (int r = 0; r < 4; r++)
#pragma unroll
            for (int cc = 0; cc < 4; cc++)
                acc[r][cc] = fmaf(av[r], bv[cc], acc[r][cc]);
    }

    const int mBase = m0 + tx * 4;
    if (mBase < NA) {
#pragma unroll
        for (int r = 0; r < 4; r++) {
            int n = n0 + ty * 4 + r;
            if (n >= NA) continue;
            float o[4] = {acc[r][0], acc[r][1], acc[r][2], acc[r][3]};
            int d = n - mBase;
            if (d >= 0 && d < 4) o[d] += expf(rb[NA * NF + NF + n]);
            float4 ov = {o[0], o[1], o[2], o[3]};
            *reinterpret_cast<float4*>(&out[(size_t)b * NA * NA + (size_t)n * NA + mBase]) = ov;
        }
    }
}

// ---------------- launch ----------------
extern "C" void kernel_launch(void* const* d_in, const int* in_sizes, int n_in,
                              void* d_out, int out_size)
{
    const float* x     = (const float*)d_in[0];
    const float* w_ih0 = (const float*)d_in[1];
    const float* w_hh0 = (const float*)d_in[2];
    const float* b_ih0 = (const float*)d_in[3];
    const float* b_hh0 = (const float*)d_in[4];
    const float* w_ih1 = (const float*)d_in[5];
    const float* w_hh1 = (const float*)d_in[6];
    const float* b_ih1 = (const float*)d_in[7];
    const float* b_hh1 = (const float*)d_in[8];
    const float* fc_w  = (const float*)d_in[9];
    const float* fc_b  = (const float*)d_in[10];
    float* out = (float*)d_out;

    static bool attr_done = false;
    if (!attr_done) {
        cudaFuncSetAttribute(lstm_persist,
            cudaFuncAttributeMaxDynamicSharedMemorySize, SM_BYTES);
        cudaFuncSetAttribute(gemm_tc,
            cudaFuncAttributeMaxDynamicSharedMemorySize, SM_BYTES_G);
        attr_done = true;
    }

    // layer 0
    gemm_tc<<<dim3(G4 / 64, (B_SZ * T_SZ) / 128), 256, SM_BYTES_G>>>(
        x, 0, w_ih0, b_ih0, b_hh0, 0, G4, IN_SZ, 1);
    lstm_persist<<<GRIDN, 256, SM_BYTES>>>(w_hh0, 0);

    // layer 1
    gemm_tc<<<dim3(G4 / 64, (B_SZ * T_SZ) / 128), 256, SM_BYTES_G>>>(
        nullptr, 1, w_ih1, b_ih1, b_hh1, 0, G4, HID, 0);
    lstm_persist<<<GRIDN, 256, SM_BYTES>>>(w_hh1, 1);
    // final h (t=63, odd) in g_hA

    // FC
    gemm_tc<<<dim3((RAWN + 63) / 64, B_SZ / 128), 256, SM_BYTES_G>>>(
        nullptr, 2, fc_w, fc_b, nullptr, 1, RAWN, HID, 0);

    // Sigma
    sigma_kernel<<<dim3(8, 8, B_SZ), 256>>>(out);
}

// round 10
// speedup vs baseline: 1.0588x; 1.0143x over previous
#include <cuda_runtime.h>
#include <math.h>
#include <stdint.h>

#define B_SZ   256
#define T_SZ   64
#define IN_SZ  500
#define HID    512
#define G4     2048
#define RAWN   16532
#define NA     500
#define NF     32
#define GRIDN  128

__device__ float g_xg[(size_t)T_SZ * B_SZ * G4];
__device__ float g_hseq[(size_t)T_SZ * B_SZ * HID];
__device__ float g_hA[B_SZ * HID];
__device__ float g_hB[B_SZ * HID];
__device__ float g_raw[(size_t)B_SZ * RAWN];
__device__ unsigned long long g_flags[GRIDN];
// pre-converted tf32-bit operands
__device__ uint32_t g_xc[(size_t)T_SZ * B_SZ * HID];    // x, [t][b][512] padded
__device__ uint32_t g_wc0[(size_t)G4 * HID];            // w_ih0 padded 500->512
__device__ uint32_t g_wc1[(size_t)G4 * HID];            // w_ih1
__device__ uint32_t g_wfc[(size_t)RAWN * HID];          // fc_w

__device__ __forceinline__ float sigmf(float x) { return 1.f / (1.f + expf(-x)); }

__device__ __forceinline__ uint32_t f2tf32(float f) {
    uint32_t r;
    asm("cvt.rna.tf32.f32 %0, %1;" : "=r"(r) : "f"(f));
    return r;
}

__device__ __forceinline__ void mma_tf32(float* c, const uint32_t* a, const uint32_t* b) {
    asm volatile(
        "mma.sync.aligned.m16n8k8.row.col.f32.tf32.tf32.f32 "
        "{%0,%1,%2,%3}, {%4,%5,%6,%7}, {%8,%9}, {%0,%1,%2,%3};\n"
        : "+f"(c[0]), "+f"(c[1]), "+f"(c[2]), "+f"(c[3])
        : "r"(a[0]), "r"(a[1]), "r"(a[2]), "r"(a[3]), "r"(b[0]), "r"(b[1]));
}

__device__ __forceinline__ void ldsm_x4(uint32_t* r, uint32_t addr) {
    asm volatile("ldmatrix.sync.aligned.m8n8.x4.shared.b16 {%0,%1,%2,%3}, [%4];"
        : "=r"(r[0]), "=r"(r[1]), "=r"(r[2]), "=r"(r[3]) : "r"(addr));
}

__device__ __forceinline__ uint32_t smem_u32(const void* p) {
    uint32_t a;
    asm("{ .reg .u64 t; cvta.to.shared.u64 t, %1; cvt.u32.u64 %0, t; }" : "=r"(a) : "l"(p));
    return a;
}

// ---------------- prep kernels: convert to tf32 bits ----------------
__global__ void cvt_pad_kernel(const float* __restrict__ in, uint32_t* __restrict__ out,
                               int Nrows, int Kin)
{
    size_t idx = (size_t)blockIdx.x * 256 + threadIdx.x;
    if (idx >= (size_t)Nrows * 512) return;
    int n = (int)(idx >> 9), k = (int)(idx & 511);
    out[idx] = (k < Kin) ? f2tf32(in[(size_t)n * Kin + k]) : 0u;
}

__global__ void cvt_x_kernel(const float* __restrict__ x, uint32_t* __restrict__ out)
{
    size_t idx = (size_t)blockIdx.x * 256 + threadIdx.x;   // over 64*256*512
    int r = (int)(idx >> 9), k = (int)(idx & 511);
    int t = r >> 8, b = r & 255;
    out[idx] = (k < IN_SZ) ? f2tf32(x[((size_t)b * T_SZ + t) * IN_SZ + k]) : 0u;
}

// ================= persistent LSTM layer (R7/R9 measured-best) =================
#define W_STR   516
#define A_STR   68
#define OFF_AP  132096
#define PAIR_ST 17408
#define BUF_ST  4352
#define OFF_XG  201728
#define SM_BYTES 218112

__global__ __launch_bounds__(256, 1) void lstm_persist(
    const float* __restrict__ w_hh, int layer)
{
    extern __shared__ __align__(16) uint32_t smraw[];
    uint32_t* Wsm = smraw;
    float*    smf = (float*)smraw;
    const uint32_t smem = smem_u32(smraw);

    const int tid  = threadIdx.x;
    const int lane = tid & 31;
    const int warp = tid >> 5;
    const int pair = warp >> 1;
    const int wh   = warp & 1;
    const int wm   = pair * 16;
    const int wn   = wh * 32;
    const int h0   = (blockIdx.x & 31) * 16;
    const int m0   = (blockIdx.x >> 5) * 64;

#pragma unroll
    for (int i = 0; i < 32; i++) {
        int s   = tid + (i << 8);
        int row = s >> 7;
        int kq  = s & 127;
        int wr  = ((row & 3) << 9) + h0 + (row >> 2);
        float4 v = *(const float4*)&w_hh[(size_t)wr * HID + (kq << 2)];
        *(uint4*)&Wsm[row * W_STR + (kq << 2)] =
            make_uint4(f2tf32(v.x), f2tf32(v.y), f2tf32(v.z), f2tf32(v.w));
    }

    const uint32_t pairBase = smem + OFF_AP + (uint32_t)pair * PAIR_ST;
    const uint32_t aFrag = pairBase
        + (uint32_t)(((lane & 15) * A_STR + (lane >> 4) * 4) << 2);
    const uint32_t rB = wn + (lane & 7) + ((lane & 16) ? 8 : 0);
    const uint32_t bBase0 = smem + (uint32_t)((rB * W_STR + ((lane >> 3) & 1) * 4) << 2);
    const uint32_t bBase1 = bBase0 + 16 * W_STR * 4;

    const int sRowBase = wh * 8;
    const uint32_t xgBase = smem + OFF_XG + (uint32_t)warp * 2048;
    const int xgW = (int)(OFF_XG / 4) + warp * 512;
    const int csW = (int)(OFF_AP / 4) + pair * (PAIR_ST / 4) + wh * 576;

    const unsigned long long barBase =
        *(volatile unsigned long long*)&g_flags[blockIdx.x];

    float creg[4] = {0.f, 0.f, 0.f, 0.f};
    const int barId = 1 + pair;

    __syncthreads();

    {
#pragma unroll
        for (int i = 0; i < 4; i++) {
            int idx = lane + 32 * i;
            int q = idx >> 5, r = (idx >> 1) & 15, gg = idx & 1;
            const float* src = g_xg + ((size_t)0 * B_SZ + m0 + wm + r) * G4
                             + q * HID + h0 + wh * 8 + gg * 4;
            asm volatile("cp.async.cg.shared.global [%0], [%1], 16;"
                :: "r"(xgBase + (uint32_t)(q * 512 + r * 32 + gg * 16)), "l"(src));
        }
        asm volatile("cp.async.commit_group;" ::: "memory");
    }

#define STAGE_H(c)                                                              \
    {                                                                           \
        uint32_t dbuf = pairBase + (uint32_t)(((c) & 3) * BUF_ST);              \
        _Pragma("unroll")                                                       \
        for (int i = 0; i < 4; i++) {                                           \
            int idx = lane + 32 * i;                                            \
            int rl = sRowBase + (idx >> 4);                                     \
            int gr = idx & 15;                                                  \
            const float* src = h_in + (size_t)(m0 + wm + rl) * HID              \
                             + (c) * 64 + gr * 4;                               \
            asm volatile("cp.async.cg.shared.global [%0], [%1], 16;"            \
                :: "r"(dbuf + (uint32_t)(rl * 272 + gr * 16)), "l"(src));       \
        }                                                                       \
        asm volatile("cp.async.commit_group;" ::: "memory");                    \
    }

#define MMA_CHUNK(ck)                                                           \
    {                                                                           \
        const uint32_t ab  = aFrag  + (uint32_t)(((ck) & 3) * BUF_ST);          \
        const uint32_t wb0 = bBase0 + (uint32_t)((ck) * 256);                   \
        const uint32_t wb1 = bBase1 + (uint32_t)((ck) * 256);                   \
        _Pragma("unroll")                                                       \
        for (int k8 = 0; k8 < 8; k8++) {                                        \
            uint32_t a[4], b0[4], b1[4];                                        \
            ldsm_x4(a,  ab  + (uint32_t)(k8 * 32));                             \
            ldsm_x4(b0, wb0 + (uint32_t)(k8 * 32));                             \
            ldsm_x4(b1, wb1 + (uint32_t)(k8 * 32));                             \
            mma_tf32(c[0], a, b0);                                              \
            mma_tf32(c[1], a, b0 + 2);                                          \
            mma_tf32(c[2], a, b1);                                              \
            mma_tf32(c[3], a, b1 + 2);                                          \
        }                                                                       \
    }

    for (int t = 0; t < T_SZ; t++) {
        const float* h_in = (t & 1) ? g_hB : g_hA;
        float* h_out      = (t & 1) ? g_hA : g_hB;

        float c[4][4];
#pragma unroll
        for (int nt = 0; nt < 4; nt++)
#pragma unroll
            for (int q = 0; q < 4; q++) c[nt][q] = 0.f;

        if (t > 0) {
            STAGE_H(0) STAGE_H(1) STAGE_H(2)
#define ITER(ck, WN)                                                            \
            asm volatile("cp.async.wait_group " #WN ";" ::: "memory");          \
            asm volatile("bar.sync %0, 64;" :: "r"(barId) : "memory");          \
            if ((ck) <= 4) STAGE_H((ck) + 3)                                    \
            MMA_CHUNK(ck)
            ITER(0, 2) ITER(1, 2) ITER(2, 2) ITER(3, 2)
            ITER(4, 2) ITER(5, 2) ITER(6, 1) ITER(7, 0)
#undef ITER
            {
                const int gid = lane >> 2, tig = lane & 3;
#pragma unroll
                for (int nt = 0; nt < 4; nt++) {
                    int cb = nt * 8 + 2 * tig;
                    smf[csW + gid * 36 + cb]           = c[nt][0];
                    smf[csW + gid * 36 + cb + 1]       = c[nt][1];
                    smf[csW + (gid + 8) * 36 + cb]     = c[nt][2];
                    smf[csW + (gid + 8) * 36 + cb + 1] = c[nt][3];
                }
            }
        } else {
            asm volatile("cp.async.wait_group 0;" ::: "memory");
        }
        __syncwarp();

        {
            const int rl = lane >> 1;
            const int hq = lane & 1;
            float4 gv[4];
            if (t > 0) {
#pragma unroll
                for (int k = 0; k < 4; k++)
                    gv[k] = *(float4*)&smf[csW + rl * 36 + hq * 16 + 4 * k];
            } else {
#pragma unroll
                for (int k = 0; k < 4; k++) gv[k] = make_float4(0, 0, 0, 0);
            }
            float4 xq[4];
#pragma unroll
            for (int q = 0; q < 4; q++)
                xq[q] = *(float4*)&smf[xgW + q * 128 + rl * 8 + hq * 4];

            float xiv[4] = {xq[0].x, xq[0].y, xq[0].z, xq[0].w};
            float xfv[4] = {xq[1].x, xq[1].y, xq[1].z, xq[1].w};
            float xgv[4] = {xq[2].x, xq[2].y, xq[2].z, xq[2].w};
            float xov[4] = {xq[3].x, xq[3].y, xq[3].z, xq[3].w};

            uint32_t hb[4];
#pragma unroll
            for (int k = 0; k < 4; k++) {
                float gi = gv[k].x + xiv[k];
                float gf = gv[k].y + xfv[k];
                float gg = gv[k].z + xgv[k];
                float go = gv[k].w + xov[k];
                float cn = sigmf(gf) * creg[k] + sigmf(gi) * tanhf(gg);
                float hn = sigmf(go) * tanhf(cn);
                creg[k] = cn;
                hb[k] = f2tf32(hn);
            }
            const int b = m0 + wm + rl;
            const int hh = h0 + wh * 8 + hq * 4;
            *(uint4*)&h_out[(size_t)b * HID + hh] = make_uint4(hb[0], hb[1], hb[2], hb[3]);
            if (layer == 0)
                *(uint4*)&g_hseq[((size_t)t * B_SZ + b) * HID + hh] =
                    make_uint4(hb[0], hb[1], hb[2], hb[3]);
        }

        if (t + 1 < T_SZ) {
#pragma unroll
            for (int i = 0; i < 4; i++) {
                int idx = lane + 32 * i;
                int q = idx >> 5, r = (idx >> 1) & 15, gg = idx & 1;
                const float* src = g_xg + ((size_t)(t + 1) * B_SZ + m0 + wm + r) * G4
                                 + q * HID + h0 + wh * 8 + gg * 4;
                asm volatile("cp.async.cg.shared.global [%0], [%1], 16;"
                    :: "r"(xgBase + (uint32_t)(q * 512 + r * 32 + gg * 16)), "l"(src));
            }
            asm volatile("cp.async.commit_group;" ::: "memory");

            __syncthreads();
            const unsigned long long tgt = barBase + (unsigned long long)(t + 1);
            if (tid == 0)
                asm volatile("st.release.gpu.global.u64 [%0], %1;"
                             :: "l"(&g_flags[blockIdx.x]), "l"(tgt) : "memory");
            if (tid < GRIDN) {
                unsigned long long v;
                do {
                    asm volatile("ld.acquire.gpu.global.u64 %0, [%1];"
                                 : "=l"(v) : "l"(&g_flags[tid]) : "memory");
                } while (v < tgt);
            }
            __syncthreads();
        }
    }
#undef STAGE_H
#undef MMA_CHUNK
}

// ============ GEMM v3: cp.async 3-stage, pre-converted tf32 operands ============
// C[M][N] = A[M][512](tf32 bits) @ W[N][512](tf32 bits)^T + bias1 (+bias2)
// Tile 128x64, 256 threads. K = 512 fixed (16 tiles of 32).
#define GP_ST   36
#define GP_ABUF 18432
#define GP_BBUF 9216
#define GP_BOFF 55296
#define GP_CST  68
#define GP_SM   82944

__global__ __launch_bounds__(256) void gemm_cp(
    const uint32_t* __restrict__ A,
    const uint32_t* __restrict__ W,
    const float* __restrict__ bias1, const float* __restrict__ bias2,
    float* __restrict__ C, int N)
{
    extern __shared__ __align__(16) uint32_t gsm[];
    float* Cs = (float*)gsm;
    const uint32_t smem = smem_u32(gsm);

    const int tid  = threadIdx.x;
    const int lane = tid & 31;
    const int warp = tid >> 5;
    const int wm   = (warp >> 1) * 32;
    const int wn   = (warp & 1) * 32;
    const int m0   = blockIdx.y * 128;
    const int n0   = blockIdx.x * 64;

    float c[2][4][4];
#pragma unroll
    for (int mt = 0; mt < 2; mt++)
#pragma unroll
        for (int nt = 0; nt < 4; nt++)
#pragma unroll
            for (int q = 0; q < 4; q++) c[mt][nt][q] = 0.f;

    const uint32_t aOff = (uint32_t)(((wm + (lane & 15)) * GP_ST + (lane >> 4) * 4) << 2);
    const uint32_t bRow = wn + (lane & 7) + ((lane & 16) ? 8 : 0);
    const uint32_t bOff = (uint32_t)((bRow * GP_ST + ((lane >> 3) & 1) * 4) << 2);

#define LOADST(kt)                                                               \
    {                                                                            \
        const uint32_t abase = smem + (uint32_t)(((kt) % 3) * GP_ABUF);          \
        const uint32_t bbase = smem + (uint32_t)(GP_BOFF + ((kt) % 3) * GP_BBUF);\
        _Pragma("unroll")                                                        \
        for (int i = 0; i < 4; i++) {                                            \
            int idx = tid + (i << 8);                                            \
            int row = idx >> 3, kq = idx & 7;                                    \
            const uint32_t* src = A + (size_t)(m0 + row) * 512 + (kt) * 32 + kq * 4; \
            asm volatile("cp.async.cg.shared.global [%0], [%1], 16;"             \
                :: "r"(abase + (uint32_t)((row * GP_ST + kq * 4) << 2)), "l"(src)); \
        }                                                                        \
        _Pragma("unroll")                                                        \
        for (int i = 0; i < 2; i++) {                                            \
            int idx = tid + (i << 8);                                            \
            int row = idx >> 3, kq = idx & 7;                                    \
            int wr = n0 + row; if (wr >= N) wr = N - 1;                          \
            const uint32_t* src = W + (size_t)wr * 512 + (kt) * 32 + kq * 4;     \
            asm volatile("cp.async.cg.shared.global [%0], [%1], 16;"             \
                :: "r"(bbase + (uint32_t)((row * GP_ST + kq * 4) << 2)), "l"(src)); \
        }                                                                        \
        asm volatile("cp.async.commit_group;" ::: "memory");                     \
    }

#define GMMA(kt)                                                                 \
    {                                                                            \
        const uint32_t abuf = smem + (uint32_t)(((kt) % 3) * GP_ABUF);           \
        const uint32_t bbuf = smem + (uint32_t)(GP_BOFF + ((kt) % 3) * GP_BBUF); \
        _Pragma("unroll")                                                        \
        for (int k8 = 0; k8 < 4; k8++) {                                         \
            uint32_t fa0[4], fa1[4], fb0[4], fb1[4];                             \
            ldsm_x4(fa0, abuf + aOff + (uint32_t)(k8 * 32));                     \
            ldsm_x4(fa1, abuf + aOff + (uint32_t)(16 * GP_ST * 4 + k8 * 32));    \
            ldsm_x4(fb0, bbuf + bOff + (uint32_t)(k8 * 32));                     \
            ldsm_x4(fb1, bbuf + bOff + (uint32_t)(16 * GP_ST * 4 + k8 * 32));    \
            mma_tf32(c[0][0], fa0, fb0);                                         \
            mma_tf32(c[0][1], fa0, fb0 + 2);                                     \
            mma_tf32(c[0][2], fa0, fb1);                                         \
            mma_tf32(c[0][3], fa0, fb1 + 2);                                     \
            mma_tf32(c[1][0], fa1, fb0);                                         \
            mma_tf32(c[1][1], fa1, fb0 + 2);                                     \
            mma_tf32(c[1][2], fa1, fb1);                                         \
            mma_tf32(c[1][3], fa1, fb1 + 2);                                     \
        }                                                                        \
    }

#define GITER(kt, WN)                                                            \
    asm volatile("cp.async.wait_group " #WN ";" ::: "memory");                   \
    __syncthreads();                                                             \
    if ((kt) + 2 < 16) LOADST((kt) + 2)                                          \
    GMMA(kt)

    LOADST(0) LOADST(1)
    GITER(0, 1)  GITER(1, 1)  GITER(2, 1)  GITER(3, 1)
    GITER(4, 1)  GITER(5, 1)  GITER(6, 1)  GITER(7, 1)
    GITER(8, 1)  GITER(9, 1)  GITER(10, 1) GITER(11, 1)
    GITER(12, 1) GITER(13, 1) GITER(14, 1) GITER(15, 0)
#undef GITER
#undef GMMA
#undef LOADST

    __syncthreads();
    {
        const int gid = lane >> 2, tig = lane & 3;
#pragma unroll
        for (int mt = 0; mt < 2; mt++)
#pragma unroll
            for (int nt = 0; nt < 4; nt++) {
                int r  = wm + mt * 16 + gid;
                int cb = wn + nt * 8 + 2 * tig;
                Cs[r * GP_CST + cb]           = c[mt][nt][0];
                Cs[r * GP_CST + cb + 1]       = c[mt][nt][1];
                Cs[(r + 8) * GP_CST + cb]     = c[mt][nt][2];
                Cs[(r + 8) * GP_CST + cb + 1] = c[mt][nt][3];
            }
    }
    __syncthreads();

#pragma unroll
    for (int i = 0; i < 8; i++) {
        int idx = tid + (i << 8);
        int row = idx >> 4, cq = idx & 15;
        int colb = n0 + cq * 4;
        if (colb < N) {   // N % 4 == 0 in all uses
            float4 v = *(float4*)&Cs[row * GP_CST + cq * 4];
            float4 b1 = *(const float4*)&bias1[colb];
            v.x += b1.x; v.y += b1.y; v.z += b1.z; v.w += b1.w;
            if (bias2) {
                float4 b2 = *(const float4*)&bias2[colb];
                v.x += b2.x; v.y += b2.y; v.z += b2.z; v.w += b2.w;
            }
            *(float4*)&C[(size_t)(m0 + row) * N + colb] = v;
        }
    }
}

// ---------------- Sigma = (L*fv) @ L^T + diag(idio) ----------------
__global__ __launch_bounds__(256) void sigma_kernel(float* __restrict__ out)
{
    __shared__ float fvs[32];
    __shared__ float Ln[32][64];
    __shared__ float Lm[32][64];

    const int b  = blockIdx.z;
    const int n0 = blockIdx.y * 64;
    const int m0 = blockIdx.x * 64;
    const int tid = threadIdx.x;
    const int tx = tid & 15;
    const int ty = tid >> 4;
    const float* rb = g_raw + (size_t)b * RAWN;

    if (tid < 32) fvs[tid] = expf(rb[NA * NF + tid]);
    __syncthreads();

#pragma unroll
    for (int i = 0; i < 8; i++) {
        int idx = tid + i * 256;
        int nl = idx >> 5, f = idx & 31;
        int n = n0 + nl;
        float v = (n < NA) ? rb[n * NF + f] : 0.f;
        Ln[f][nl] = v * fvs[f];
        int m = m0 + nl;
        float w = (m < NA) ? rb[m * NF + f] : 0.f;
        Lm[f][nl] = w;
    }
    __syncthreads();

    float acc[4][4];
#pragma unroll
    for (int r = 0; r < 4; r++)
#pragma unroll
        for (int cc = 0; cc < 4; cc++) acc[r][cc] = 0.f;

#pragma unroll
    for (int f = 0; f < 32; f++) {
        float4 a  = *reinterpret_cast<const float4*>(&Ln[f][ty * 4]);
        float4 bb = *reinterpret_cast<const float4*>(&Lm[f][tx * 4]);
        float av[4] = {a.x, a.y, a.z, a.w};
        float bv[4] = {bb.x, bb.y, bb.z, bb.w};
#pragma unroll
        for (int r = 0; r < 4; r++)
#pragma unroll
            for (int cc = 0; cc < 4; cc++)
                acc[r][cc] = fmaf(av[r], bv[cc], acc[r][cc]);
    }

    const int mBase = m0 + tx * 4;
    if (mBase < NA) {
#pragma unroll
        for (int r = 0; r < 4; r++) {
            int n = n0 + ty * 4 + r;
            if (n >= NA) continue;
            float o[4] = {acc[r][0], acc[r][1], acc[r][2], acc[r][3]};
            int d = n - mBase;
            if (d >= 0 && d < 4) o[d] += expf(rb[NA * NF + NF + n]);
            float4 ov = {o[0], o[1], o[2], o[3]};
            *reinterpret_cast<float4*>(&out[(size_t)b * NA * NA + (size_t)n * NA + mBase]) = ov;
        }
    }
}

// ---------------- launch ----------------
extern "C" void kernel_launch(void* const* d_in, const int* in_sizes, int n_in,
                              void* d_out, int out_size)
{
    const float* x     = (const float*)d_in[0];
    const float* w_ih0 = (const float*)d_in[1];
    const float* w_hh0 = (const float*)d_in[2];
    const float* b_ih0 = (const float*)d_in[3];
    const float* b_hh0 = (const float*)d_in[4];
    const float* w_ih1 = (const float*)d_in[5];
    const float* w_hh1 = (const float*)d_in[6];
    const float* b_ih1 = (const float*)d_in[7];
    const float* b_hh1 = (const float*)d_in[8];
    const float* fc_w  = (const float*)d_in[9];
    const float* fc_b  = (const float*)d_in[10];
    float* out = (float*)d_out;

    static bool attr_done = false;
    if (!attr_done) {
        cudaFuncSetAttribute(lstm_persist,
            cudaFuncAttributeMaxDynamicSharedMemorySize, SM_BYTES);
        cudaFuncSetAttribute(gemm_cp,
            cudaFuncAttributeMaxDynamicSharedMemorySize, GP_SM);
        attr_done = true;
    }

    // device pointers to scratch
    uint32_t *p_xc, *p_wc0, *p_wc1, *p_wfc;
    cudaGetSymbolAddress((void**)&p_xc,  g_xc);
    cudaGetSymbolAddress((void**)&p_wc0, g_wc0);
    cudaGetSymbolAddress((void**)&p_wc1, g_wc1);
    cudaGetSymbolAddress((void**)&p_wfc, g_wfc);
    float *p_xg, *p_hseq, *p_hA, *p_raw;
    cudaGetSymbolAddress((void**)&p_xg,   g_xg);
    cudaGetSymbolAddress((void**)&p_hseq, g_hseq);
    cudaGetSymbolAddress((void**)&p_hA,   g_hA);
    cudaGetSymbolAddress((void**)&p_raw,  g_raw);

    // ---- prep: convert operands to tf32 bits ----
    cvt_x_kernel<<<(T_SZ * B_SZ * HID) / 256, 256>>>(x, p_xc);
    cvt_pad_kernel<<<(G4 * HID) / 256, 256>>>(w_ih0, p_wc0, G4, IN_SZ);
    cvt_pad_kernel<<<(G4 * HID) / 256, 256>>>(w_ih1, p_wc1, G4, HID);
    cvt_pad_kernel<<<((RAWN * HID) + 255) / 256, 256>>>(fc_w, p_wfc, RAWN, HID);

    // ---- layer 0 ----
    gemm_cp<<<dim3(G4 / 64, (B_SZ * T_SZ) / 128), 256, GP_SM>>>(
        p_xc, p_wc0, b_ih0, b_hh0, p_xg, G4);
    lstm_persist<<<GRIDN, 256, SM_BYTES>>>(w_hh0, 0);

    // ---- layer 1 ----
    gemm_cp<<<dim3(G4 / 64, (B_SZ * T_SZ) / 128), 256, GP_SM>>>(
        (const uint32_t*)p_hseq, p_wc1, b_ih1, b_hh1, p_xg, G4);
    lstm_persist<<<GRIDN, 256, SM_BYTES>>>(w_hh1, 1);
    // final h (t=63, odd) in g_hA

    // ---- FC ----
    gemm_cp<<<dim3((RAWN + 63) / 64, B_SZ / 128), 256, GP_SM>>>(
        (const uint32_t*)p_hA, p_wfc, fc_b, nullptr, p_raw, RAWN);

    // ---- Sigma ----
    sigma_kernel<<<dim3(8, 8, B_SZ), 256>>>(out);
}

// round 11
// speedup vs baseline: 1.1003x; 1.0392x over previous
#include <cuda_runtime.h>
#include <math.h>
#include <stdint.h>

#define B_SZ   256
#define T_SZ   64
#define IN_SZ  500
#define HID    512
#define G4     2048
#define RAWN   16532
#define NA     500
#define NF     32
#define GRIDN  128

__device__ float g_xg[(size_t)T_SZ * B_SZ * G4];
__device__ float g_hseq[(size_t)T_SZ * B_SZ * HID];
__device__ float g_hA[B_SZ * HID];
__device__ float g_hB[B_SZ * HID];
__device__ float g_raw[(size_t)B_SZ * RAWN];
__device__ unsigned long long g_flags[GRIDN];
// pre-converted tf32-bit operands
__device__ uint32_t g_xc[(size_t)T_SZ * B_SZ * HID];
__device__ uint32_t g_wc0[(size_t)G4 * HID];
__device__ uint32_t g_wc1[(size_t)G4 * HID];
__device__ uint32_t g_wfc[(size_t)RAWN * HID];

__device__ __forceinline__ float sigmf(float x) { return 1.f / (1.f + expf(-x)); }

__device__ __forceinline__ uint32_t f2tf32(float f) {
    uint32_t r;
    asm("cvt.rna.tf32.f32 %0, %1;" : "=r"(r) : "f"(f));
    return r;
}

__device__ __forceinline__ void mma_tf32(float* c, const uint32_t* a, const uint32_t* b) {
    asm volatile(
        "mma.sync.aligned.m16n8k8.row.col.f32.tf32.tf32.f32 "
        "{%0,%1,%2,%3}, {%4,%5,%6,%7}, {%8,%9}, {%0,%1,%2,%3};\n"
        : "+f"(c[0]), "+f"(c[1]), "+f"(c[2]), "+f"(c[3])
        : "r"(a[0]), "r"(a[1]), "r"(a[2]), "r"(a[3]), "r"(b[0]), "r"(b[1]));
}

__device__ __forceinline__ void ldsm_x4(uint32_t* r, uint32_t addr) {
    asm volatile("ldmatrix.sync.aligned.m8n8.x4.shared.b16 {%0,%1,%2,%3}, [%4];"
        : "=r"(r[0]), "=r"(r[1]), "=r"(r[2]), "=r"(r[3]) : "r"(addr));
}

__device__ __forceinline__ uint32_t smem_u32(const void* p) {
    uint32_t a;
    asm("{ .reg .u64 t; cvta.to.shared.u64 t, %1; cvt.u32.u64 %0, t; }" : "=r"(a) : "l"(p));
    return a;
}

// ---------------- prep kernels ----------------
__global__ void cvt_pad_kernel(const float* __restrict__ in, uint32_t* __restrict__ out,
                               int Nrows, int Kin)
{
    size_t idx = (size_t)blockIdx.x * 256 + threadIdx.x;
    if (idx >= (size_t)Nrows * 512) return;
    int n = (int)(idx >> 9), k = (int)(idx & 511);
    out[idx] = (k < Kin) ? f2tf32(in[(size_t)n * Kin + k]) : 0u;
}

__global__ void cvt_x_kernel(const float* __restrict__ x, uint32_t* __restrict__ out)
{
    size_t idx = (size_t)blockIdx.x * 256 + threadIdx.x;
    int r = (int)(idx >> 9), k = (int)(idx & 511);
    int t = r >> 8, b = r & 255;
    out[idx] = (k < IN_SZ) ? f2tf32(x[((size_t)b * T_SZ + t) * IN_SZ + k]) : 0u;
}

// ================= persistent LSTM layer (R7/R9 measured-best) =================
#define W_STR   516
#define A_STR   68
#define OFF_AP  132096
#define PAIR_ST 17408
#define BUF_ST  4352
#define OFF_XG  201728
#define SM_BYTES 218112

__global__ __launch_bounds__(256, 1) void lstm_persist(
    const float* __restrict__ w_hh, int layer)
{
    extern __shared__ __align__(16) uint32_t smraw[];
    uint32_t* Wsm = smraw;
    float*    smf = (float*)smraw;
    const uint32_t smem = smem_u32(smraw);

    const int tid  = threadIdx.x;
    const int lane = tid & 31;
    const int warp = tid >> 5;
    const int pair = warp >> 1;
    const int wh   = warp & 1;
    const int wm   = pair * 16;
    const int wn   = wh * 32;
    const int h0   = (blockIdx.x & 31) * 16;
    const int m0   = (blockIdx.x >> 5) * 64;

#pragma unroll
    for (int i = 0; i < 32; i++) {
        int s   = tid + (i << 8);
        int row = s >> 7;
        int kq  = s & 127;
        int wr  = ((row & 3) << 9) + h0 + (row >> 2);
        float4 v = *(const float4*)&w_hh[(size_t)wr * HID + (kq << 2)];
        *(uint4*)&Wsm[row * W_STR + (kq << 2)] =
            make_uint4(f2tf32(v.x), f2tf32(v.y), f2tf32(v.z), f2tf32(v.w));
    }

    const uint32_t pairBase = smem + OFF_AP + (uint32_t)pair * PAIR_ST;
    const uint32_t aFrag = pairBase
        + (uint32_t)(((lane & 15) * A_STR + (lane >> 4) * 4) << 2);
    const uint32_t rB = wn + (lane & 7) + ((lane & 16) ? 8 : 0);
    const uint32_t bBase0 = smem + (uint32_t)((rB * W_STR + ((lane >> 3) & 1) * 4) << 2);
    const uint32_t bBase1 = bBase0 + 16 * W_STR * 4;

    const int sRowBase = wh * 8;
    const uint32_t xgBase = smem + OFF_XG + (uint32_t)warp * 2048;
    const int xgW = (int)(OFF_XG / 4) + warp * 512;
    const int csW = (int)(OFF_AP / 4) + pair * (PAIR_ST / 4) + wh * 576;

    const unsigned long long barBase =
        *(volatile unsigned long long*)&g_flags[blockIdx.x];

    float creg[4] = {0.f, 0.f, 0.f, 0.f};
    const int barId = 1 + pair;

    __syncthreads();

    {
#pragma unroll
        for (int i = 0; i < 4; i++) {
            int idx = lane + 32 * i;
            int q = idx >> 5, r = (idx >> 1) & 15, gg = idx & 1;
            const float* src = g_xg + ((size_t)0 * B_SZ + m0 + wm + r) * G4
                             + q * HID + h0 + wh * 8 + gg * 4;
            asm volatile("cp.async.cg.shared.global [%0], [%1], 16;"
                :: "r"(xgBase + (uint32_t)(q * 512 + r * 32 + gg * 16)), "l"(src));
        }
        asm volatile("cp.async.commit_group;" ::: "memory");
    }

#define STAGE_H(c)                                                              \
    {                                                                           \
        uint32_t dbuf = pairBase + (uint32_t)(((c) & 3) * BUF_ST);              \
        _Pragma("unroll")                                                       \
        for (int i = 0; i < 4; i++) {                                           \
            int idx = lane + 32 * i;                                            \
            int rl = sRowBase + (idx >> 4);                                     \
            int gr = idx & 15;                                                  \
            const float* src = h_in + (size_t)(m0 + wm + rl) * HID              \
                             + (c) * 64 + gr * 4;                               \
            asm volatile("cp.async.cg.shared.global [%0], [%1], 16;"            \
                :: "r"(dbuf + (uint32_t)(rl * 272 + gr * 16)), "l"(src));       \
        }                                                                       \
        asm volatile("cp.async.commit_group;" ::: "memory");                    \
    }

#define MMA_CHUNK(ck)                                                           \
    {                                                                           \
        const uint32_t ab  = aFrag  + (uint32_t)(((ck) & 3) * BUF_ST);          \
        const uint32_t wb0 = bBase0 + (uint32_t)((ck) * 256);                   \
        const uint32_t wb1 = bBase1 + (uint32_t)((ck) * 256);                   \
        _Pragma("unroll")                                                       \
        for (int k8 = 0; k8 < 8; k8++) {                                        \
            uint32_t a[4], b0[4], b1[4];                                        \
            ldsm_x4(a,  ab  + (uint32_t)(k8 * 32));                             \
            ldsm_x4(b0, wb0 + (uint32_t)(k8 * 32));                             \
            ldsm_x4(b1, wb1 + (uint32_t)(k8 * 32));                             \
            mma_tf32(c[0], a, b0);                                              \
            mma_tf32(c[1], a, b0 + 2);                                          \
            mma_tf32(c[2], a, b1);                                              \
            mma_tf32(c[3], a, b1 + 2);                                          \
        }                                                                       \
    }

    for (int t = 0; t < T_SZ; t++) {
        const float* h_in = (t & 1) ? g_hB : g_hA;
        float* h_out      = (t & 1) ? g_hA : g_hB;

        float c[4][4];
#pragma unroll
        for (int nt = 0; nt < 4; nt++)
#pragma unroll
            for (int q = 0; q < 4; q++) c[nt][q] = 0.f;

        if (t > 0) {
            STAGE_H(0) STAGE_H(1) STAGE_H(2)
#define ITER(ck, WN)                                                            \
            asm volatile("cp.async.wait_group " #WN ";" ::: "memory");          \
            asm volatile("bar.sync %0, 64;" :: "r"(barId) : "memory");          \
            if ((ck) <= 4) STAGE_H((ck) + 3)                                    \
            MMA_CHUNK(ck)
            ITER(0, 2) ITER(1, 2) ITER(2, 2) ITER(3, 2)
            ITER(4, 2) ITER(5, 2) ITER(6, 1) ITER(7, 0)
#undef ITER
            {
                const int gid = lane >> 2, tig = lane & 3;
#pragma unroll
                for (int nt = 0; nt < 4; nt++) {
                    int cb = nt * 8 + 2 * tig;
                    smf[csW + gid * 36 + cb]           = c[nt][0];
                    smf[csW + gid * 36 + cb + 1]       = c[nt][1];
                    smf[csW + (gid + 8) * 36 + cb]     = c[nt][2];
                    smf[csW + (gid + 8) * 36 + cb + 1] = c[nt][3];
                }
            }
        } else {
            asm volatile("cp.async.wait_group 0;" ::: "memory");
        }
        __syncwarp();

        {
            const int rl = lane >> 1;
            const int hq = lane & 1;
            float4 gv[4];
            if (t > 0) {
#pragma unroll
                for (int k = 0; k < 4; k++)
                    gv[k] = *(float4*)&smf[csW + rl * 36 + hq * 16 + 4 * k];
            } else {
#pragma unroll
                for (int k = 0; k < 4; k++) gv[k] = make_float4(0, 0, 0, 0);
            }
            float4 xq[4];
#pragma unroll
            for (int q = 0; q < 4; q++)
                xq[q] = *(float4*)&smf[xgW + q * 128 + rl * 8 + hq * 4];

            float xiv[4] = {xq[0].x, xq[0].y, xq[0].z, xq[0].w};
            float xfv[4] = {xq[1].x, xq[1].y, xq[1].z, xq[1].w};
            float xgv[4] = {xq[2].x, xq[2].y, xq[2].z, xq[2].w};
            float xov[4] = {xq[3].x, xq[3].y, xq[3].z, xq[3].w};

            uint32_t hb[4];
#pragma unroll
            for (int k = 0; k < 4; k++) {
                float gi = gv[k].x + xiv[k];
                float gf = gv[k].y + xfv[k];
                float gg = gv[k].z + xgv[k];
                float go = gv[k].w + xov[k];
                float cn = sigmf(gf) * creg[k] + sigmf(gi) * tanhf(gg);
                float hn = sigmf(go) * tanhf(cn);
                creg[k] = cn;
                hb[k] = f2tf32(hn);
            }
            const int b = m0 + wm + rl;
            const int hh = h0 + wh * 8 + hq * 4;
            *(uint4*)&h_out[(size_t)b * HID + hh] = make_uint4(hb[0], hb[1], hb[2], hb[3]);
            if (layer == 0)
                *(uint4*)&g_hseq[((size_t)t * B_SZ + b) * HID + hh] =
                    make_uint4(hb[0], hb[1], hb[2], hb[3]);
        }

        if (t + 1 < T_SZ) {
#pragma unroll
            for (int i = 0; i < 4; i++) {
                int idx = lane + 32 * i;
                int q = idx >> 5, r = (idx >> 1) & 15, gg = idx & 1;
                const float* src = g_xg + ((size_t)(t + 1) * B_SZ + m0 + wm + r) * G4
                                 + q * HID + h0 + wh * 8 + gg * 4;
                asm volatile("cp.async.cg.shared.global [%0], [%1], 16;"
                    :: "r"(xgBase + (uint32_t)(q * 512 + r * 32 + gg * 16)), "l"(src));
            }
            asm volatile("cp.async.commit_group;" ::: "memory");

            __syncthreads();
            const unsigned long long tgt = barBase + (unsigned long long)(t + 1);
            if (tid == 0)
                asm volatile("st.release.gpu.global.u64 [%0], %1;"
                             :: "l"(&g_flags[blockIdx.x]), "l"(tgt) : "memory");
            if (tid < GRIDN) {
                unsigned long long v;
                do {
                    asm volatile("ld.acquire.gpu.global.u64 %0, [%1];"
                                 : "=l"(v) : "l"(&g_flags[tid]) : "memory");
                } while (v < tgt);
            }
            __syncthreads();
        }
    }
#undef STAGE_H
#undef MMA_CHUNK
}

// ============ GEMM v4: 128x128 tile, warp 32x64, cp.async 3-stage ============
// C[M][N] = A[M][512](tf32 bits) @ W[N][512](tf32 bits)^T + bias1 (+bias2)
// 256 threads (8 warps = 4 M-groups x 2 N-groups). K = 512 (16 tiles of 32).
#define GP_ST   36
#define GP_BUF  18432                 // one 128x32 tile (u32, stride 36)
#define GP_BOFF 55296                 // B region after 3 A stages
#define GP_CST  132
#define GP_SM   110592

__global__ __launch_bounds__(256, 2) void gemm_cp(
    const uint32_t* __restrict__ A,
    const uint32_t* __restrict__ W,
    const float* __restrict__ bias1, const float* __restrict__ bias2,
    float* __restrict__ C, int N)
{
    extern __shared__ __align__(16) uint32_t gsm[];
    float* Cs = (float*)gsm;
    const uint32_t smem = smem_u32(gsm);

    const int tid  = threadIdx.x;
    const int lane = tid & 31;
    const int warp = tid >> 5;
    const int wm   = (warp >> 1) * 32;    // 4 groups along M(128)
    const int wn   = (warp & 1) * 64;     // 2 groups along N(128)
    const int m0   = blockIdx.y * 128;
    const int n0   = blockIdx.x * 128;

    float c[2][8][4];
#pragma unroll
    for (int mt = 0; mt < 2; mt++)
#pragma unroll
        for (int nt = 0; nt < 8; nt++)
#pragma unroll
            for (int q = 0; q < 4; q++) c[mt][nt][q] = 0.f;

    const uint32_t aOff = (uint32_t)(((wm + (lane & 15)) * GP_ST + (lane >> 4) * 4) << 2);
    const uint32_t bRow = wn + (lane & 7) + ((lane & 16) ? 8 : 0);
    const uint32_t bOff = (uint32_t)((bRow * GP_ST + ((lane >> 3) & 1) * 4) << 2);

#define LOADST(kt)                                                               \
    {                                                                            \
        const uint32_t abase = smem + (uint32_t)(((kt) % 3) * GP_BUF);           \
        const uint32_t bbase = smem + (uint32_t)(GP_BOFF + ((kt) % 3) * GP_BUF); \
        _Pragma("unroll")                                                        \
        for (int i = 0; i < 4; i++) {                                            \
            int idx = tid + (i << 8);                                            \
            int row = idx >> 3, kq = idx & 7;                                    \
            const uint32_t* srcA = A + (size_t)(m0 + row) * 512 + (kt) * 32 + kq * 4; \
            asm volatile("cp.async.cg.shared.global [%0], [%1], 16;"             \
                :: "r"(abase + (uint32_t)((row * GP_ST + kq * 4) << 2)), "l"(srcA)); \
            int wr = n0 + row; if (wr >= N) wr = N - 1;                          \
            const uint32_t* srcB = W + (size_t)wr * 512 + (kt) * 32 + kq * 4;    \
            asm volatile("cp.async.cg.shared.global [%0], [%1], 16;"             \
                :: "r"(bbase + (uint32_t)((row * GP_ST + kq * 4) << 2)), "l"(srcB)); \
        }                                                                        \
        asm volatile("cp.async.commit_group;" ::: "memory");                     \
    }

#define GMMA(kt)                                                                 \
    {                                                                            \
        const uint32_t abuf = smem + (uint32_t)(((kt) % 3) * GP_BUF);            \
        const uint32_t bbuf = smem + (uint32_t)(GP_BOFF + ((kt) % 3) * GP_BUF);  \
        _Pragma("unroll")                                                        \
        for (int k8 = 0; k8 < 4; k8++) {                                         \
            uint32_t fa[2][4], fb[4][4];                                         \
            _Pragma("unroll")                                                    \
            for (int mt = 0; mt < 2; mt++)                                       \
                ldsm_x4(fa[mt], abuf + aOff                                      \
                        + (uint32_t)(mt * 16 * GP_ST * 4 + k8 * 32));            \
            _Pragma("unroll")                                                    \
            for (int n4 = 0; n4 < 4; n4++)                                       \
                ldsm_x4(fb[n4], bbuf + bOff                                      \
                        + (uint32_t)(n4 * 16 * GP_ST * 4 + k8 * 32));            \
            _Pragma("unroll")                                                    \
            for (int mt = 0; mt < 2; mt++)                                       \
                _Pragma("unroll")                                                \
                for (int n4 = 0; n4 < 4; n4++) {                                 \
                    mma_tf32(c[mt][2 * n4],     fa[mt], fb[n4]);                 \
                    mma_tf32(c[mt][2 * n4 + 1], fa[mt], fb[n4] + 2);             \
                }                                                                \
        }                                                                        \
    }

#define GITER(kt, WN)                                                            \
    asm volatile("cp.async.wait_group " #WN ";" ::: "memory");                   \
    __syncthreads();                                                             \
    if ((kt) + 2 < 16) LOADST((kt) + 2)                                          \
    GMMA(kt)

    LOADST(0) LOADST(1)
    GITER(0, 1)  GITER(1, 1)  GITER(2, 1)  GITER(3, 1)
    GITER(4, 1)  GITER(5, 1)  GITER(6, 1)  GITER(7, 1)
    GITER(8, 1)  GITER(9, 1)  GITER(10, 1) GITER(11, 1)
    GITER(12, 1) GITER(13, 1) GITER(14, 1) GITER(15, 0)
#undef GITER
#undef GMMA
#undef LOADST

    __syncthreads();
    {
        const int gid = lane >> 2, tig = lane & 3;
#pragma unroll
        for (int mt = 0; mt < 2; mt++)
#pragma unroll
            for (int nt = 0; nt < 8; nt++) {
                int r  = wm + mt * 16 + gid;
                int cb = wn + nt * 8 + 2 * tig;
                Cs[r * GP_CST + cb]           = c[mt][nt][0];
                Cs[r * GP_CST + cb + 1]       = c[mt][nt][1];
                Cs[(r + 8) * GP_CST + cb]     = c[mt][nt][2];
                Cs[(r + 8) * GP_CST + cb + 1] = c[mt][nt][3];
            }
    }
    __syncthreads();

#pragma unroll
    for (int i = 0; i < 16; i++) {
        int idx = tid + (i << 8);
        int row = idx >> 5, cq = idx & 31;
        int colb = n0 + cq * 4;
        if (colb < N) {   // N % 4 == 0 in all uses
            float4 v = *(float4*)&Cs[row * GP_CST + cq * 4];
            float4 b1 = *(const float4*)&bias1[colb];
            v.x += b1.x; v.y += b1.y; v.z += b1.z; v.w += b1.w;
            if (bias2) {
                float4 b2 = *(const float4*)&bias2[colb];
                v.x += b2.x; v.y += b2.y; v.z += b2.z; v.w += b2.w;
            }
            *(float4*)&C[(size_t)(m0 + row) * N + colb] = v;
        }
    }
}

// ---------------- Sigma = (L*fv) @ L^T + diag(idio) ----------------
__global__ __launch_bounds__(256) void sigma_kernel(float* __restrict__ out)
{
    __shared__ float fvs[32];
    __shared__ float Ln[32][64];
    __shared__ float Lm[32][64];

    const int b  = blockIdx.z;
    const int n0 = blockIdx.y * 64;
    const int m0 = blockIdx.x * 64;
    const int tid = threadIdx.x;
    const int tx = tid & 15;
    const int ty = tid >> 4;
    const float* rb = g_raw + (size_t)b * RAWN;

    if (tid < 32) fvs[tid] = expf(rb[NA * NF + tid]);
    __syncthreads();

#pragma unroll
    for (int i = 0; i < 8; i++) {
        int idx = tid + i * 256;
        int nl = idx >> 5, f = idx & 31;
        int n = n0 + nl;
        float v = (n < NA) ? rb[n * NF + f] : 0.f;
        Ln[f][nl] = v * fvs[f];
        int m = m0 + nl;
        float w = (m < NA) ? rb[m * NF + f] : 0.f;
        Lm[f][nl] = w;
    }
    __syncthreads();

    float acc[4][4];
#pragma unroll
    for (int r = 0; r < 4; r++)
#pragma unroll
        for (int cc = 0; cc < 4; cc++) acc[r][cc] = 0.f;

#pragma unroll
    for (int f = 0; f < 32; f++) {
        float4 a  = *reinterpret_cast<const float4*>(&Ln[f][ty * 4]);
        float4 bb = *reinterpret_cast<const float4*>(&Lm[f][tx * 4]);
        float av[4] = {a.x, a.y, a.z, a.w};
        float bv[4] = {bb.x, bb.y, bb.z, bb.w};
#pragma unroll
        for (int r = 0; r < 4; r++)
#pragma unroll
            for (int cc = 0; cc < 4; cc++)
                acc[r][cc] = fmaf(av[r], bv[cc], acc[r][cc]);
    }

    const int mBase = m0 + tx * 4;
    if (mBase < NA) {
#pragma unroll
        for (int r = 0; r < 4; r++) {
            int n = n0 + ty * 4 + r;
            if (n >= NA) continue;
            float o[4] = {acc[r][0], acc[r][1], acc[r][2], acc[r][3]};
            int d = n - mBase;
            if (d >= 0 && d < 4) o[d] += expf(rb[NA * NF + NF + n]);
            float4 ov = {o[0], o[1], o[2], o[3]};
            *reinterpret_cast<float4*>(&out[(size_t)b * NA * NA + (size_t)n * NA + mBase]) = ov;
        }
    }
}

// ---------------- launch ----------------
extern "C" void kernel_launch(void* const* d_in, const int* in_sizes, int n_in,
                              void* d_out, int out_size)
{
    const float* x     = (const float*)d_in[0];
    const float* w_ih0 = (const float*)d_in[1];
    const float* w_hh0 = (const float*)d_in[2];
    const float* b_ih0 = (const float*)d_in[3];
    const float* b_hh0 = (const float*)d_in[4];
    const float* w_ih1 = (const float*)d_in[5];
    const float* w_hh1 = (const float*)d_in[6];
    const float* b_ih1 = (const float*)d_in[7];
    const float* b_hh1 = (const float*)d_in[8];
    const float* fc_w  = (const float*)d_in[9];
    const float* fc_b  = (const float*)d_in[10];
    float* out = (float*)d_out;

    static bool attr_done = false;
    if (!attr_done) {
        cudaFuncSetAttribute(lstm_persist,
            cudaFuncAttributeMaxDynamicSharedMemorySize, SM_BYTES);
        cudaFuncSetAttribute(gemm_cp,
            cudaFuncAttributeMaxDynamicSharedMemorySize, GP_SM);
        attr_done = true;
    }

    uint32_t *p_xc, *p_wc0, *p_wc1, *p_wfc;
    cudaGetSymbolAddress((void**)&p_xc,  g_xc);
    cudaGetSymbolAddress((void**)&p_wc0, g_wc0);
    cudaGetSymbolAddress((void**)&p_wc1, g_wc1);
    cudaGetSymbolAddress((void**)&p_wfc, g_wfc);
    float *p_xg, *p_hseq, *p_hA, *p_raw;
    cudaGetSymbolAddress((void**)&p_xg,   g_xg);
    cudaGetSymbolAddress((void**)&p_hseq, g_hseq);
    cudaGetSymbolAddress((void**)&p_hA,   g_hA);
    cudaGetSymbolAddress((void**)&p_raw,  g_raw);

    // ---- prep ----
    cvt_x_kernel<<<(T_SZ * B_SZ * HID) / 256, 256>>>(x, p_xc);
    cvt_pad_kernel<<<(G4 * HID) / 256, 256>>>(w_ih0, p_wc0, G4, IN_SZ);
    cvt_pad_kernel<<<(G4 * HID) / 256, 256>>>(w_ih1, p_wc1, G4, HID);
    cvt_pad_kernel<<<((RAWN * HID) + 255) / 256, 256>>>(fc_w, p_wfc, RAWN, HID);

    // ---- layer 0 ----
    gemm_cp<<<dim3(G4 / 128, (B_SZ * T_SZ) / 128), 256, GP_SM>>>(
        p_xc, p_wc0, b_ih0, b_hh0, p_xg, G4);
    lstm_persist<<<GRIDN, 256, SM_BYTES>>>(w_hh0, 0);

    // ---- layer 1 ----
    gemm_cp<<<dim3(G4 / 128, (B_SZ * T_SZ) / 128), 256, GP_SM>>>(
        (const uint32_t*)p_hseq, p_wc1, b_ih1, b_hh1, p_xg, G4);
    lstm_persist<<<GRIDN, 256, SM_BYTES>>>(w_hh1, 1);
    // final h (t=63, odd) in g_hA

    // ---- FC ----
    gemm_cp<<<dim3((RAWN + 127) / 128, B_SZ / 128), 256, GP_SM>>>(
        (const uint32_t*)p_hA, p_wfc, fc_b, nullptr, p_raw, RAWN);

    // ---- Sigma ----
    sigma_kernel<<<dim3(8, 8, B_SZ), 256>>>(out);
}

// round 13
// speedup vs baseline: 1.1339x; 1.0306x over previous
#include <cuda_runtime.h>
#include <math.h>
#include <stdint.h>

#define B_SZ   256
#define T_SZ   64
#define IN_SZ  500
#define HID    512
#define G4     2048
#define RAWN   16532
#define NA     500
#define NF     32
#define GRIDN  128

__device__ float g_xg[(size_t)T_SZ * B_SZ * G4];
__device__ float g_hseq[(size_t)T_SZ * B_SZ * HID];
__device__ float g_hA[B_SZ * HID];
__device__ float g_hB[B_SZ * HID];
__device__ float g_raw[(size_t)B_SZ * RAWN];
__device__ unsigned long long g_flags[GRIDN];
// pre-converted tf32-bit operands
__device__ uint32_t g_xc[(size_t)T_SZ * B_SZ * HID];
__device__ uint32_t g_wc0[(size_t)G4 * HID];
__device__ uint32_t g_wc1[(size_t)G4 * HID];
__device__ uint32_t g_wfc[(size_t)RAWN * HID];

__device__ __forceinline__ float sigmf(float x) { return 1.f / (1.f + expf(-x)); }

__device__ __forceinline__ uint32_t f2tf32(float f) {
    uint32_t r;
    asm("cvt.rna.tf32.f32 %0, %1;" : "=r"(r) : "f"(f));
    return r;
}

__device__ __forceinline__ void mma_tf32(float* c, const uint32_t* a, const uint32_t* b) {
    asm volatile(
        "mma.sync.aligned.m16n8k8.row.col.f32.tf32.tf32.f32 "
        "{%0,%1,%2,%3}, {%4,%5,%6,%7}, {%8,%9}, {%0,%1,%2,%3};\n"
        : "+f"(c[0]), "+f"(c[1]), "+f"(c[2]), "+f"(c[3])
        : "r"(a[0]), "r"(a[1]), "r"(a[2]), "r"(a[3]), "r"(b[0]), "r"(b[1]));
}

__device__ __forceinline__ void ldsm_x4(uint32_t* r, uint32_t addr) {
    asm volatile("ldmatrix.sync.aligned.m8n8.x4.shared.b16 {%0,%1,%2,%3}, [%4];"
        : "=r"(r[0]), "=r"(r[1]), "=r"(r[2]), "=r"(r[3]) : "r"(addr));
}

__device__ __forceinline__ uint32_t smem_u32(const void* p) {
    uint32_t a;
    asm("{ .reg .u64 t; cvta.to.shared.u64 t, %1; cvt.u32.u64 %0, t; }" : "=r"(a) : "l"(p));
    return a;
}

// ---------------- prep kernels ----------------
__global__ void cvt_pad_kernel(const float* __restrict__ in, uint32_t* __restrict__ out,
                               int Nrows, int Kin)
{
    size_t idx = (size_t)blockIdx.x * 256 + threadIdx.x;
    if (idx >= (size_t)Nrows * 512) return;
    int n = (int)(idx >> 9), k = (int)(idx & 511);
    out[idx] = (k < Kin) ? f2tf32(in[(size_t)n * Kin + k]) : 0u;
}

__global__ void cvt_x_kernel(const float* __restrict__ x, uint32_t* __restrict__ out)
{
    size_t idx = (size_t)blockIdx.x * 256 + threadIdx.x;
    int r = (int)(idx >> 9), k = (int)(idx & 511);
    int t = r >> 8, b = r & 255;
    out[idx] = (k < IN_SZ) ? f2tf32(x[((size_t)b * T_SZ + t) * IN_SZ + k]) : 0u;
}

// ================= persistent LSTM layer (R7/R9 measured-best, unchanged) =================
#define W_STR   516
#define A_STR   68
#define OFF_AP  132096
#define PAIR_ST 17408
#define BUF_ST  4352
#define OFF_XG  201728
#define SM_BYTES 218112

__global__ __launch_bounds__(256, 1) void lstm_persist(
    const float* __restrict__ w_hh, int layer)
{
    extern __shared__ __align__(16) uint32_t smraw[];
    uint32_t* Wsm = smraw;
    float*    smf = (float*)smraw;
    const uint32_t smem = smem_u32(smraw);

    const int tid  = threadIdx.x;
    const int lane = tid & 31;
    const int warp = tid >> 5;
    const int pair = warp >> 1;
    const int wh   = warp & 1;
    const int wm   = pair * 16;
    const int wn   = wh * 32;
    const int h0   = (blockIdx.x & 31) * 16;
    const int m0   = (blockIdx.x >> 5) * 64;

#pragma unroll
    for (int i = 0; i < 32; i++) {
        int s   = tid + (i << 8);
        int row = s >> 7;
        int kq  = s & 127;
        int wr  = ((row & 3) << 9) + h0 + (row >> 2);
        float4 v = *(const float4*)&w_hh[(size_t)wr * HID + (kq << 2)];
        *(uint4*)&Wsm[row * W_STR + (kq << 2)] =
            make_uint4(f2tf32(v.x), f2tf32(v.y), f2tf32(v.z), f2tf32(v.w));
    }

    const uint32_t pairBase = smem + OFF_AP + (uint32_t)pair * PAIR_ST;
    const uint32_t aFrag = pairBase
        + (uint32_t)(((lane & 15) * A_STR + (lane >> 4) * 4) << 2);
    const uint32_t rB = wn + (lane & 7) + ((lane & 16) ? 8 : 0);
    const uint32_t bBase0 = smem + (uint32_t)((rB * W_STR + ((lane >> 3) & 1) * 4) << 2);
    const uint32_t bBase1 = bBase0 + 16 * W_STR * 4;

    const int sRowBase = wh * 8;
    const uint32_t xgBase = smem + OFF_XG + (uint32_t)warp * 2048;
    const int xgW = (int)(OFF_XG / 4) + warp * 512;
    const int csW = (int)(OFF_AP / 4) + pair * (PAIR_ST / 4) + wh * 576;

    const unsigned long long barBase =
        *(volatile unsigned long long*)&g_flags[blockIdx.x];

    float creg[4] = {0.f, 0.f, 0.f, 0.f};
    const int barId = 1 + pair;

    __syncthreads();

    {
#pragma unroll
        for (int i = 0; i < 4; i++) {
            int idx = lane + 32 * i;
            int q = idx >> 5, r = (idx >> 1) & 15, gg = idx & 1;
            const float* src = g_xg + ((size_t)0 * B_SZ + m0 + wm + r) * G4
                             + q * HID + h0 + wh * 8 + gg * 4;
            asm volatile("cp.async.cg.shared.global [%0], [%1], 16;"
                :: "r"(xgBase + (uint32_t)(q * 512 + r * 32 + gg * 16)), "l"(src));
        }
        asm volatile("cp.async.commit_group;" ::: "memory");
    }

#define STAGE_H(c)                                                              \
    {                                                                           \
        uint32_t dbuf = pairBase + (uint32_t)(((c) & 3) * BUF_ST);              \
        _Pragma("unroll")                                                       \
        for (int i = 0; i < 4; i++) {                                           \
            int idx = lane + 32 * i;                                            \
            int rl = sRowBase + (idx >> 4);                                     \
            int gr = idx & 15;                                                  \
            const float* src = h_in + (size_t)(m0 + wm + rl) * HID              \
                             + (c) * 64 + gr * 4;                               \
            asm volatile("cp.async.cg.shared.global [%0], [%1], 16;"            \
                :: "r"(dbuf + (uint32_t)(rl * 272 + gr * 16)), "l"(src));       \
        }                                                                       \
        asm volatile("cp.async.commit_group;" ::: "memory");                    \
    }

#define MMA_CHUNK(ck)                                                           \
    {                                                                           \
        const uint32_t ab  = aFrag  + (uint32_t)(((ck) & 3) * BUF_ST);          \
        const uint32_t wb0 = bBase0 + (uint32_t)((ck) * 256);                   \
        const uint32_t wb1 = bBase1 + (uint32_t)((ck) * 256);                   \
        _Pragma("unroll")                                                       \
        for (int k8 = 0; k8 < 8; k8++) {                                        \
            uint32_t a[4], b0[4], b1[4];                                        \
            ldsm_x4(a,  ab  + (uint32_t)(k8 * 32));                             \
            ldsm_x4(b0, wb0 + (uint32_t)(k8 * 32));                             \
            ldsm_x4(b1, wb1 + (uint32_t)(k8 * 32));                             \
            mma_tf32(c[0], a, b0);                                              \
            mma_tf32(c[1], a, b0 + 2);                                          \
            mma_tf32(c[2], a, b1);                                              \
            mma_tf32(c[3], a, b1 + 2);                                          \
        }                                                                       \
    }

    for (int t = 0; t < T_SZ; t++) {
        const float* h_in = (t & 1) ? g_hB : g_hA;
        float* h_out      = (t & 1) ? g_hA : g_hB;

        float c[4][4];
#pragma unroll
        for (int nt = 0; nt < 4; nt++)
#pragma unroll
            for (int q = 0; q < 4; q++) c[nt][q] = 0.f;

        if (t > 0) {
            STAGE_H(0) STAGE_H(1) STAGE_H(2)
#define ITER(ck, WN)                                                            \
            asm volatile("cp.async.wait_group " #WN ";" ::: "memory");          \
            asm volatile("bar.sync %0, 64;" :: "r"(barId) : "memory");          \
            if ((ck) <= 4) STAGE_H((ck) + 3)                                    \
            MMA_CHUNK(ck)
            ITER(0, 2) ITER(1, 2) ITER(2, 2) ITER(3, 2)
            ITER(4, 2) ITER(5, 2) ITER(6, 1) ITER(7, 0)
#undef ITER
            {
                const int gid = lane >> 2, tig = lane & 3;
#pragma unroll
                for (int nt = 0; nt < 4; nt++) {
                    int cb = nt * 8 + 2 * tig;
                    smf[csW + gid * 36 + cb]           = c[nt][0];
                    smf[csW + gid * 36 + cb + 1]       = c[nt][1];
                    smf[csW + (gid + 8) * 36 + cb]     = c[nt][2];
                    smf[csW + (gid + 8) * 36 + cb + 1] = c[nt][3];
                }
            }
        } else {
            asm volatile("cp.async.wait_group 0;" ::: "memory");
        }
        __syncwarp();

        {
            const int rl = lane >> 1;
            const int hq = lane & 1;
            float4 gv[4];
            if (t > 0) {
#pragma unroll
                for (int k = 0; k < 4; k++)
                    gv[k] = *(float4*)&smf[csW + rl * 36 + hq * 16 + 4 * k];
            } else {
#pragma unroll
                for (int k = 0; k < 4; k++) gv[k] = make_float4(0, 0, 0, 0);
            }
            float4 xq[4];
#pragma unroll
            for (int q = 0; q < 4; q++)
                xq[q] = *(float4*)&smf[xgW + q * 128 + rl * 8 + hq * 4];

            float xiv[4] = {xq[0].x, xq[0].y, xq[0].z, xq[0].w};
            float xfv[4] = {xq[1].x, xq[1].y, xq[1].z, xq[1].w};
            float xgv[4] = {xq[2].x, xq[2].y, xq[2].z, xq[2].w};
            float xov[4] = {xq[3].x, xq[3].y, xq[3].z, xq[3].w};

            uint32_t hb[4];
#pragma unroll
            for (int k = 0; k < 4; k++) {
                float gi = gv[k].x + xiv[k];
                float gf = gv[k].y + xfv[k];
                float gg = gv[k].z + xgv[k];
                float go = gv[k].w + xov[k];
                float cn = sigmf(gf) * creg[k] + sigmf(gi) * tanhf(gg);
                float hn = sigmf(go) * tanhf(cn);
                creg[k] = cn;
                hb[k] = f2tf32(hn);
            }
            const int b = m0 + wm + rl;
            const int hh = h0 + wh * 8 + hq * 4;
            *(uint4*)&h_out[(size_t)b * HID + hh] = make_uint4(hb[0], hb[1], hb[2], hb[3]);
            if (layer == 0)
                *(uint4*)&g_hseq[((size_t)t * B_SZ + b) * HID + hh] =
                    make_uint4(hb[0], hb[1], hb[2], hb[3]);
        }

        if (t + 1 < T_SZ) {
#pragma unroll
            for (int i = 0; i < 4; i++) {
                int idx = lane + 32 * i;
                int q = idx >> 5, r = (idx >> 1) & 15, gg = idx & 1;
                const float* src = g_xg + ((size_t)(t + 1) * B_SZ + m0 + wm + r) * G4
                                 + q * HID + h0 + wh * 8 + gg * 4;
                asm volatile("cp.async.cg.shared.global [%0], [%1], 16;"
                    :: "r"(xgBase + (uint32_t)(q * 512 + r * 32 + gg * 16)), "l"(src));
            }
            asm volatile("cp.async.commit_group;" ::: "memory");

            __syncthreads();
            const unsigned long long tgt = barBase + (unsigned long long)(t + 1);
            if (tid == 0)
                asm volatile("st.release.gpu.global.u64 [%0], %1;"
                             :: "l"(&g_flags[blockIdx.x]), "l"(tgt) : "memory");
            if (tid < GRIDN) {
                unsigned long long v;
                do {
                    asm volatile("ld.acquire.gpu.global.u64 %0, [%1];"
                                 : "=l"(v) : "l"(&g_flags[tid]) : "memory");
                } while (v < tgt);
            }
            __syncthreads();
        }
    }
#undef STAGE_H
#undef MMA_CHUNK
}

// ============ GEMM v4 (R11 winner, unchanged): 128x128, cp.async 3-stage ============
#define GP_ST   36
#define GP_BUF  18432
#define GP_BOFF 55296
#define GP_CST  132
#define GP_SM   110592

__global__ __launch_bounds__(256, 2) void gemm_cp(
    const uint32_t* __restrict__ A,
    const uint32_t* __restrict__ W,
    const float* __restrict__ bias1, const float* __restrict__ bias2,
    float* __restrict__ C, int N)
{
    extern __shared__ __align__(16) uint32_t gsm[];
    float* Cs = (float*)gsm;
    const uint32_t smem = smem_u32(gsm);

    const int tid  = threadIdx.x;
    const int lane = tid & 31;
    const int warp = tid >> 5;
    const int wm   = (warp >> 1) * 32;
    const int wn   = (warp & 1) * 64;
    const int m0   = blockIdx.y * 128;
    const int n0   = blockIdx.x * 128;

    float c[2][8][4];
#pragma unroll
    for (int mt = 0; mt < 2; mt++)
#pragma unroll
        for (int nt = 0; nt < 8; nt++)
#pragma unroll
            for (int q = 0; q < 4; q++) c[mt][nt][q] = 0.f;

    const uint32_t aOff = (uint32_t)(((wm + (lane & 15)) * GP_ST + (lane >> 4) * 4) << 2);
    const uint32_t bRow = wn + (lane & 7) + ((lane & 16) ? 8 : 0);
    const uint32_t bOff = (uint32_t)((bRow * GP_ST + ((lane >> 3) & 1) * 4) << 2);

#define LOADST(kt)                                                               \
    {                                                                            \
        const uint32_t abase = smem + (uint32_t)(((kt) % 3) * GP_BUF);           \
        const uint32_t bbase = smem + (uint32_t)(GP_BOFF + ((kt) % 3) * GP_BUF); \
        _Pragma("unroll")                                                        \
        for (int i = 0; i < 4; i++) {                                            \
            int idx = tid + (i << 8);                                            \
            int row = idx >> 3, kq = idx & 7;                                    \
            const uint32_t* srcA = A + (size_t)(m0 + row) * 512 + (kt) * 32 + kq * 4; \
            asm volatile("cp.async.cg.shared.global [%0], [%1], 16;"             \
                :: "r"(abase + (uint32_t)((row * GP_ST + kq * 4) << 2)), "l"(srcA)); \
            int wr = n0 + row; if (wr >= N) wr = N - 1;                          \
            const uint32_t* srcB = W + (size_t)wr * 512 + (kt) * 32 + kq * 4;    \
            asm volatile("cp.async.cg.shared.global [%0], [%1], 16;"             \
                :: "r"(bbase + (uint32_t)((row * GP_ST + kq * 4) << 2)), "l"(srcB)); \
        }                                                                        \
        asm volatile("cp.async.commit_group;" ::: "memory");                     \
    }

#define GMMA(kt)                                                                 \
    {                                                                            \
        const uint32_t abuf = smem + (uint32_t)(((kt) % 3) * GP_BUF);            \
        const uint32_t bbuf = smem + (uint32_t)(GP_BOFF + ((kt) % 3) * GP_BUF);  \
        _Pragma("unroll")                                                        \
        for (int k8 = 0; k8 < 4; k8++) {                                         \
            uint32_t fa[2][4], fb[4][4];                                         \
            _Pragma("unroll")                                                    \
            for (int mt = 0; mt < 2; mt++)                                       \
                ldsm_x4(fa[mt], abuf + aOff                                      \
                        + (uint32_t)(mt * 16 * GP_ST * 4 + k8 * 32));            \
            _Pragma("unroll")                                                    \
            for (int n4 = 0; n4 < 4; n4++)                                       \
                ldsm_x4(fb[n4], bbuf + bOff                                      \
                        + (uint32_t)(n4 * 16 * GP_ST * 4 + k8 * 32));            \
            _Pragma("unroll")                                                    \
            for (int mt = 0; mt < 2; mt++)                                       \
                _Pragma("unroll")                                                \
                for (int n4 = 0; n4 < 4; n4++) {                                 \
                    mma_tf32(c[mt][2 * n4],     fa[mt], fb[n4]);                 \
                    mma_tf32(c[mt][2 * n4 + 1], fa[mt], fb[n4] + 2);             \
                }                                                                \
        }                                                                        \
    }

#define GITER(kt, WN)                                                            \
    asm volatile("cp.async.wait_group " #WN ";" ::: "memory");                   \
    __syncthreads();                                                             \
    if ((kt) + 2 < 16) LOADST((kt) + 2)                                          \
    GMMA(kt)

    LOADST(0) LOADST(1)
    GITER(0, 1)  GITER(1, 1)  GITER(2, 1)  GITER(3, 1)
    GITER(4, 1)  GITER(5, 1)  GITER(6, 1)  GITER(7, 1)
    GITER(8, 1)  GITER(9, 1)  GITER(10, 1) GITER(11, 1)
    GITER(12, 1) GITER(13, 1) GITER(14, 1) GITER(15, 0)
#undef GITER
#undef GMMA
#undef LOADST

    __syncthreads();
    {
        const int gid = lane >> 2, tig = lane & 3;
#pragma unroll
        for (int mt = 0; mt < 2; mt++)
#pragma unroll
            for (int nt = 0; nt < 8; nt++) {
                int r  = wm + mt * 16 + gid;
                int cb = wn + nt * 8 + 2 * tig;
                Cs[r * GP_CST + cb]           = c[mt][nt][0];
                Cs[r * GP_CST + cb + 1]       = c[mt][nt][1];
                Cs[(r + 8) * GP_CST + cb]     = c[mt][nt][2];
                Cs[(r + 8) * GP_CST + cb + 1] = c[mt][nt][3];
            }
    }
    __syncthreads();

#pragma unroll
    for (int i = 0; i < 16; i++) {
        int idx = tid + (i << 8);
        int row = idx >> 5, cq = idx & 31;
        int colb = n0 + cq * 4;
        if (colb < N) {
            float4 v = *(float4*)&Cs[row * GP_CST + cq * 4];
            float4 b1 = *(const float4*)&bias1[colb];
            v.x += b1.x; v.y += b1.y; v.z += b1.z; v.w += b1.w;
            if (bias2) {
                float4 b2 = *(const float4*)&bias2[colb];
                v.x += b2.x; v.y += b2.y; v.z += b2.z; v.w += b2.w;
            }
            *(float4*)&C[(size_t)(m0 + row) * N + colb] = v;
        }
    }
}

// ---------------- Sigma (symmetric): 36 upper-triangle tiles + mirror ----------------
__global__ __launch_bounds__(256) void sigma_sym(float* __restrict__ out)
{
    __shared__ float fvs[32];
    __shared__ float Ln[32][64];
    __shared__ float Lm[32][64];
    __shared__ float Ts[64][65];

    const int b = blockIdx.y;
    int L = blockIdx.x, bi = 0;
    while (L >= 8 - bi) { L -= 8 - bi; bi++; }
    const int bj = bi + L;        // bi <= bj
    const int m0 = bi * 64;       // col block
    const int n0 = bj * 64;       // row block

    const int tid = threadIdx.x;
    const int tx = tid & 15;
    const int ty = tid >> 4;
    const float* rb = g_raw + (size_t)b * RAWN;

    if (tid < 32) fvs[tid] = expf(rb[NA * NF + tid]);
    __syncthreads();

#pragma unroll
    for (int i = 0; i < 8; i++) {
        int idx = tid + i * 256;
        int nl = idx >> 5, f = idx & 31;
        int n = n0 + nl;
        float v = (n < NA) ? rb[n * NF + f] : 0.f;
        Ln[f][nl] = v * fvs[f];
        int m = m0 + nl;
        float w = (m < NA) ? rb[m * NF + f] : 0.f;
        Lm[f][nl] = w;
    }
    __syncthreads();

    float acc[4][4];
#pragma unroll
    for (int r = 0; r < 4; r++)
#pragma unroll
        for (int cc = 0; cc < 4; cc++) acc[r][cc] = 0.f;

#pragma unroll
    for (int f = 0; f < 32; f++) {
        float4 a  = *reinterpret_cast<const float4*>(&Ln[f][ty * 4]);
        float4 bb = *reinterpret_cast<const float4*>(&Lm[f][tx * 4]);
        float av[4] = {a.x, a.y, a.z, a.w};
        float bv[4] = {bb.x, bb.y, bb.z, bb.w};
#pragma unroll
        for (int r = 0; r < 4; r++)
#pragma unroll
            for (int cc = 0; cc < 4; cc++)
                acc[r][cc] = fmaf(av[r], bv[cc], acc[r][cc]);
    }

    const int mBase = m0 + tx * 4;
#pragma unroll
    for (int r = 0; r < 4; r++) {
        int nl = ty * 4 + r;
        int n = n0 + nl;
        float o[4] = {acc[r][0], acc[r][1], acc[r][2], acc[r][3]};
        Ts[nl][tx * 4]     = o[0];
        Ts[nl][tx * 4 + 1] = o[1];
        Ts[nl][tx * 4 + 2] = o[2];
        Ts[nl][tx * 4 + 3] = o[3];
        if (n < NA && mBase < NA) {   // NA % 4 == 0 -> float4-exact guard
            int d = n - mBase;
            if (d >= 0 && d < 4) o[d] += expf(rb[NA * NF + NF + n]);
            float4 ov = {o[0], o[1], o[2], o[3]};
            *reinterpret_cast<float4*>(&out[(size_t)b * NA * NA + (size_t)n * NA + mBase]) = ov;
        }
    }

    // mirror for off-diagonal tiles: out[b][m][ncol] = Ts[ncol_local][m_local]
    if (bi != bj) {
        __syncthreads();
        for (int idx = tid; idx < 64 * 64; idx += 256) {
            int mr = idx >> 6;            // local row on m0 side
            int nc = idx & 63;            // local col on n0 side
            int m = m0 + mr;
            int ncol = n0 + nc;
            if (m < NA && ncol < NA)
                out[(size_t)b * NA * NA + (size_t)m * NA + ncol] = Ts[nc][mr];
        }
    }
}

// ---------------- launch ----------------
extern "C" void kernel_launch(void* const* d_in, const int* in_sizes, int n_in,
                              void* d_out, int out_size)
{
    const float* x     = (const float*)d_in[0];
    const float* w_ih0 = (const float*)d_in[1];
    const float* w_hh0 = (const float*)d_in[2];
    const float* b_ih0 = (const float*)d_in[3];
    const float* b_hh0 = (const float*)d_in[4];
    const float* w_ih1 = (const float*)d_in[5];
    const float* w_hh1 = (const float*)d_in[6];
    const float* b_ih1 = (const float*)d_in[7];
    const float* b_hh1 = (const float*)d_in[8];
    const float* fc_w  = (const float*)d_in[9];
    const float* fc_b  = (const float*)d_in[10];
    float* out = (float*)d_out;

    static bool attr_done = false;
    if (!attr_done) {
        cudaFuncSetAttribute(lstm_persist,
            cudaFuncAttributeMaxDynamicSharedMemorySize, SM_BYTES);
        cudaFuncSetAttribute(gemm_cp,
            cudaFuncAttributeMaxDynamicSharedMemorySize, GP_SM);
        attr_done = true;
    }

    uint32_t *p_xc, *p_wc0, *p_wc1, *p_wfc;
    cudaGetSymbolAddress((void**)&p_xc,  g_xc);
    cudaGetSymbolAddress((void**)&p_wc0, g_wc0);
    cudaGetSymbolAddress((void**)&p_wc1, g_wc1);
    cudaGetSymbolAddress((void**)&p_wfc, g_wfc);
    float *p_xg, *p_hseq, *p_hA, *p_raw;
    cudaGetSymbolAddress((void**)&p_xg,   g_xg);
    cudaGetSymbolAddress((void**)&p_hseq, g_hseq);
    cudaGetSymbolAddress((void**)&p_hA,   g_hA);
    cudaGetSymbolAddress((void**)&p_raw,  g_raw);

    // ---- prep ----
    cvt_x_kernel<<<(T_SZ * B_SZ * HID) / 256, 256>>>(x, p_xc);
    cvt_pad_kernel<<<(G4 * HID) / 256, 256>>>(w_ih0, p_wc0, G4, IN_SZ);
    cvt_pad_kernel<<<(G4 * HID) / 256, 256>>>(w_ih1, p_wc1, G4, HID);
    cvt_pad_kernel<<<((RAWN * HID) + 255) / 256, 256>>>(fc_w, p_wfc, RAWN, HID);

    // ---- layer 0 ----
    gemm_cp<<<dim3(G4 / 128, (B_SZ * T_SZ) / 128), 256, GP_SM>>>(
        p_xc, p_wc0, b_ih0, b_hh0, p_xg, G4);
    lstm_persist<<<GRIDN, 256, SM_BYTES>>>(w_hh0, 0);

    // ---- layer 1 ----
    gemm_cp<<<dim3(G4 / 128, (B_SZ * T_SZ) / 128), 256, GP_SM>>>(
        (const uint32_t*)p_hseq, p_wc1, b_ih1, b_hh1, p_xg, G4);
    lstm_persist<<<GRIDN, 256, SM_BYTES>>>(w_hh1, 1);
    // final h (t=63, odd) in g_hA

    // ---- FC (R11 pre-convert path) ----
    gemm_cp<<<dim3((RAWN + 127) / 128, B_SZ / 128), 256, GP_SM>>>(
        (const uint32_t*)p_hA, p_wfc, fc_b, nullptr, p_raw, RAWN);

    // ---- Sigma (symmetric) ----
    sigma_sym<<<dim3(36, B_SZ), 256>>>(out);
}

// round 14
// speedup vs baseline: 1.1375x; 1.0032x over previous
#include <cuda_runtime.h>
#include <math.h>
#include <stdint.h>

#define B_SZ   256
#define T_SZ   64
#define IN_SZ  500
#define HID    512
#define G4     2048
#define RAWN   16532
#define NA     500
#define NF     32
#define GRIDN  256

__device__ float g_xg[(size_t)T_SZ * B_SZ * G4];
__device__ float g_hseq[(size_t)T_SZ * B_SZ * HID];
__device__ float g_hA[B_SZ * HID];
__device__ float g_hB[B_SZ * HID];
__device__ float g_raw[(size_t)B_SZ * RAWN];
__device__ unsigned long long g_flags[GRIDN];
// pre-converted tf32-bit operands
__device__ uint32_t g_xc[(size_t)T_SZ * B_SZ * HID];
__device__ uint32_t g_wc0[(size_t)G4 * HID];
__device__ uint32_t g_wc1[(size_t)G4 * HID];
__device__ uint32_t g_wfc[(size_t)RAWN * HID];

__device__ __forceinline__ float sigmf(float x) { return 1.f / (1.f + expf(-x)); }

__device__ __forceinline__ uint32_t f2tf32(float f) {
    uint32_t r;
    asm("cvt.rna.tf32.f32 %0, %1;" : "=r"(r) : "f"(f));
    return r;
}

__device__ __forceinline__ void mma_tf32(float* c, const uint32_t* a, const uint32_t* b) {
    asm volatile(
        "mma.sync.aligned.m16n8k8.row.col.f32.tf32.tf32.f32 "
        "{%0,%1,%2,%3}, {%4,%5,%6,%7}, {%8,%9}, {%0,%1,%2,%3};\n"
        : "+f"(c[0]), "+f"(c[1]), "+f"(c[2]), "+f"(c[3])
        : "r"(a[0]), "r"(a[1]), "r"(a[2]), "r"(a[3]), "r"(b[0]), "r"(b[1]));
}

__device__ __forceinline__ void ldsm_x4(uint32_t* r, uint32_t addr) {
    asm volatile("ldmatrix.sync.aligned.m8n8.x4.shared.b16 {%0,%1,%2,%3}, [%4];"
        : "=r"(r[0]), "=r"(r[1]), "=r"(r[2]), "=r"(r[3]) : "r"(addr));
}

__device__ __forceinline__ uint32_t smem_u32(const void* p) {
    uint32_t a;
    asm("{ .reg .u64 t; cvta.to.shared.u64 t, %1; cvt.u32.u64 %0, t; }" : "=r"(a) : "l"(p));
    return a;
}

// ---------------- prep kernels ----------------
__global__ void cvt_pad_kernel(const float* __restrict__ in, uint32_t* __restrict__ out,
                               int Nrows, int Kin)
{
    size_t idx = (size_t)blockIdx.x * 256 + threadIdx.x;
    if (idx >= (size_t)Nrows * 512) return;
    int n = (int)(idx >> 9), k = (int)(idx & 511);
    out[idx] = (k < Kin) ? f2tf32(in[(size_t)n * Kin + k]) : 0u;
}

__global__ void cvt_x_kernel(const float* __restrict__ x, uint32_t* __restrict__ out)
{
    size_t idx = (size_t)blockIdx.x * 256 + threadIdx.x;
    int r = (int)(idx >> 9), k = (int)(idx & 511);
    int t = r >> 8, b = r & 255;
    out[idx] = (k < IN_SZ) ? f2tf32(x[((size_t)b * T_SZ + t) * IN_SZ + k]) : 0u;
}

// ================= persistent LSTM v2: 256 blocks x 128 thr, 2 blocks/SM =================
// Block: 64 batch x 32 gate-cols (8 hid x 4 interleaved gates) x K=512.
// Warp w owns batch rows w*16..+15, ALL 32 gate cols; fully warp-private pipeline.
// smem: W [32][516]u32 @0 (66048B); A 4 warps x 2 bufs x 4352B @66048;
//       xg 4 warps x 2048B @100864. Cs (2304B/warp) aliases warp's A buf0.
#define W_STR    516
#define A_STR    68
#define OFF_A2   66048
#define WBUFS    8704          // 2 * 4352 per warp
#define ABUF2    4352
#define OFF_XG2  100864
#define SM_BYTES2 109056

__global__ __launch_bounds__(128, 2) void lstm_persist(
    const float* __restrict__ w_hh, int layer)
{
    extern __shared__ __align__(16) uint32_t smraw[];
    uint32_t* Wsm = smraw;
    float*    smf = (float*)smraw;
    const uint32_t smem = smem_u32(smraw);

    const int tid  = threadIdx.x;
    const int lane = tid & 31;
    const int warp = tid >> 5;
    const int wm   = warp * 16;                  // batch rows within block
    const int h0   = (blockIdx.x & 63) * 8;      // 8 hidden units
    const int m0   = (blockIdx.x >> 6) * 64;     // 64 batch rows

    // ---- load W slice once: row n (0..31) = w_hh row (n&3)*HID + h0 + (n>>2) ----
#pragma unroll
    for (int i = 0; i < 32; i++) {
        int s   = tid + (i << 7);          // 0..4095 granules
        int row = s >> 7;                  // 0..31
        int kq  = s & 127;
        int wr  = ((row & 3) << 9) + h0 + (row >> 2);
        float4 v = *(const float4*)&w_hh[(size_t)wr * HID + (kq << 2)];
        *(uint4*)&Wsm[row * W_STR + (kq << 2)] =
            make_uint4(f2tf32(v.x), f2tf32(v.y), f2tf32(v.z), f2tf32(v.w));
    }

    // warp-private A ring + fragment bases
    const uint32_t warpA = smem + OFF_A2 + (uint32_t)warp * WBUFS;
    const uint32_t aFrag = warpA
        + (uint32_t)(((lane & 15) * A_STR + (lane >> 4) * 4) << 2);
    const uint32_t rB = (lane & 7) + ((lane & 16) ? 8 : 0);
    const uint32_t bBase0 = smem + (uint32_t)((rB * W_STR + ((lane >> 3) & 1) * 4) << 2);
    const uint32_t bBase1 = bBase0 + 16 * W_STR * 4;

    const uint32_t xgBase = smem + OFF_XG2 + (uint32_t)warp * 2048;
    const int xgW = (int)(OFF_XG2 / 4) + warp * 512;
    const int csW = (int)(OFF_A2 / 4) + warp * (WBUFS / 4);   // aliases A buf0

    const unsigned long long barBase =
        *(volatile unsigned long long*)&g_flags[blockIdx.x];

    float creg[4] = {0.f, 0.f, 0.f, 0.f};

    __syncthreads();   // W visible to all warps

    // ---- prefetch xg for t=0 ----
    {
#pragma unroll
        for (int i = 0; i < 4; i++) {
            int idx = lane + 32 * i;
            int q = idx >> 5, r = (idx >> 1) & 15, gg = idx & 1;
            const float* src = g_xg + ((size_t)0 * B_SZ + m0 + wm + r) * G4
                             + q * HID + h0 + gg * 4;
            asm volatile("cp.async.cg.shared.global [%0], [%1], 16;"
                :: "r"(xgBase + (uint32_t)(q * 512 + r * 32 + gg * 16)), "l"(src));
        }
        asm volatile("cp.async.commit_group;" ::: "memory");
    }

#define STAGE_H(c)                                                              \
    {                                                                           \
        uint32_t dbuf = warpA + (uint32_t)(((c) & 1) * ABUF2);                  \
        _Pragma("unroll")                                                       \
        for (int i = 0; i < 8; i++) {                                           \
            int idx = lane + 32 * i;                                            \
            int rl = idx >> 4;                                                  \
            int gr = idx & 15;                                                  \
            const float* src = h_in + (size_t)(m0 + wm + rl) * HID              \
                             + (c) * 64 + gr * 4;                               \
            asm volatile("cp.async.cg.shared.global [%0], [%1], 16;"            \
                :: "r"(dbuf + (uint32_t)(rl * 272 + gr * 16)), "l"(src));       \
        }                                                                       \
        asm volatile("cp.async.commit_group;" ::: "memory");                    \
    }

#define MMA_CHUNK(ck)                                                           \
    {                                                                           \
        const uint32_t ab  = aFrag  + (uint32_t)(((ck) & 1) * ABUF2);           \
        const uint32_t wb0 = bBase0 + (uint32_t)((ck) * 256);                   \
        const uint32_t wb1 = bBase1 + (uint32_t)((ck) * 256);                   \
        _Pragma("unroll")                                                       \
        for (int k8 = 0; k8 < 8; k8++) {                                        \
            uint32_t a[4], b0[4], b1[4];                                        \
            ldsm_x4(a,  ab  + (uint32_t)(k8 * 32));                             \
            ldsm_x4(b0, wb0 + (uint32_t)(k8 * 32));                             \
            ldsm_x4(b1, wb1 + (uint32_t)(k8 * 32));                             \
            mma_tf32(c[0], a, b0);                                              \
            mma_tf32(c[1], a, b0 + 2);                                          \
            mma_tf32(c[2], a, b1);                                              \
            mma_tf32(c[3], a, b1 + 2);                                          \
        }                                                                       \
    }

    for (int t = 0; t < T_SZ; t++) {
        const float* h_in = (t & 1) ? g_hB : g_hA;
        float* h_out      = (t & 1) ? g_hA : g_hB;

        float c[4][4];
#pragma unroll
        for (int nt = 0; nt < 4; nt++)
#pragma unroll
            for (int q = 0; q < 4; q++) c[nt][q] = 0.f;

        if (t > 0) {
            STAGE_H(0) STAGE_H(1)
            // warp-synchronous pipeline: wait -> MMA(ck) -> stage(ck+2)
#define ITER(ck, WN)                                                            \
            asm volatile("cp.async.wait_group " #WN ";" ::: "memory");          \
            MMA_CHUNK(ck)                                                       \
            if ((ck) < 6) STAGE_H((ck) + 2)
            ITER(0, 1) ITER(1, 1) ITER(2, 1) ITER(3, 1)
            ITER(4, 1) ITER(5, 1) ITER(6, 1) ITER(7, 0)
#undef ITER
            // ---- transpose gates into warp's own (drained) A buf0 ----
            {
                const int gid = lane >> 2, tig = lane & 3;
#pragma unroll
                for (int nt = 0; nt < 4; nt++) {
                    int cb = nt * 8 + 2 * tig;
                    smf[csW + gid * 36 + cb]           = c[nt][0];
                    smf[csW + gid * 36 + cb + 1]       = c[nt][1];
                    smf[csW + (gid + 8) * 36 + cb]     = c[nt][2];
                    smf[csW + (gid + 8) * 36 + cb + 1] = c[nt][3];
                }
            }
        } else {
            asm volatile("cp.async.wait_group 0;" ::: "memory");   // xg(t=0)
        }
        __syncwarp();

        // ---- epilogue: lane owns 4 cells: row wm+(lane>>1), hid h0+(lane&1)*4.. ----
        {
            const int rl = lane >> 1;
            const int hq = lane & 1;
            float4 gv[4];
            if (t > 0) {
#pragma unroll
                for (int k = 0; k < 4; k++)
                    gv[k] = *(float4*)&smf[csW + rl * 36 + hq * 16 + 4 * k];
            } else {
#pragma unroll
                for (int k = 0; k < 4; k++) gv[k] = make_float4(0, 0, 0, 0);
            }
            float4 xq[4];
#pragma unroll
            for (int q = 0; q < 4; q++)
                xq[q] = *(float4*)&smf[xgW + q * 128 + rl * 8 + hq * 4];

            float xiv[4] = {xq[0].x, xq[0].y, xq[0].z, xq[0].w};
            float xfv[4] = {xq[1].x, xq[1].y, xq[1].z, xq[1].w};
            float xgv[4] = {xq[2].x, xq[2].y, xq[2].z, xq[2].w};
            float xov[4] = {xq[3].x, xq[3].y, xq[3].z, xq[3].w};

            uint32_t hb[4];
#pragma unroll
            for (int k = 0; k < 4; k++) {
                float gi = gv[k].x + xiv[k];
                float gf = gv[k].y + xfv[k];
                float gg = gv[k].z + xgv[k];
                float go = gv[k].w + xov[k];
                float cn = sigmf(gf) * creg[k] + sigmf(gi) * tanhf(gg);
                float hn = sigmf(go) * tanhf(cn);
                creg[k] = cn;
                hb[k] = f2tf32(hn);
            }
            const int b = m0 + wm + rl;
            const int hh = h0 + hq * 4;
            *(uint4*)&h_out[(size_t)b * HID + hh] = make_uint4(hb[0], hb[1], hb[2], hb[3]);
            if (layer == 0)
                *(uint4*)&g_hseq[((size_t)t * B_SZ + b) * HID + hh] =
                    make_uint4(hb[0], hb[1], hb[2], hb[3]);
        }

        // ---- prefetch xg for t+1 ----
        if (t + 1 < T_SZ) {
#pragma unroll
            for (int i = 0; i < 4; i++) {
                int idx = lane + 32 * i;
                int q = idx >> 5, r = (idx >> 1) & 15, gg = idx & 1;
                const float* src = g_xg + ((size_t)(t + 1) * B_SZ + m0 + wm + r) * G4
                                 + q * HID + h0 + gg * 4;
                asm volatile("cp.async.cg.shared.global [%0], [%1], 16;"
                    :: "r"(xgBase + (uint32_t)(q * 512 + r * 32 + gg * 16)), "l"(src));
            }
            asm volatile("cp.async.commit_group;" ::: "memory");

            // ---- grid barrier: 256 flags, 128 threads poll 2 each ----
            __syncthreads();
            const unsigned long long tgt = barBase + (unsigned long long)(t + 1);
            if (tid == 0)
                asm volatile("st.release.gpu.global.u64 [%0], %1;"
                             :: "l"(&g_flags[blockIdx.x]), "l"(tgt) : "memory");
            {
                unsigned long long v;
                do {
                    asm volatile("ld.acquire.gpu.global.u64 %0, [%1];"
                                 : "=l"(v) : "l"(&g_flags[tid]) : "memory");
                } while (v < tgt);
                do {
                    asm volatile("ld.acquire.gpu.global.u64 %0, [%1];"
                                 : "=l"(v) : "l"(&g_flags[tid + 128]) : "memory");
                } while (v < tgt);
            }
            __syncthreads();
        }
    }
#undef STAGE_H
#undef MMA_CHUNK
}

// ============ GEMM v4 (R11 winner, unchanged): 128x128, cp.async 3-stage ============
#define GP_ST   36
#define GP_BUF  18432
#define GP_BOFF 55296
#define GP_CST  132
#define GP_SM   110592

__global__ __launch_bounds__(256, 2) void gemm_cp(
    const uint32_t* __restrict__ A,
    const uint32_t* __restrict__ W,
    const float* __restrict__ bias1, const float* __restrict__ bias2,
    float* __restrict__ C, int N)
{
    extern __shared__ __align__(16) uint32_t gsm[];
    float* Cs = (float*)gsm;
    const uint32_t smem = smem_u32(gsm);

    const int tid  = threadIdx.x;
    const int lane = tid & 31;
    const int warp = tid >> 5;
    const int wm   = (warp >> 1) * 32;
    const int wn   = (warp & 1) * 64;
    const int m0   = blockIdx.y * 128;
    const int n0   = blockIdx.x * 128;

    float c[2][8][4];
#pragma unroll
    for (int mt = 0; mt < 2; mt++)
#pragma unroll
        for (int nt = 0; nt < 8; nt++)
#pragma unroll
            for (int q = 0; q < 4; q++) c[mt][nt][q] = 0.f;

    const uint32_t aOff = (uint32_t)(((wm + (lane & 15)) * GP_ST + (lane >> 4) * 4) << 2);
    const uint32_t bRow = wn + (lane & 7) + ((lane & 16) ? 8 : 0);
    const uint32_t bOff = (uint32_t)((bRow * GP_ST + ((lane >> 3) & 1) * 4) << 2);

#define LOADST(kt)                                                               \
    {                                                                            \
        const uint32_t abase = smem + (uint32_t)(((kt) % 3) * GP_BUF);           \
        const uint32_t bbase = smem + (uint32_t)(GP_BOFF + ((kt) % 3) * GP_BUF); \
        _Pragma("unroll")                                                        \
        for (int i = 0; i < 4; i++) {                                            \
            int idx = tid + (i << 8);                                            \
            int row = idx >> 3, kq = idx & 7;                                    \
            const uint32_t* srcA = A + (size_t)(m0 + row) * 512 + (kt) * 32 + kq * 4; \
            asm volatile("cp.async.cg.shared.global [%0], [%1], 16;"             \
                :: "r"(abase + (uint32_t)((row * GP_ST + kq * 4) << 2)), "l"(srcA)); \
            int wr = n0 + row; if (wr >= N) wr = N - 1;                          \
            const uint32_t* srcB = W + (size_t)wr * 512 + (kt) * 32 + kq * 4;    \
            asm volatile("cp.async.cg.shared.global [%0], [%1], 16;"             \
                :: "r"(bbase + (uint32_t)((row * GP_ST + kq * 4) << 2)), "l"(srcB)); \
        }                                                                        \
        asm volatile("cp.async.commit_group;" ::: "memory");                     \
    }

#define GMMA(kt)                                                                 \
    {                                                                            \
        const uint32_t abuf = smem + (uint32_t)(((kt) % 3) * GP_BUF);            \
        const uint32_t bbuf = smem + (uint32_t)(GP_BOFF + ((kt) % 3) * GP_BUF);  \
        _Pragma("unroll")                                                        \
        for (int k8 = 0; k8 < 4; k8++) {                                         \
            uint32_t fa[2][4], fb[4][4];                                         \
            _Pragma("unroll")                                                    \
            for (int mt = 0; mt < 2; mt++)                                       \
                ldsm_x4(fa[mt], abuf + aOff                                      \
                        + (uint32_t)(mt * 16 * GP_ST * 4 + k8 * 32));            \
            _Pragma("unroll")                                                    \
            for (int n4 = 0; n4 < 4; n4++)                                       \
                ldsm_x4(fb[n4], bbuf + bOff                                      \
                        + (uint32_t)(n4 * 16 * GP_ST * 4 + k8 * 32));            \
            _Pragma("unroll")                                                    \
            for (int mt = 0; mt < 2; mt++)                                       \
                _Pragma("unroll")                                                \
                for (int n4 = 0; n4 < 4; n4++) {                                 \
                    mma_tf32(c[mt][2 * n4],     fa[mt], fb[n4]);                 \
                    mma_tf32(c[mt][2 * n4 + 1], fa[mt], fb[n4] + 2);             \
                }                                                                \
        }                                                                        \
    }

#define GITER(kt, WN)                                                            \
    asm volatile("cp.async.wait_group " #WN ";" ::: "memory");                   \
    __syncthreads();                                                             \
    if ((kt) + 2 < 16) LOADST((kt) + 2)                                          \
    GMMA(kt)

    LOADST(0) LOADST(1)
    GITER(0, 1)  GITER(1, 1)  GITER(2, 1)  GITER(3, 1)
    GITER(4, 1)  GITER(5, 1)  GITER(6, 1)  GITER(7, 1)
    GITER(8, 1)  GITER(9, 1)  GITER(10, 1) GITER(11, 1)
    GITER(12, 1) GITER(13, 1) GITER(14, 1) GITER(15, 0)
#undef GITER
#undef GMMA
#undef LOADST

    __syncthreads();
    {
        const int gid = lane >> 2, tig = lane & 3;
#pragma unroll
        for (int mt = 0; mt < 2; mt++)
#pragma unroll
            for (int nt = 0; nt < 8; nt++) {
                int r  = wm + mt * 16 + gid;
                int cb = wn + nt * 8 + 2 * tig;
                Cs[r * GP_CST + cb]           = c[mt][nt][0];
                Cs[r * GP_CST + cb + 1]       = c[mt][nt][1];
                Cs[(r + 8) * GP_CST + cb]     = c[mt][nt][2];
                Cs[(r + 8) * GP_CST + cb + 1] = c[mt][nt][3];
            }
    }
    __syncthreads();

#pragma unroll
    for (int i = 0; i < 16; i++) {
        int idx = tid + (i << 8);
        int row = idx >> 5, cq = idx & 31;
        int colb = n0 + cq * 4;
        if (colb < N) {
            float4 v = *(float4*)&Cs[row * GP_CST + cq * 4];
            float4 b1 = *(const float4*)&bias1[colb];
            v.x += b1.x; v.y += b1.y; v.z += b1.z; v.w += b1.w;
            if (bias2) {
                float4 b2 = *(const float4*)&bias2[colb];
                v.x += b2.x; v.y += b2.y; v.z += b2.z; v.w += b2.w;
            }
            *(float4*)&C[(size_t)(m0 + row) * N + colb] = v;
        }
    }
}

// ---------------- Sigma (symmetric): 36 upper-triangle tiles + mirror ----------------
__global__ __launch_bounds__(256) void sigma_sym(float* __restrict__ out)
{
    __shared__ float fvs[32];
    __shared__ float Ln[32][64];
    __shared__ float Lm[32][64];
    __shared__ float Ts[64][65];

    const int b = blockIdx.y;
    int L = blockIdx.x, bi = 0;
    while (L >= 8 - bi) { L -= 8 - bi; bi++; }
    const int bj = bi + L;
    const int m0 = bi * 64;
    const int n0 = bj * 64;

    const int tid = threadIdx.x;
    const int tx = tid & 15;
    const int ty = tid >> 4;
    const float* rb = g_raw + (size_t)b * RAWN;

    if (tid < 32) fvs[tid] = expf(rb[NA * NF + tid]);
    __syncthreads();

#pragma unroll
    for (int i = 0; i < 8; i++) {
        int idx = tid + i * 256;
        int nl = idx >> 5, f = idx & 31;
        int n = n0 + nl;
        float v = (n < NA) ? rb[n * NF + f] : 0.f;
        Ln[f][nl] = v * fvs[f];
        int m = m0 + nl;
        float w = (m < NA) ? rb[m * NF + f] : 0.f;
        Lm[f][nl] = w;
    }
    __syncthreads();

    float acc[4][4];
#pragma unroll
    for (int r = 0; r < 4; r++)
#pragma unroll
        for (int cc = 0; cc < 4; cc++) acc[r][cc] = 0.f;

#pragma unroll
    for (int f = 0; f < 32; f++) {
        float4 a  = *reinterpret_cast<const float4*>(&Ln[f][ty * 4]);
        float4 bb = *reinterpret_cast<const float4*>(&Lm[f][tx * 4]);
        float av[4] = {a.x, a.y, a.z, a.w};
        float bv[4] = {bb.x, bb.y, bb.z, bb.w};
#pragma unroll
        for (int r = 0; r < 4; r++)
#pragma unroll
            for (int cc = 0; cc < 4; cc++)
                acc[r][cc] = fmaf(av[r], bv[cc], acc[r][cc]);
    }

    const int mBase = m0 + tx * 4;
#pragma unroll
    for (int r = 0; r < 4; r++) {
        int nl = ty * 4 + r;
        int n = n0 + nl;
        float o[4] = {acc[r][0], acc[r][1], acc[r][2], acc[r][3]};
        Ts[nl][tx * 4]     = o[0];
        Ts[nl][tx * 4 + 1] = o[1];
        Ts[nl][tx * 4 + 2] = o[2];
        Ts[nl][tx * 4 + 3] = o[3];
        if (n < NA && mBase < NA) {
            int d = n - mBase;
            if (d >= 0 && d < 4) o[d] += expf(rb[NA * NF + NF + n]);
            float4 ov = {o[0], o[1], o[2], o[3]};
            *reinterpret_cast<float4*>(&out[(size_t)b * NA * NA + (size_t)n * NA + mBase]) = ov;
        }
    }

    if (bi != bj) {
        __syncthreads();
        for (int idx = tid; idx < 64 * 64; idx += 256) {
            int mr = idx >> 6;
            int nc = idx & 63;
            int m = m0 + mr;
            int ncol = n0 + nc;
            if (m < NA && ncol < NA)
                out[(size_t)b * NA * NA + (size_t)m * NA + ncol] = Ts[nc][mr];
        }
    }
}

// ---------------- launch ----------------
extern "C" void kernel_launch(void* const* d_in, const int* in_sizes, int n_in,
                              void* d_out, int out_size)
{
    const float* x     = (const float*)d_in[0];
    const float* w_ih0 = (const float*)d_in[1];
    const float* w_hh0 = (const float*)d_in[2];
    const float* b_ih0 = (const float*)d_in[3];
    const float* b_hh0 = (const float*)d_in[4];
    const float* w_ih1 = (const float*)d_in[5];
    const float* w_hh1 = (const float*)d_in[6];
    const float* b_ih1 = (const float*)d_in[7];
    const float* b_hh1 = (const float*)d_in[8];
    const float* fc_w  = (const float*)d_in[9];
    const float* fc_b  = (const float*)d_in[10];
    float* out = (float*)d_out;

    static bool attr_done = false;
    if (!attr_done) {
        cudaFuncSetAttribute(lstm_persist,
            cudaFuncAttributeMaxDynamicSharedMemorySize, SM_BYTES2);
        cudaFuncSetAttribute(gemm_cp,
            cudaFuncAttributeMaxDynamicSharedMemorySize, GP_SM);
        attr_done = true;
    }

    uint32_t *p_xc, *p_wc0, *p_wc1, *p_wfc;
    cudaGetSymbolAddress((void**)&p_xc,  g_xc);
    cudaGetSymbolAddress((void**)&p_wc0, g_wc0);
    cudaGetSymbolAddress((void**)&p_wc1, g_wc1);
    cudaGetSymbolAddress((void**)&p_wfc, g_wfc);
    float *p_xg, *p_hseq, *p_hA, *p_raw;
    cudaGetSymbolAddress((void**)&p_xg,   g_xg);
    cudaGetSymbolAddress((void**)&p_hseq, g_hseq);
    cudaGetSymbolAddress((void**)&p_hA,   g_hA);
    cudaGetSymbolAddress((void**)&p_raw,  g_raw);

    // ---- prep ----
    cvt_x_kernel<<<(T_SZ * B_SZ * HID) / 256, 256>>>(x, p_xc);
    cvt_pad_kernel<<<(G4 * HID) / 256, 256>>>(w_ih0, p_wc0, G4, IN_SZ);
    cvt_pad_kernel<<<(G4 * HID) / 256, 256>>>(w_ih1, p_wc1, G4, HID);
    cvt_pad_kernel<<<((RAWN * HID) + 255) / 256, 256>>>(fc_w, p_wfc, RAWN, HID);

    // ---- layer 0 ----
    gemm_cp<<<dim3(G4 / 128, (B_SZ * T_SZ) / 128), 256, GP_SM>>>(
        p_xc, p_wc0, b_ih0, b_hh0, p_xg, G4);
    lstm_persist<<<GRIDN, 128, SM_BYTES2>>>(w_hh0, 0);

    // ---- layer 1 ----
    gemm_cp<<<dim3(G4 / 128, (B_SZ * T_SZ) / 128), 256, GP_SM>>>(
        (const uint32_t*)p_hseq, p_wc1, b_ih1, b_hh1, p_xg, G4);
    lstm_persist<<<GRIDN, 128, SM_BYTES2>>>(w_hh1, 1);
    // final h (t=63, odd) in g_hA

    // ---- FC ----
    gemm_cp<<<dim3((RAWN + 127) / 128, B_SZ / 128), 256, GP_SM>>>(
        (const uint32_t*)p_hA, p_wfc, fc_b, nullptr, p_raw, RAWN);

    // ---- Sigma (symmetric) ----
    sigma_sym<<<dim3(36, B_SZ), 256>>>(out);
}

// round 15
// speedup vs baseline: 1.1673x; 1.0262x over previous
#include <cuda_runtime.h>
#include <math.h>
#include <stdint.h>

#define B_SZ   256
#define T_SZ   64
#define IN_SZ  500
#define HID    512
#define G4     2048
#define RAWN   16532
#define NA     500
#define NF     32
#define GRIDN  256

__device__ float g_xg[(size_t)T_SZ * B_SZ * G4];
__device__ float g_hseq[(size_t)T_SZ * B_SZ * HID];
__device__ float g_hA[B_SZ * HID];
__device__ float g_hB[B_SZ * HID];
__device__ float g_raw[(size_t)B_SZ * RAWN];
__device__ unsigned long long g_flags[GRIDN];
// pre-converted tf32-bit operands
__device__ uint32_t g_xc[(size_t)T_SZ * B_SZ * HID];
__device__ uint32_t g_wc0[(size_t)G4 * HID];
__device__ uint32_t g_wc1[(size_t)G4 * HID];
__device__ uint32_t g_wfc[(size_t)RAWN * HID];

__device__ __forceinline__ float sigmf(float x) { return 1.f / (1.f + expf(-x)); }

__device__ __forceinline__ uint32_t f2tf32(float f) {
    uint32_t r;
    asm("cvt.rna.tf32.f32 %0, %1;" : "=r"(r) : "f"(f));
    return r;
}

__device__ __forceinline__ void mma_tf32(float* c, const uint32_t* a, const uint32_t* b) {
    asm volatile(
        "mma.sync.aligned.m16n8k8.row.col.f32.tf32.tf32.f32 "
        "{%0,%1,%2,%3}, {%4,%5,%6,%7}, {%8,%9}, {%0,%1,%2,%3};\n"
        : "+f"(c[0]), "+f"(c[1]), "+f"(c[2]), "+f"(c[3])
        : "r"(a[0]), "r"(a[1]), "r"(a[2]), "r"(a[3]), "r"(b[0]), "r"(b[1]));
}

__device__ __forceinline__ void ldsm_x4(uint32_t* r, uint32_t addr) {
    asm volatile("ldmatrix.sync.aligned.m8n8.x4.shared.b16 {%0,%1,%2,%3}, [%4];"
        : "=r"(r[0]), "=r"(r[1]), "=r"(r[2]), "=r"(r[3]) : "r"(addr));
}

__device__ __forceinline__ uint32_t smem_u32(const void* p) {
    uint32_t a;
    asm("{ .reg .u64 t; cvta.to.shared.u64 t, %1; cvt.u32.u64 %0, t; }" : "=r"(a) : "l"(p));
    return a;
}

// ---------------- prep kernels ----------------
__global__ void cvt_pad_kernel(const float* __restrict__ in, uint32_t* __restrict__ out,
                               int Nrows, int Kin)
{
    size_t idx = (size_t)blockIdx.x * 256 + threadIdx.x;
    if (idx >= (size_t)Nrows * 512) return;
    int n = (int)(idx >> 9), k = (int)(idx & 511);
    out[idx] = (k < Kin) ? f2tf32(in[(size_t)n * Kin + k]) : 0u;
}

__global__ void cvt_x_kernel(const float* __restrict__ x, uint32_t* __restrict__ out)
{
    size_t idx = (size_t)blockIdx.x * 256 + threadIdx.x;
    int r = (int)(idx >> 9), k = (int)(idx & 511);
    int t = r >> 8, b = r & 255;
    out[idx] = (k < IN_SZ) ? f2tf32(x[((size_t)b * T_SZ + t) * IN_SZ + k]) : 0u;
}

// ================= persistent LSTM v2 (R14, unchanged) =================
#define W_STR    516
#define A_STR    68
#define OFF_A2   66048
#define WBUFS    8704
#define ABUF2    4352
#define OFF_XG2  100864
#define SM_BYTES2 109056

__global__ __launch_bounds__(128, 2) void lstm_persist(
    const float* __restrict__ w_hh, int layer)
{
    extern __shared__ __align__(16) uint32_t smraw[];
    uint32_t* Wsm = smraw;
    float*    smf = (float*)smraw;
    const uint32_t smem = smem_u32(smraw);

    const int tid  = threadIdx.x;
    const int lane = tid & 31;
    const int warp = tid >> 5;
    const int wm   = warp * 16;
    const int h0   = (blockIdx.x & 63) * 8;
    const int m0   = (blockIdx.x >> 6) * 64;

#pragma unroll
    for (int i = 0; i < 32; i++) {
        int s   = tid + (i << 7);
        int row = s >> 7;
        int kq  = s & 127;
        int wr  = ((row & 3) << 9) + h0 + (row >> 2);
        float4 v = *(const float4*)&w_hh[(size_t)wr * HID + (kq << 2)];
        *(uint4*)&Wsm[row * W_STR + (kq << 2)] =
            make_uint4(f2tf32(v.x), f2tf32(v.y), f2tf32(v.z), f2tf32(v.w));
    }

    const uint32_t warpA = smem + OFF_A2 + (uint32_t)warp * WBUFS;
    const uint32_t aFrag = warpA
        + (uint32_t)(((lane & 15) * A_STR + (lane >> 4) * 4) << 2);
    const uint32_t rB = (lane & 7) + ((lane & 16) ? 8 : 0);
    const uint32_t bBase0 = smem + (uint32_t)((rB * W_STR + ((lane >> 3) & 1) * 4) << 2);
    const uint32_t bBase1 = bBase0 + 16 * W_STR * 4;

    const uint32_t xgBase = smem + OFF_XG2 + (uint32_t)warp * 2048;
    const int xgW = (int)(OFF_XG2 / 4) + warp * 512;
    const int csW = (int)(OFF_A2 / 4) + warp * (WBUFS / 4);

    const unsigned long long barBase =
        *(volatile unsigned long long*)&g_flags[blockIdx.x];

    float creg[4] = {0.f, 0.f, 0.f, 0.f};

    __syncthreads();

    {
#pragma unroll
        for (int i = 0; i < 4; i++) {
            int idx = lane + 32 * i;
            int q = idx >> 5, r = (idx >> 1) & 15, gg = idx & 1;
            const float* src = g_xg + ((size_t)0 * B_SZ + m0 + wm + r) * G4
                             + q * HID + h0 + gg * 4;
            asm volatile("cp.async.cg.shared.global [%0], [%1], 16;"
                :: "r"(xgBase + (uint32_t)(q * 512 + r * 32 + gg * 16)), "l"(src));
        }
        asm volatile("cp.async.commit_group;" ::: "memory");
    }

#define STAGE_H(c)                                                              \
    {                                                                           \
        uint32_t dbuf = warpA + (uint32_t)(((c) & 1) * ABUF2);                  \
        _Pragma("unroll")                                                       \
        for (int i = 0; i < 8; i++) {                                           \
            int idx = lane + 32 * i;                                            \
            int rl = idx >> 4;                                                  \
            int gr = idx & 15;                                                  \
            const float* src = h_in + (size_t)(m0 + wm + rl) * HID              \
                             + (c) * 64 + gr * 4;                               \
            asm volatile("cp.async.cg.shared.global [%0], [%1], 16;"            \
                :: "r"(dbuf + (uint32_t)(rl * 272 + gr * 16)), "l"(src));       \
        }                                                                       \
        asm volatile("cp.async.commit_group;" ::: "memory");                    \
    }

#define MMA_CHUNK(ck)                                                           \
    {                                                                           \
        const uint32_t ab  = aFrag  + (uint32_t)(((ck) & 1) * ABUF2);           \
        const uint32_t wb0 = bBase0 + (uint32_t)((ck) * 256);                   \
        const uint32_t wb1 = bBase1 + (uint32_t)((ck) * 256);                   \
        _Pragma("unroll")                                                       \
        for (int k8 = 0; k8 < 8; k8++) {                                        \
            uint32_t a[4], b0[4], b1[4];                                        \
            ldsm_x4(a,  ab  + (uint32_t)(k8 * 32));                             \
            ldsm_x4(b0, wb0 + (uint32_t)(k8 * 32));                             \
            ldsm_x4(b1, wb1 + (uint32_t)(k8 * 32));                             \
            mma_tf32(c[0], a, b0);                                              \
            mma_tf32(c[1], a, b0 + 2);                                          \
            mma_tf32(c[2], a, b1);                                              \
            mma_tf32(c[3], a, b1 + 2);                                          \
        }                                                                       \
    }

    for (int t = 0; t < T_SZ; t++) {
        const float* h_in = (t & 1) ? g_hB : g_hA;
        float* h_out      = (t & 1) ? g_hA : g_hB;

        float c[4][4];
#pragma unroll
        for (int nt = 0; nt < 4; nt++)
#pragma unroll
            for (int q = 0; q < 4; q++) c[nt][q] = 0.f;

        if (t > 0) {
            STAGE_H(0) STAGE_H(1)
#define ITER(ck, WN)                                                            \
            asm volatile("cp.async.wait_group " #WN ";" ::: "memory");          \
            MMA_CHUNK(ck)                                                       \
            if ((ck) < 6) STAGE_H((ck) + 2)
            ITER(0, 1) ITER(1, 1) ITER(2, 1) ITER(3, 1)
            ITER(4, 1) ITER(5, 1) ITER(6, 1) ITER(7, 0)
#undef ITER
            {
                const int gid = lane >> 2, tig = lane & 3;
#pragma unroll
                for (int nt = 0; nt < 4; nt++) {
                    int cb = nt * 8 + 2 * tig;
                    smf[csW + gid * 36 + cb]           = c[nt][0];
                    smf[csW + gid * 36 + cb + 1]       = c[nt][1];
                    smf[csW + (gid + 8) * 36 + cb]     = c[nt][2];
                    smf[csW + (gid + 8) * 36 + cb + 1] = c[nt][3];
                }
            }
        } else {
            asm volatile("cp.async.wait_group 0;" ::: "memory");
        }
        __syncwarp();

        {
            const int rl = lane >> 1;
            const int hq = lane & 1;
            float4 gv[4];
            if (t > 0) {
#pragma unroll
                for (int k = 0; k < 4; k++)
                    gv[k] = *(float4*)&smf[csW + rl * 36 + hq * 16 + 4 * k];
            } else {
#pragma unroll
                for (int k = 0; k < 4; k++) gv[k] = make_float4(0, 0, 0, 0);
            }
            float4 xq[4];
#pragma unroll
            for (int q = 0; q < 4; q++)
                xq[q] = *(float4*)&smf[xgW + q * 128 + rl * 8 + hq * 4];

            float xiv[4] = {xq[0].x, xq[0].y, xq[0].z, xq[0].w};
            float xfv[4] = {xq[1].x, xq[1].y, xq[1].z, xq[1].w};
            float xgv[4] = {xq[2].x, xq[2].y, xq[2].z, xq[2].w};
            float xov[4] = {xq[3].x, xq[3].y, xq[3].z, xq[3].w};

            uint32_t hb[4];
#pragma unroll
            for (int k = 0; k < 4; k++) {
                float gi = gv[k].x + xiv[k];
                float gf = gv[k].y + xfv[k];
                float gg = gv[k].z + xgv[k];
                float go = gv[k].w + xov[k];
                float cn = sigmf(gf) * creg[k] + sigmf(gi) * tanhf(gg);
                float hn = sigmf(go) * tanhf(cn);
                creg[k] = cn;
                hb[k] = f2tf32(hn);
            }
            const int b = m0 + wm + rl;
            const int hh = h0 + hq * 4;
            *(uint4*)&h_out[(size_t)b * HID + hh] = make_uint4(hb[0], hb[1], hb[2], hb[3]);
            if (layer == 0)
                *(uint4*)&g_hseq[((size_t)t * B_SZ + b) * HID + hh] =
                    make_uint4(hb[0], hb[1], hb[2], hb[3]);
        }

        if (t + 1 < T_SZ) {
#pragma unroll
            for (int i = 0; i < 4; i++) {
                int idx = lane + 32 * i;
                int q = idx >> 5, r = (idx >> 1) & 15, gg = idx & 1;
                const float* src = g_xg + ((size_t)(t + 1) * B_SZ + m0 + wm + r) * G4
                                 + q * HID + h0 + gg * 4;
                asm volatile("cp.async.cg.shared.global [%0], [%1], 16;"
                    :: "r"(xgBase + (uint32_t)(q * 512 + r * 32 + gg * 16)), "l"(src));
            }
            asm volatile("cp.async.commit_group;" ::: "memory");

            __syncthreads();
            const unsigned long long tgt = barBase + (unsigned long long)(t + 1);
            if (tid == 0)
                asm volatile("st.release.gpu.global.u64 [%0], %1;"
                             :: "l"(&g_flags[blockIdx.x]), "l"(tgt) : "memory");
            {
                unsigned long long v;
                do {
                    asm volatile("ld.acquire.gpu.global.u64 %0, [%1];"
                                 : "=l"(v) : "l"(&g_flags[tid]) : "memory");
                } while (v < tgt);
                do {
                    asm volatile("ld.acquire.gpu.global.u64 %0, [%1];"
                                 : "=l"(v) : "l"(&g_flags[tid + 128]) : "memory");
                } while (v < tgt);
            }
            __syncthreads();
        }
    }
#undef STAGE_H
#undef MMA_CHUNK
}

// ============ GEMM v5: 128x128 block, 4 warps, warp tile 64x64 (128B/MMA) ============
// C[M][N] = A[M][512](tf32 bits) @ W[N][512](tf32 bits)^T + bias1 (+bias2)
// 128 threads. K = 512 (16 tiles of 32). 3-stage cp.async. 2 blocks/SM.
#define GP_ST   36
#define GP_BUF  18432
#define GP_BOFF 55296
#define GP_CST  132
#define GP_SM   110592

__global__ __launch_bounds__(128, 2) void gemm_cp(
    const uint32_t* __restrict__ A,
    const uint32_t* __restrict__ W,
    const float* __restrict__ bias1, const float* __restrict__ bias2,
    float* __restrict__ C, int N)
{
    extern __shared__ __align__(16) uint32_t gsm[];
    float* Cs = (float*)gsm;
    const uint32_t smem = smem_u32(gsm);

    const int tid  = threadIdx.x;
    const int lane = tid & 31;
    const int warp = tid >> 5;
    const int wm   = (warp >> 1) * 64;    // 2 groups along M(128)
    const int wn   = (warp & 1) * 64;     // 2 groups along N(128)
    const int m0   = blockIdx.y * 128;
    const int n0   = blockIdx.x * 128;

    float c[4][8][4];
#pragma unroll
    for (int mt = 0; mt < 4; mt++)
#pragma unroll
        for (int nt = 0; nt < 8; nt++)
#pragma unroll
            for (int q = 0; q < 4; q++) c[mt][nt][q] = 0.f;

    const uint32_t aOff = (uint32_t)(((wm + (lane & 15)) * GP_ST + (lane >> 4) * 4) << 2);
    const uint32_t bRow = wn + (lane & 7) + ((lane & 16) ? 8 : 0);
    const uint32_t bOff = (uint32_t)((bRow * GP_ST + ((lane >> 3) & 1) * 4) << 2);

#define LOADST(kt)                                                               \
    {                                                                            \
        const uint32_t abase = smem + (uint32_t)(((kt) % 3) * GP_BUF);           \
        const uint32_t bbase = smem + (uint32_t)(GP_BOFF + ((kt) % 3) * GP_BUF); \
        _Pragma("unroll")                                                        \
        for (int i = 0; i < 8; i++) {                                            \
            int idx = tid + (i << 7);                                            \
            int row = idx >> 3, kq = idx & 7;                                    \
            const uint32_t* srcA = A + (size_t)(m0 + row) * 512 + (kt) * 32 + kq * 4; \
            asm volatile("cp.async.cg.shared.global [%0], [%1], 16;"             \
                :: "r"(abase + (uint32_t)((row * GP_ST + kq * 4) << 2)), "l"(srcA)); \
            int wr = n0 + row; if (wr >= N) wr = N - 1;                          \
            const uint32_t* srcB = W + (size_t)wr * 512 + (kt) * 32 + kq * 4;    \
            asm volatile("cp.async.cg.shared.global [%0], [%1], 16;"             \
                :: "r"(bbase + (uint32_t)((row * GP_ST + kq * 4) << 2)), "l"(srcB)); \
        }                                                                        \
        asm volatile("cp.async.commit_group;" ::: "memory");                     \
    }

#define GMMA(kt)                                                                 \
    {                                                                            \
        const uint32_t abuf = smem + (uint32_t)(((kt) % 3) * GP_BUF);            \
        const uint32_t bbuf = smem + (uint32_t)(GP_BOFF + ((kt) % 3) * GP_BUF);  \
        _Pragma("unroll")                                                        \
        for (int k8 = 0; k8 < 4; k8++) {                                         \
            uint32_t fa[4][4], fb[4][4];                                         \
            _Pragma("unroll")                                                    \
            for (int mt = 0; mt < 4; mt++)                                       \
                ldsm_x4(fa[mt], abuf + aOff                                      \
                        + (uint32_t)(mt * 16 * GP_ST * 4 + k8 * 32));            \
            _Pragma("unroll")                                                    \
            for (int n4 = 0; n4 < 4; n4++)                                       \
                ldsm_x4(fb[n4], bbuf + bOff                                      \
                        + (uint32_t)(n4 * 16 * GP_ST * 4 + k8 * 32));            \
            _Pragma("unroll")                                                    \
            for (int mt = 0; mt < 4; mt++)                                       \
                _Pragma("unroll")                                                \
                for (int n4 = 0; n4 < 4; n4++) {                                 \
                    mma_tf32(c[mt][2 * n4],     fa[mt], fb[n4]);                 \
                    mma_tf32(c[mt][2 * n4 + 1], fa[mt], fb[n4] + 2);             \
                }                                                                \
        }                                                                        \
    }

#define GITER(kt, WN)                                                            \
    asm volatile("cp.async.wait_group " #WN ";" ::: "memory");                   \
    __syncthreads();                                                             \
    if ((kt) + 2 < 16) LOADST((kt) + 2)                                          \
    GMMA(kt)

    LOADST(0) LOADST(1)
    GITER(0, 1)  GITER(1, 1)  GITER(2, 1)  GITER(3, 1)
    GITER(4, 1)  GITER(5, 1)  GITER(6, 1)  GITER(7, 1)
    GITER(8, 1)  GITER(9, 1)  GITER(10, 1) GITER(11, 1)
    GITER(12, 1) GITER(13, 1) GITER(14, 1) GITER(15, 0)
#undef GITER
#undef GMMA
#undef LOADST

    __syncthreads();
    {
        const int gid = lane >> 2, tig = lane & 3;
#pragma unroll
        for (int mt = 0; mt < 4; mt++)
#pragma unroll
            for (int nt = 0; nt < 8; nt++) {
                int r  = wm + mt * 16 + gid;
                int cb = wn + nt * 8 + 2 * tig;
                Cs[r * GP_CST + cb]           = c[mt][nt][0];
                Cs[r * GP_CST + cb + 1]       = c[mt][nt][1];
                Cs[(r + 8) * GP_CST + cb]     = c[mt][nt][2];
                Cs[(r + 8) * GP_CST + cb + 1] = c[mt][nt][3];
            }
    }
    __syncthreads();

#pragma unroll
    for (int i = 0; i < 32; i++) {
        int idx = tid + (i << 7);
        int row = idx >> 5, cq = idx & 31;
        int colb = n0 + cq * 4;
        if (colb < N) {   // N % 4 == 0 in all uses
            float4 v = *(float4*)&Cs[row * GP_CST + cq * 4];
            float4 b1 = *(const float4*)&bias1[colb];
            v.x += b1.x; v.y += b1.y; v.z += b1.z; v.w += b1.w;
            if (bias2) {
                float4 b2 = *(const float4*)&bias2[colb];
                v.x += b2.x; v.y += b2.y; v.z += b2.z; v.w += b2.w;
            }
            *(float4*)&C[(size_t)(m0 + row) * N + colb] = v;
        }
    }
}

// ---------------- Sigma (symmetric, R13 winner, unchanged) ----------------
__global__ __launch_bounds__(256) void sigma_sym(float* __restrict__ out)
{
    __shared__ float fvs[32];
    __shared__ float Ln[32][64];
    __shared__ float Lm[32][64];
    __shared__ float Ts[64][65];

    const int b = blockIdx.y;
    int L = blockIdx.x, bi = 0;
    while (L >= 8 - bi) { L -= 8 - bi; bi++; }
    const int bj = bi + L;
    const int m0 = bi * 64;
    const int n0 = bj * 64;

    const int tid = threadIdx.x;
    const int tx = tid & 15;
    const int ty = tid >> 4;
    const float* rb = g_raw + (size_t)b * RAWN;

    if (tid < 32) fvs[tid] = expf(rb[NA * NF + tid]);
    __syncthreads();

#pragma unroll
    for (int i = 0; i < 8; i++) {
        int idx = tid + i * 256;
        int nl = idx >> 5, f = idx & 31;
        int n = n0 + nl;
        float v = (n < NA) ? rb[n * NF + f] : 0.f;
        Ln[f][nl] = v * fvs[f];
        int m = m0 + nl;
        float w = (m < NA) ? rb[m * NF + f] : 0.f;
        Lm[f][nl] = w;
    }
    __syncthreads();

    float acc[4][4];
#pragma unroll
    for (int r = 0; r < 4; r++)
#pragma unroll
        for (int cc = 0; cc < 4; cc++) acc[r][cc] = 0.f;

#pragma unroll
    for (int f = 0; f < 32; f++) {
        float4 a  = *reinterpret_cast<const float4*>(&Ln[f][ty * 4]);
        float4 bb = *reinterpret_cast<const float4*>(&Lm[f][tx * 4]);
        float av[4] = {a.x, a.y, a.z, a.w};
        float bv[4] = {bb.x, bb.y, bb.z, bb.w};
#pragma unroll
        for (int r = 0; r < 4; r++)
#pragma unroll
            for (int cc = 0; cc < 4; cc++)
                acc[r][cc] = fmaf(av[r], bv[cc], acc[r][cc]);
    }

    const int mBase = m0 + tx * 4;
#pragma unroll
    for (int r = 0; r < 4; r++) {
        int nl = ty * 4 + r;
        int n = n0 + nl;
        float o[4] = {acc[r][0], acc[r][1], acc[r][2], acc[r][3]};
        Ts[nl][tx * 4]     = o[0];
        Ts[nl][tx * 4 + 1] = o[1];
        Ts[nl][tx * 4 + 2] = o[2];
        Ts[nl][tx * 4 + 3] = o[3];
        if (n < NA && mBase < NA) {
            int d = n - mBase;
            if (d >= 0 && d < 4) o[d] += expf(rb[NA * NF + NF + n]);
            float4 ov = {o[0], o[1], o[2], o[3]};
            *reinterpret_cast<float4*>(&out[(size_t)b * NA * NA + (size_t)n * NA + mBase]) = ov;
        }
    }

    if (bi != bj) {
        __syncthreads();
        for (int idx = tid; idx < 64 * 64; idx += 256) {
            int mr = idx >> 6;
            int nc = idx & 63;
            int m = m0 + mr;
            int ncol = n0 + nc;
            if (m < NA && ncol < NA)
                out[(size_t)b * NA * NA + (size_t)m * NA + ncol] = Ts[nc][mr];
        }
    }
}

// ---------------- launch ----------------
extern "C" void kernel_launch(void* const* d_in, const int* in_sizes, int n_in,
                              void* d_out, int out_size)
{
    const float* x     = (const float*)d_in[0];
    const float* w_ih0 = (const float*)d_in[1];
    const float* w_hh0 = (const float*)d_in[2];
    const float* b_ih0 = (const float*)d_in[3];
    const float* b_hh0 = (const float*)d_in[4];
    const float* w_ih1 = (const float*)d_in[5];
    const float* w_hh1 = (const float*)d_in[6];
    const float* b_ih1 = (const float*)d_in[7];
    const float* b_hh1 = (const float*)d_in[8];
    const float* fc_w  = (const float*)d_in[9];
    const float* fc_b  = (const float*)d_in[10];
    float* out = (float*)d_out;

    static bool attr_done = false;
    if (!attr_done) {
        cudaFuncSetAttribute(lstm_persist,
            cudaFuncAttributeMaxDynamicSharedMemorySize, SM_BYTES2);
        cudaFuncSetAttribute(gemm_cp,
            cudaFuncAttributeMaxDynamicSharedMemorySize, GP_SM);
        attr_done = true;
    }

    uint32_t *p_xc, *p_wc0, *p_wc1, *p_wfc;
    cudaGetSymbolAddress((void**)&p_xc,  g_xc);
    cudaGetSymbolAddress((void**)&p_wc0, g_wc0);
    cudaGetSymbolAddress((void**)&p_wc1, g_wc1);
    cudaGetSymbolAddress((void**)&p_wfc, g_wfc);
    float *p_xg, *p_hseq, *p_hA, *p_raw;
    cudaGetSymbolAddress((void**)&p_xg,   g_xg);
    cudaGetSymbolAddress((void**)&p_hseq, g_hseq);
    cudaGetSymbolAddress((void**)&p_hA,   g_hA);
    cudaGetSymbolAddress((void**)&p_raw,  g_raw);

    // ---- prep ----
    cvt_x_kernel<<<(T_SZ * B_SZ * HID) / 256, 256>>>(x, p_xc);
    cvt_pad_kernel<<<(G4 * HID) / 256, 256>>>(w_ih0, p_wc0, G4, IN_SZ);
    cvt_pad_kernel<<<(G4 * HID) / 256, 256>>>(w_ih1, p_wc1, G4, HID);
    cvt_pad_kernel<<<((RAWN * HID) + 255) / 256, 256>>>(fc_w, p_wfc, RAWN, HID);

    // ---- layer 0 ----
    gemm_cp<<<dim3(G4 / 128, (B_SZ * T_SZ) / 128), 128, GP_SM>>>(
        p_xc, p_wc0, b_ih0, b_hh0, p_xg, G4);
    lstm_persist<<<GRIDN, 128, SM_BYTES2>>>(w_hh0, 0);

    // ---- layer 1 ----
    gemm_cp<<<dim3(G4 / 128, (B_SZ * T_SZ) / 128), 128, GP_SM>>>(
        (const uint32_t*)p_hseq, p_wc1, b_ih1, b_hh1, p_xg, G4);
    lstm_persist<<<GRIDN, 128, SM_BYTES2>>>(w_hh1, 1);
    // final h (t=63, odd) in g_hA

    // ---- FC ----
    gemm_cp<<<dim3((RAWN + 127) / 128, B_SZ / 128), 128, GP_SM>>>(
        (const uint32_t*)p_hA, p_wfc, fc_b, nullptr, p_raw, RAWN);

    // ---- Sigma (symmetric) ----
    sigma_sym<<<dim3(36, B_SZ), 256>>>(out);
}

// round 16
// speedup vs baseline: 1.1860x; 1.0160x over previous
#include <cuda_runtime.h>
#include <math.h>
#include <stdint.h>

#define B_SZ   256
#define T_SZ   64
#define IN_SZ  500
#define HID    512
#define G4     2048
#define RAWN   16532
#define NA     500
#define NF     32
#define GRIDN  256

__device__ float g_xg[(size_t)T_SZ * B_SZ * G4];
__device__ float g_hseq[(size_t)T_SZ * B_SZ * HID];
__device__ float g_hA[B_SZ * HID];
__device__ float g_hB[B_SZ * HID];
__device__ float g_raw[(size_t)B_SZ * RAWN];
__device__ unsigned long long g_flags[GRIDN];
// pre-converted tf32-bit operands
__device__ uint32_t g_xc[(size_t)T_SZ * B_SZ * HID];
__device__ uint32_t g_wc0[(size_t)G4 * HID];
__device__ uint32_t g_wc1[(size_t)G4 * HID];
__device__ uint32_t g_wfc[(size_t)RAWN * HID];

__device__ __forceinline__ float sigmf(float x) { return 1.f / (1.f + expf(-x)); }

__device__ __forceinline__ uint32_t f2tf32(float f) {
    uint32_t r;
    asm("cvt.rna.tf32.f32 %0, %1;" : "=r"(r) : "f"(f));
    return r;
}

__device__ __forceinline__ void mma_tf32(float* c, const uint32_t* a, const uint32_t* b) {
    asm volatile(
        "mma.sync.aligned.m16n8k8.row.col.f32.tf32.tf32.f32 "
        "{%0,%1,%2,%3}, {%4,%5,%6,%7}, {%8,%9}, {%0,%1,%2,%3};\n"
        : "+f"(c[0]), "+f"(c[1]), "+f"(c[2]), "+f"(c[3])
        : "r"(a[0]), "r"(a[1]), "r"(a[2]), "r"(a[3]), "r"(b[0]), "r"(b[1]));
}

__device__ __forceinline__ void ldsm_x4(uint32_t* r, uint32_t addr) {
    asm volatile("ldmatrix.sync.aligned.m8n8.x4.shared.b16 {%0,%1,%2,%3}, [%4];"
        : "=r"(r[0]), "=r"(r[1]), "=r"(r[2]), "=r"(r[3]) : "r"(addr));
}

__device__ __forceinline__ uint32_t smem_u32(const void* p) {
    uint32_t a;
    asm("{ .reg .u64 t; cvta.to.shared.u64 t, %1; cvt.u32.u64 %0, t; }" : "=r"(a) : "l"(p));
    return a;
}

// ---------------- prep kernels (vectorized: 1 granule = 4 floats per thread) ----------------
// Kin % 4 == 0 for all uses (500, 512) -> each granule fully in or fully padded.
__global__ void cvt_pad_v4(const float* __restrict__ in, uint32_t* __restrict__ out,
                           int Nrows, int Kin)
{
    size_t idx = (size_t)blockIdx.x * 256 + threadIdx.x;   // granule index
    if (idx >= (size_t)Nrows * 128) return;
    int n  = (int)(idx >> 7);
    int k4 = (int)(idx & 127) << 2;
    uint4 u = make_uint4(0u, 0u, 0u, 0u);
    if (k4 < Kin) {
        float4 v = *(const float4*)&in[(size_t)n * Kin + k4];
        u = make_uint4(f2tf32(v.x), f2tf32(v.y), f2tf32(v.z), f2tf32(v.w));
    }
    *(uint4*)&out[((size_t)n << 9) + k4] = u;
}

__global__ void cvt_x_v4(const float* __restrict__ x, uint32_t* __restrict__ out)
{
    size_t idx = (size_t)blockIdx.x * 256 + threadIdx.x;   // granules over [t][b][128]
    int r  = (int)(idx >> 7);        // t*256 + b
    int k4 = (int)(idx & 127) << 2;
    int t = r >> 8, b = r & 255;
    uint4 u = make_uint4(0u, 0u, 0u, 0u);
    if (k4 < IN_SZ) {
        float4 v = *(const float4*)&x[((size_t)b * T_SZ + t) * IN_SZ + k4];
        u = make_uint4(f2tf32(v.x), f2tf32(v.y), f2tf32(v.z), f2tf32(v.w));
    }
    *(uint4*)&out[((size_t)r << 9) + k4] = u;
}

// ================= persistent LSTM v2 (R14, unchanged) =================
#define W_STR    516
#define A_STR    68
#define OFF_A2   66048
#define WBUFS    8704
#define ABUF2    4352
#define OFF_XG2  100864
#define SM_BYTES2 109056

__global__ __launch_bounds__(128, 2) void lstm_persist(
    const float* __restrict__ w_hh, int layer)
{
    extern __shared__ __align__(16) uint32_t smraw[];
    uint32_t* Wsm = smraw;
    float*    smf = (float*)smraw;
    const uint32_t smem = smem_u32(smraw);

    const int tid  = threadIdx.x;
    const int lane = tid & 31;
    const int warp = tid >> 5;
    const int wm   = warp * 16;
    const int h0   = (blockIdx.x & 63) * 8;
    const int m0   = (blockIdx.x >> 6) * 64;

#pragma unroll
    for (int i = 0; i < 32; i++) {
        int s   = tid + (i << 7);
        int row = s >> 7;
        int kq  = s & 127;
        int wr  = ((row & 3) << 9) + h0 + (row >> 2);
        float4 v = *(const float4*)&w_hh[(size_t)wr * HID + (kq << 2)];
        *(uint4*)&Wsm[row * W_STR + (kq << 2)] =
            make_uint4(f2tf32(v.x), f2tf32(v.y), f2tf32(v.z), f2tf32(v.w));
    }

    const uint32_t warpA = smem + OFF_A2 + (uint32_t)warp * WBUFS;
    const uint32_t aFrag = warpA
        + (uint32_t)(((lane & 15) * A_STR + (lane >> 4) * 4) << 2);
    const uint32_t rB = (lane & 7) + ((lane & 16) ? 8 : 0);
    const uint32_t bBase0 = smem + (uint32_t)((rB * W_STR + ((lane >> 3) & 1) * 4) << 2);
    const uint32_t bBase1 = bBase0 + 16 * W_STR * 4;

    const uint32_t xgBase = smem + OFF_XG2 + (uint32_t)warp * 2048;
    const int xgW = (int)(OFF_XG2 / 4) + warp * 512;
    const int csW = (int)(OFF_A2 / 4) + warp * (WBUFS / 4);

    const unsigned long long barBase =
        *(volatile unsigned long long*)&g_flags[blockIdx.x];

    float creg[4] = {0.f, 0.f, 0.f, 0.f};

    __syncthreads();

    {
#pragma unroll
        for (int i = 0; i < 4; i++) {
            int idx = lane + 32 * i;
            int q = idx >> 5, r = (idx >> 1) & 15, gg = idx & 1;
            const float* src = g_xg + ((size_t)0 * B_SZ + m0 + wm + r) * G4
                             + q * HID + h0 + gg * 4;
            asm volatile("cp.async.cg.shared.global [%0], [%1], 16;"
                :: "r"(xgBase + (uint32_t)(q * 512 + r * 32 + gg * 16)), "l"(src));
        }
        asm volatile("cp.async.commit_group;" ::: "memory");
    }

#define STAGE_H(c)                                                              \
    {                                                                           \
        uint32_t dbuf = warpA + (uint32_t)(((c) & 1) * ABUF2);                  \
        _Pragma("unroll")                                                       \
        for (int i = 0; i < 8; i++) {                                           \
            int idx = lane + 32 * i;                                            \
            int rl = idx >> 4;                                                  \
            int gr = idx & 15;                                                  \
            const float* src = h_in + (size_t)(m0 + wm + rl) * HID              \
                             + (c) * 64 + gr * 4;                               \
            asm volatile("cp.async.cg.shared.global [%0], [%1], 16;"            \
                :: "r"(dbuf + (uint32_t)(rl * 272 + gr * 16)), "l"(src));       \
        }                                                                       \
        asm volatile("cp.async.commit_group;" ::: "memory");                    \
    }

#define MMA_CHUNK(ck)                                                           \
    {                                                                           \
        const uint32_t ab  = aFrag  + (uint32_t)(((ck) & 1) * ABUF2);           \
        const uint32_t wb0 = bBase0 + (uint32_t)((ck) * 256);                   \
        const uint32_t wb1 = bBase1 + (uint32_t)((ck) * 256);                   \
        _Pragma("unroll")                                                       \
        for (int k8 = 0; k8 < 8; k8++) {                                        \
            uint32_t a[4], b0[4], b1[4];                                        \
            ldsm_x4(a,  ab  + (uint32_t)(k8 * 32));                             \
            ldsm_x4(b0, wb0 + (uint32_t)(k8 * 32));                             \
            ldsm_x4(b1, wb1 + (uint32_t)(k8 * 32));                             \
            mma_tf32(c[0], a, b0);                                              \
            mma_tf32(c[1], a, b0 + 2);                                          \
            mma_tf32(c[2], a, b1);                                              \
            mma_tf32(c[3], a, b1 + 2);                                          \
        }                                                                       \
    }

    for (int t = 0; t < T_SZ; t++) {
        const float* h_in = (t & 1) ? g_hB : g_hA;
        float* h_out      = (t & 1) ? g_hA : g_hB;

        float c[4][4];
#pragma unroll
        for (int nt = 0; nt < 4; nt++)
#pragma unroll
            for (int q = 0; q < 4; q++) c[nt][q] = 0.f;

        if (t > 0) {
            STAGE_H(0) STAGE_H(1)
#define ITER(ck, WN)                                                            \
            asm volatile("cp.async.wait_group " #WN ";" ::: "memory");          \
            MMA_CHUNK(ck)                                                       \
            if ((ck) < 6) STAGE_H((ck) + 2)
            ITER(0, 1) ITER(1, 1) ITER(2, 1) ITER(3, 1)
            ITER(4, 1) ITER(5, 1) ITER(6, 1) ITER(7, 0)
#undef ITER
            {
                const int gid = lane >> 2, tig = lane & 3;
#pragma unroll
                for (int nt = 0; nt < 4; nt++) {
                    int cb = nt * 8 + 2 * tig;
                    smf[csW + gid * 36 + cb]           = c[nt][0];
                    smf[csW + gid * 36 + cb + 1]       = c[nt][1];
                    smf[csW + (gid + 8) * 36 + cb]     = c[nt][2];
                    smf[csW + (gid + 8) * 36 + cb + 1] = c[nt][3];
                }
            }
        } else {
            asm volatile("cp.async.wait_group 0;" ::: "memory");
        }
        __syncwarp();

        {
            const int rl = lane >> 1;
            const int hq = lane & 1;
            float4 gv[4];
            if (t > 0) {
#pragma unroll
                for (int k = 0; k < 4; k++)
                    gv[k] = *(float4*)&smf[csW + rl * 36 + hq * 16 + 4 * k];
            } else {
#pragma unroll
                for (int k = 0; k < 4; k++) gv[k] = make_float4(0, 0, 0, 0);
            }
            float4 xq[4];
#pragma unroll
            for (int q = 0; q < 4; q++)
                xq[q] = *(float4*)&smf[xgW + q * 128 + rl * 8 + hq * 4];

            float xiv[4] = {xq[0].x, xq[0].y, xq[0].z, xq[0].w};
            float xfv[4] = {xq[1].x, xq[1].y, xq[1].z, xq[1].w};
            float xgv[4] = {xq[2].x, xq[2].y, xq[2].z, xq[2].w};
            float xov[4] = {xq[3].x, xq[3].y, xq[3].z, xq[3].w};

            uint32_t hb[4];
#pragma unroll
            for (int k = 0; k < 4; k++) {
                float gi = gv[k].x + xiv[k];
                float gf = gv[k].y + xfv[k];
                float gg = gv[k].z + xgv[k];
                float go = gv[k].w + xov[k];
                float cn = sigmf(gf) * creg[k] + sigmf(gi) * tanhf(gg);
                float hn = sigmf(go) * tanhf(cn);
                creg[k] = cn;
                hb[k] = f2tf32(hn);
            }
            const int b = m0 + wm + rl;
            const int hh = h0 + hq * 4;
            *(uint4*)&h_out[(size_t)b * HID + hh] = make_uint4(hb[0], hb[1], hb[2], hb[3]);
            if (layer == 0)
                *(uint4*)&g_hseq[((size_t)t * B_SZ + b) * HID + hh] =
                    make_uint4(hb[0], hb[1], hb[2], hb[3]);
        }

        if (t + 1 < T_SZ) {
#pragma unroll
            for (int i = 0; i < 4; i++) {
                int idx = lane + 32 * i;
                int q = idx >> 5, r = (idx >> 1) & 15, gg = idx & 1;
                const float* src = g_xg + ((size_t)(t + 1) * B_SZ + m0 + wm + r) * G4
                                 + q * HID + h0 + gg * 4;
                asm volatile("cp.async.cg.shared.global [%0], [%1], 16;"
                    :: "r"(xgBase + (uint32_t)(q * 512 + r * 32 + gg * 16)), "l"(src));
            }
            asm volatile("cp.async.commit_group;" ::: "memory");

            __syncthreads();
            const unsigned long long tgt = barBase + (unsigned long long)(t + 1);
            if (tid == 0)
                asm volatile("st.release.gpu.global.u64 [%0], %1;"
                             :: "l"(&g_flags[blockIdx.x]), "l"(tgt) : "memory");
            {
                unsigned long long v;
                do {
                    asm volatile("ld.acquire.gpu.global.u64 %0, [%1];"
                                 : "=l"(v) : "l"(&g_flags[tid]) : "memory");
                } while (v < tgt);
                do {
                    asm volatile("ld.acquire.gpu.global.u64 %0, [%1];"
                                 : "=l"(v) : "l"(&g_flags[tid + 128]) : "memory");
                } while (v < tgt);
            }
            __syncthreads();
        }
    }
#undef STAGE_H
#undef MMA_CHUNK
}

// ============ GEMM v5 (R15 winner, unchanged): 128x128, 4 warps, 64x64 warp tile ============
#define GP_ST   36
#define GP_BUF  18432
#define GP_BOFF 55296
#define GP_CST  132
#define GP_SM   110592

__global__ __launch_bounds__(128, 2) void gemm_cp(
    const uint32_t* __restrict__ A,
    const uint32_t* __restrict__ W,
    const float* __restrict__ bias1, const float* __restrict__ bias2,
    float* __restrict__ C, int N)
{
    extern __shared__ __align__(16) uint32_t gsm[];
    float* Cs = (float*)gsm;
    const uint32_t smem = smem_u32(gsm);

    const int tid  = threadIdx.x;
    const int lane = tid & 31;
    const int warp = tid >> 5;
    const int wm   = (warp >> 1) * 64;
    const int wn   = (warp & 1) * 64;
    const int m0   = blockIdx.y * 128;
    const int n0   = blockIdx.x * 128;

    float c[4][8][4];
#pragma unroll
    for (int mt = 0; mt < 4; mt++)
#pragma unroll
        for (int nt = 0; nt < 8; nt++)
#pragma unroll
            for (int q = 0; q < 4; q++) c[mt][nt][q] = 0.f;

    const uint32_t aOff = (uint32_t)(((wm + (lane & 15)) * GP_ST + (lane >> 4) * 4) << 2);
    const uint32_t bRow = wn + (lane & 7) + ((lane & 16) ? 8 : 0);
    const uint32_t bOff = (uint32_t)((bRow * GP_ST + ((lane >> 3) & 1) * 4) << 2);

#define LOADST(kt)                                                               \
    {                                                                            \
        const uint32_t abase = smem + (uint32_t)(((kt) % 3) * GP_BUF);           \
        const uint32_t bbase = smem + (uint32_t)(GP_BOFF + ((kt) % 3) * GP_BUF); \
        _Pragma("unroll")                                                        \
        for (int i = 0; i < 8; i++) {                                            \
            int idx = tid + (i << 7);                                            \
            int row = idx >> 3, kq = idx & 7;                                    \
            const uint32_t* srcA = A + (size_t)(m0 + row) * 512 + (kt) * 32 + kq * 4; \
            asm volatile("cp.async.cg.shared.global [%0], [%1], 16;"             \
                :: "r"(abase + (uint32_t)((row * GP_ST + kq * 4) << 2)), "l"(srcA)); \
            int wr = n0 + row; if (wr >= N) wr = N - 1;                          \
            const uint32_t* srcB = W + (size_t)wr * 512 + (kt) * 32 + kq * 4;    \
            asm volatile("cp.async.cg.shared.global [%0], [%1], 16;"             \
                :: "r"(bbase + (uint32_t)((row * GP_ST + kq * 4) << 2)), "l"(srcB)); \
        }                                                                        \
        asm volatile("cp.async.commit_group;" ::: "memory");                     \
    }

#define GMMA(kt)                                                                 \
    {                                                                            \
        const uint32_t abuf = smem + (uint32_t)(((kt) % 3) * GP_BUF);            \
        const uint32_t bbuf = smem + (uint32_t)(GP_BOFF + ((kt) % 3) * GP_BUF);  \
        _Pragma("unroll")                                                        \
        for (int k8 = 0; k8 < 4; k8++) {                                         \
            uint32_t fa[4][4], fb[4][4];                                         \
            _Pragma("unroll")                                                    \
            for (int mt = 0; mt < 4; mt++)                                       \
                ldsm_x4(fa[mt], abuf + aOff                                      \
                        + (uint32_t)(mt * 16 * GP_ST * 4 + k8 * 32));            \
            _Pragma("unroll")                                                    \
            for (int n4 = 0; n4 < 4; n4++)                                       \
                ldsm_x4(fb[n4], bbuf + bOff                                      \
                        + (uint32_t)(n4 * 16 * GP_ST * 4 + k8 * 32));            \
            _Pragma("unroll")                                                    \
            for (int mt = 0; mt < 4; mt++)                                       \
                _Pragma("unroll")                                                \
                for (int n4 = 0; n4 < 4; n4++) {                                 \
                    mma_tf32(c[mt][2 * n4],     fa[mt], fb[n4]);                 \
                    mma_tf32(c[mt][2 * n4 + 1], fa[mt], fb[n4] + 2);             \
                }                                                                \
        }                                                                        \
    }

#define GITER(kt, WN)                                                            \
    asm volatile("cp.async.wait_group " #WN ";" ::: "memory");                   \
    __syncthreads();                                                             \
    if ((kt) + 2 < 16) LOADST((kt) + 2)                                          \
    GMMA(kt)

    LOADST(0) LOADST(1)
    GITER(0, 1)  GITER(1, 1)  GITER(2, 1)  GITER(3, 1)
    GITER(4, 1)  GITER(5, 1)  GITER(6, 1)  GITER(7, 1)
    GITER(8, 1)  GITER(9, 1)  GITER(10, 1) GITER(11, 1)
    GITER(12, 1) GITER(13, 1) GITER(14, 1) GITER(15, 0)
#undef GITER
#undef GMMA
#undef LOADST

    __syncthreads();
    {
        const int gid = lane >> 2, tig = lane & 3;
#pragma unroll
        for (int mt = 0; mt < 4; mt++)
#pragma unroll
            for (int nt = 0; nt < 8; nt++) {
                int r  = wm + mt * 16 + gid;
                int cb = wn + nt * 8 + 2 * tig;
                Cs[r * GP_CST + cb]           = c[mt][nt][0];
                Cs[r * GP_CST + cb + 1]       = c[mt][nt][1];
                Cs[(r + 8) * GP_CST + cb]     = c[mt][nt][2];
                Cs[(r + 8) * GP_CST + cb + 1] = c[mt][nt][3];
            }
    }
    __syncthreads();

#pragma unroll
    for (int i = 0; i < 32; i++) {
        int idx = tid + (i << 7);
        int row = idx >> 5, cq = idx & 31;
        int colb = n0 + cq * 4;
        if (colb < N) {
            float4 v = *(float4*)&Cs[row * GP_CST + cq * 4];
            float4 b1 = *(const float4*)&bias1[colb];
            v.x += b1.x; v.y += b1.y; v.z += b1.z; v.w += b1.w;
            if (bias2) {
                float4 b2 = *(const float4*)&bias2[colb];
                v.x += b2.x; v.y += b2.y; v.z += b2.z; v.w += b2.w;
            }
            *(float4*)&C[(size_t)(m0 + row) * N + colb] = v;
        }
    }
}

// ---------------- Sigma (symmetric, R13 winner, unchanged) ----------------
__global__ __launch_bounds__(256) void sigma_sym(float* __restrict__ out)
{
    __shared__ float fvs[32];
    __shared__ float Ln[32][64];
    __shared__ float Lm[32][64];
    __shared__ float Ts[64][65];

    const int b = blockIdx.y;
    int L = blockIdx.x, bi = 0;
    while (L >= 8 - bi) { L -= 8 - bi; bi++; }
    const int bj = bi + L;
    const int m0 = bi * 64;
    const int n0 = bj * 64;

    const int tid = threadIdx.x;
    const int tx = tid & 15;
    const int ty = tid >> 4;
    const float* rb = g_raw + (size_t)b * RAWN;

    if (tid < 32) fvs[tid] = expf(rb[NA * NF + tid]);
    __syncthreads();

#pragma unroll
    for (int i = 0; i < 8; i++) {
        int idx = tid + i * 256;
        int nl = idx >> 5, f = idx & 31;
        int n = n0 + nl;
        float v = (n < NA) ? rb[n * NF + f] : 0.f;
        Ln[f][nl] = v * fvs[f];
        int m = m0 + nl;
        float w = (m < NA) ? rb[m * NF + f] : 0.f;
        Lm[f][nl] = w;
    }
    __syncthreads();

    float acc[4][4];
#pragma unroll
    for (int r = 0; r < 4; r++)
#pragma unroll
        for (int cc = 0; cc < 4; cc++) acc[r][cc] = 0.f;

#pragma unroll
    for (int f = 0; f < 32; f++) {
        float4 a  = *reinterpret_cast<const float4*>(&Ln[f][ty * 4]);
        float4 bb = *reinterpret_cast<const float4*>(&Lm[f][tx * 4]);
        float av[4] = {a.x, a.y, a.z, a.w};
        float bv[4] = {bb.x, bb.y, bb.z, bb.w};
#pragma unroll
        for (int r = 0; r < 4; r++)
#pragma unroll
            for (int cc = 0; cc < 4; cc++)
                acc[r][cc] = fmaf(av[r], bv[cc], acc[r][cc]);
    }

    const int mBase = m0 + tx * 4;
#pragma unroll
    for (int r = 0; r < 4; r++) {
        int nl = ty * 4 + r;
        int n = n0 + nl;
        float o[4] = {acc[r][0], acc[r][1], acc[r][2], acc[r][3]};
        Ts[nl][tx * 4]     = o[0];
        Ts[nl][tx * 4 + 1] = o[1];
        Ts[nl][tx * 4 + 2] = o[2];
        Ts[nl][tx * 4 + 3] = o[3];
        if (n < NA && mBase < NA) {
            int d = n - mBase;
            if (d >= 0 && d < 4) o[d] += expf(rb[NA * NF + NF + n]);
            float4 ov = {o[0], o[1], o[2], o[3]};
            *reinterpret_cast<float4*>(&out[(size_t)b * NA * NA + (size_t)n * NA + mBase]) = ov;
        }
    }

    if (bi != bj) {
        __syncthreads();
        for (int idx = tid; idx < 64 * 64; idx += 256) {
            int mr = idx >> 6;
            int nc = idx & 63;
            int m = m0 + mr;
            int ncol = n0 + nc;
            if (m < NA && ncol < NA)
                out[(size_t)b * NA * NA + (size_t)m * NA + ncol] = Ts[nc][mr];
        }
    }
}

// ---------------- launch ----------------
extern "C" void kernel_launch(void* const* d_in, const int* in_sizes, int n_in,
                              void* d_out, int out_size)
{
    const float* x     = (const float*)d_in[0];
    const float* w_ih0 = (const float*)d_in[1];
    const float* w_hh0 = (const float*)d_in[2];
    const float* b_ih0 = (const float*)d_in[3];
    const float* b_hh0 = (const float*)d_in[4];
    const float* w_ih1 = (const float*)d_in[5];
    const float* w_hh1 = (const float*)d_in[6];
    const float* b_ih1 = (const float*)d_in[7];
    const float* b_hh1 = (const float*)d_in[8];
    const float* fc_w  = (const float*)d_in[9];
    const float* fc_b  = (const float*)d_in[10];
    float* out = (float*)d_out;

    static bool attr_done = false;
    if (!attr_done) {
        cudaFuncSetAttribute(lstm_persist,
            cudaFuncAttributeMaxDynamicSharedMemorySize, SM_BYTES2);
        cudaFuncSetAttribute(gemm_cp,
            cudaFuncAttributeMaxDynamicSharedMemorySize, GP_SM);
        attr_done = true;
    }

    uint32_t *p_xc, *p_wc0, *p_wc1, *p_wfc;
    cudaGetSymbolAddress((void**)&p_xc,  g_xc);
    cudaGetSymbolAddress((void**)&p_wc0, g_wc0);
    cudaGetSymbolAddress((void**)&p_wc1, g_wc1);
    cudaGetSymbolAddress((void**)&p_wfc, g_wfc);
    float *p_xg, *p_hseq, *p_hA, *p_raw;
    cudaGetSymbolAddress((void**)&p_xg,   g_xg);
    cudaGetSymbolAddress((void**)&p_hseq, g_hseq);
    cudaGetSymbolAddress((void**)&p_hA,   g_hA);
    cudaGetSymbolAddress((void**)&p_raw,  g_raw);

    // ---- prep (vectorized) ----
    cvt_x_v4<<<(T_SZ * B_SZ * 128) / 256, 256>>>(x, p_xc);
    cvt_pad_v4<<<(G4 * 128) / 256, 256>>>(w_ih0, p_wc0, G4, IN_SZ);
    cvt_pad_v4<<<(G4 * 128) / 256, 256>>>(w_ih1, p_wc1, G4, HID);
    cvt_pad_v4<<<((RAWN * 128) + 255) / 256, 256>>>(fc_w, p_wfc, RAWN, HID);

    // ---- layer 0 ----
    gemm_cp<<<dim3(G4 / 128, (B_SZ * T_SZ) / 128), 128, GP_SM>>>(
        p_xc, p_wc0, b_ih0, b_hh0, p_xg, G4);
    lstm_persist<<<GRIDN, 128, SM_BYTES2>>>(w_hh0, 0);

    // ---- layer 1 ----
    gemm_cp<<<dim3(G4 / 128, (B_SZ * T_SZ) / 128), 128, GP_SM>>>(
        (const uint32_t*)p_hseq, p_wc1, b_ih1, b_hh1, p_xg, G4);
    lstm_persist<<<GRIDN, 128, SM_BYTES2>>>(w_hh1, 1);
    // final h (t=63, odd) in g_hA

    // ---- FC ----
    gemm_cp<<<dim3((RAWN + 127) / 128, B_SZ / 128), 128, GP_SM>>>(
        (const uint32_t*)p_hA, p_wfc, fc_b, nullptr, p_raw, RAWN);

    // ---- Sigma (symmetric) ----
    sigma_sym<<<dim3(36, B_SZ), 256>>>(out);
}